// round 13
// baseline (speedup 1.0000x reference)
#include <cuda_runtime.h>
#include <cuda_bf16.h>
#include <math.h>

// ---------------- problem constants ----------------
constexpr int EMS   = 768;
constexpr int NHD   = 12;
constexpr int HDM   = 64;
constexpr int SEQL  = 65;
constexpr int BAT   = 256;
constexpr int STOK  = BAT * SEQL;       // 16640 = 65 * 256
constexpr int NHID_ = 3072;
constexpr int NE    = 8;
constexpr int CAP   = 2600;
constexpr int NCHUNK = 130;
constexpr int NCLS  = 1000;

// ---------------- bf16 transposed weight buffer ----------------
constexpr size_t W_QKV = 0;
constexpr size_t SZ_QKV = (size_t)8 * 2304 * 768;
constexpr size_t W_O  = W_QKV + SZ_QKV;
constexpr size_t SZ_O = (size_t)8 * 768 * 768;
constexpr size_t W_D1 = W_O + SZ_O;
constexpr size_t SZ_D1 = (size_t)4 * 3072 * 768;
constexpr size_t W_D2 = W_D1 + SZ_D1;
constexpr size_t SZ_D2 = (size_t)4 * 768 * 3072;
constexpr size_t W_E1 = W_D2 + SZ_D2;
constexpr size_t SZ_E1 = (size_t)32 * 3072 * 768;
constexpr size_t W_E2 = W_E1 + SZ_E1;
constexpr size_t SZ_E2 = (size_t)32 * 768 * 3072;
constexpr size_t W_TOTAL = W_E2 + SZ_E2;

__device__ __nv_bfloat16 g_wbf[W_TOTAL];

// ---------------- scratch ----------------
__device__ float g_h   [(size_t)STOK * EMS];
__device__ float g_qkv [(size_t)STOK * 3 * EMS];   // low half reused as bf16 qkv
__device__ float g_attn[(size_t)STOK * EMS];
__device__ float g_f2  [(size_t)STOK * EMS];
__device__ float g_patch[(size_t)BAT * 64 * 48];
__device__ float g_ebuf2[(size_t)NE * CAP * EMS];
__device__ float g_logits[BAT * NCLS];
__device__ float g_clsrow[BAT * EMS];
__device__ float g_lossb[BAT];
__device__ float g_g1[STOK], g_g2[STOK];
__device__ int   g_e1[STOK], g_e2[STOK], g_p1[STOK], g_p2[STOK];
__device__ int   g_h1[NCHUNK * NE], g_h2[NCHUNK * NE];
__device__ int   g_o1[NCHUNK * NE], g_o2[NCHUNK * NE];

__device__ __nv_bfloat16 g_hb   [(size_t)STOK * EMS];
__device__ __nv_bfloat16 g_attnb[(size_t)STOK * EMS];
__device__ __nv_bfloat16 g_f1b  [(size_t)STOK * NHID_];
__device__ __nv_bfloat16 g_bufb [(size_t)NE * CAP * EMS];
__device__ __nv_bfloat16 g_eb1b [(size_t)NE * CAP * NHID_];

// ---------------- small PTX helpers (base ISA only) ----------------
__device__ __forceinline__ unsigned smem_u32(const void* p) {
    unsigned a;
    asm("{ .reg .u64 t; cvta.to.shared.u64 t, %1; cvt.u32.u64 %0, t; }" : "=r"(a) : "l"(p));
    return a;
}
__device__ __forceinline__ void cp_async16(unsigned dst, const void* src) {
    asm volatile("cp.async.cg.shared.global [%0], [%1], 16;" :: "r"(dst), "l"(src));
}
__device__ __forceinline__ void cp_commit() { asm volatile("cp.async.commit_group;"); }
template <int N>
__device__ __forceinline__ void cp_wait() { asm volatile("cp.async.wait_group %0;" :: "n"(N)); }

__device__ __forceinline__ void ldmx4(unsigned* r, unsigned addr) {
    asm volatile("ldmatrix.sync.aligned.m8n8.x4.shared.b16 {%0,%1,%2,%3}, [%4];"
                 : "=r"(r[0]), "=r"(r[1]), "=r"(r[2]), "=r"(r[3]) : "r"(addr));
}
__device__ __forceinline__ void mma16816(float* d, const unsigned* a, unsigned b0, unsigned b1) {
    asm volatile("mma.sync.aligned.m16n8k16.row.col.f32.bf16.bf16.f32 "
                 "{%0,%1,%2,%3}, {%4,%5,%6,%7}, {%8,%9}, {%0,%1,%2,%3};"
                 : "+f"(d[0]), "+f"(d[1]), "+f"(d[2]), "+f"(d[3])
                 : "r"(a[0]), "r"(a[1]), "r"(a[2]), "r"(a[3]), "r"(b0), "r"(b1));
}
__device__ __forceinline__ unsigned long long pack2(float lo, float hi) {
    unsigned long long r;
    asm("mov.b64 %0, {%1, %2};" : "=l"(r) : "f"(lo), "f"(hi));
    return r;
}
__device__ __forceinline__ void fma2(unsigned long long& d, unsigned long long a, unsigned long long b) {
    asm("fma.rn.f32x2 %0, %1, %2, %0;" : "+l"(d) : "l"(a), "l"(b));
}
__device__ __forceinline__ float2 unpack2(unsigned long long v) {
    float2 f;
    asm("mov.b64 {%0, %1}, %2;" : "=f"(f.x), "=f"(f.y) : "l"(v));
    return f;
}

// ---------------- bf16 GEMM v4: 128x128 CTA, 256 thr, 4-stage (PROVEN; expert/batched) ----------------
constexpr int HROWB = 80;                  // 32 bf16 (64B) + 16B pad -> conflict-free ldmatrix
constexpr int HSTAGE = 2 * 128 * HROWB;    // 20480 bytes
constexpr int NSTG = 4;
constexpr int HG_SMEM = NSTG * HSTAGE;     // 81920

__global__ void __launch_bounds__(256) hgemm_kernel(
    const __nv_bfloat16* __restrict__ A, const __nv_bfloat16* __restrict__ Bt,
    const float* __restrict__ bias, void* __restrict__ Cout,
    int M, int N, int K, int mode,
    long long strA, long long strB, long long strBias, long long strC)
{
    extern __shared__ __align__(16) char smem[];
    const unsigned sb = smem_u32(smem);
    const int tid = threadIdx.x;
    const int wid = tid >> 5, lane = tid & 31;

    A    += (long long)blockIdx.z * strA;
    Bt   += (long long)blockIdx.z * strB;
    bias += (long long)blockIdx.z * strBias;

    const int brow = blockIdx.y * 128;
    const int bcol = blockIdx.x * 128;
    const int KIT = K >> 5;                // BK = 32

    const int c0 = tid, c1 = tid + 256;
    const int ar0 = c0 >> 2, ac0 = (c0 & 3) * 16;
    const int ar1 = c1 >> 2, ac1 = (c1 & 3) * 16;
    const __nv_bfloat16* Arow0 = A + (size_t)min(brow + ar0, M - 1) * K;
    const __nv_bfloat16* Arow1 = A + (size_t)min(brow + ar1, M - 1) * K;
    const __nv_bfloat16* Brow0 = Bt + (size_t)(bcol + ar0) * K;
    const __nv_bfloat16* Brow1 = Bt + (size_t)(bcol + ar1) * K;

    auto load_stage = [&](int st, int k0) {
        const unsigned sa = sb + st * HSTAGE;
        const unsigned sbm = sa + 128 * HROWB;
        cp_async16(sa + ar0 * HROWB + ac0, (const char*)(Arow0 + k0) + ac0);
        cp_async16(sa + ar1 * HROWB + ac1, (const char*)(Arow1 + k0) + ac1);
        cp_async16(sbm + ar0 * HROWB + ac0, (const char*)(Brow0 + k0) + ac0);
        cp_async16(sbm + ar1 * HROWB + ac1, (const char*)(Brow1 + k0) + ac1);
    };

    float acc[2][8][4];
#pragma unroll
    for (int i = 0; i < 2; i++)
#pragma unroll
        for (int j = 0; j < 8; j++)
#pragma unroll
            for (int q = 0; q < 4; q++) acc[i][j][q] = 0.f;

    const int wm = wid >> 1;
    const int wn = wid & 1;
    const unsigned aFragOff = (unsigned)((wm * 32 + (lane & 15)) * HROWB + (lane >> 4) * 16);
    const unsigned bFragOff = (unsigned)(128 * HROWB +
        (wn * 64 + ((lane >> 3) & 1) * 8 + (lane & 7)) * HROWB + (lane >> 4) * 16);

#pragma unroll
    for (int s = 0; s < NSTG - 1; s++) {
        if (s < KIT) load_stage(s, s * 32);
        cp_commit();
    }

    int cur = 0;
    for (int it = 0; it < KIT; it++) {
        cp_wait<NSTG - 2>();
        __syncthreads();
        {
            const int pf = it + NSTG - 1;
            if (pf < KIT) {
                int pfs = cur + NSTG - 1; if (pfs >= NSTG) pfs -= NSTG;
                load_stage(pfs, pf * 32);
            }
            cp_commit();
        }
        const unsigned aBase = sb + cur * HSTAGE + aFragOff;
        const unsigned bBase = sb + cur * HSTAGE + bFragOff;
#pragma unroll
        for (int ks = 0; ks < 2; ks++) {
            unsigned afr[2][4];
            ldmx4(afr[0], aBase + ks * 32);
            ldmx4(afr[1], aBase + ks * 32 + 16 * HROWB);
#pragma unroll
            for (int ng = 0; ng < 4; ng++) {
                unsigned bfr[4];
                ldmx4(bfr, bBase + ks * 32 + ng * 16 * HROWB);
#pragma unroll
                for (int mt = 0; mt < 2; mt++) {
                    mma16816(acc[mt][2 * ng + 0], afr[mt], bfr[0], bfr[2]);
                    mma16816(acc[mt][2 * ng + 1], afr[mt], bfr[1], bfr[3]);
                }
            }
        }
        cur++; if (cur >= NSTG) cur = 0;
    }

    const bool relu = (mode & 1);
    const bool isbf = (mode & 2);
    float* Cf = (float*)Cout + (long long)blockIdx.z * strC;
    __nv_bfloat16* Cb = (__nv_bfloat16*)Cout + (long long)blockIdx.z * strC;
    const int rbase = brow + wm * 32 + (lane >> 2);
    const int cbase = bcol + wn * 64 + 2 * (lane & 3);
#pragma unroll
    for (int mt = 0; mt < 2; mt++) {
#pragma unroll
        for (int nt = 0; nt < 8; nt++) {
            const int gcol = cbase + nt * 8;
            const float b0 = bias[gcol], b1 = bias[gcol + 1];
#pragma unroll
            for (int half = 0; half < 2; half++) {
                const int grow = rbase + mt * 16 + half * 8;
                if (grow < M) {
                    float v0 = acc[mt][nt][2 * half + 0] + b0;
                    float v1 = acc[mt][nt][2 * half + 1] + b1;
                    if (relu) { v0 = fmaxf(v0, 0.f); v1 = fmaxf(v1, 0.f); }
                    if (isbf) {
                        __nv_bfloat162 p;
                        p.x = __float2bfloat16(v0); p.y = __float2bfloat16(v1);
                        *reinterpret_cast<__nv_bfloat162*>(Cb + (size_t)grow * N + gcol) = p;
                    } else {
                        *reinterpret_cast<float2*>(Cf + (size_t)grow * N + gcol) = make_float2(v0, v1);
                    }
                }
            }
        }
    }
}

// ---------------- bf16 GEMM v7: 256x128 CTA, 512 thr (16 warps), 4-stage ----------------
// For M % 256 == 0 GEMMs (QKV/proj/dense FFN). 25% less L2 tile traffic, half the CTAs.
// smem 120 KB -> 1 CTA/SM but STILL 16 warps/SM. Bit-identical accumulation order vs v4.
constexpr int H2STAGE = (256 + 128) * HROWB;   // 30720 bytes
constexpr int HG2_SMEM = NSTG * H2STAGE;       // 122880

__global__ void __launch_bounds__(512) hgemm256_kernel(
    const __nv_bfloat16* __restrict__ A, const __nv_bfloat16* __restrict__ Bt,
    const float* __restrict__ bias, void* __restrict__ Cout,
    int M, int N, int K, int mode)
{
    extern __shared__ __align__(16) char smem[];
    const unsigned sb = smem_u32(smem);
    const int tid = threadIdx.x;
    const int wid = tid >> 5, lane = tid & 31;

    const int brow = blockIdx.y * 256;
    const int bcol = blockIdx.x * 128;
    const int KIT = K >> 5;                // BK = 32

    // 1536 chunks of 16B per stage (384 rows x 4); 3 per thread
    const int c0 = tid, c1 = tid + 512, c2 = tid + 1024;
    const int r0 = c0 >> 2, o0 = (c0 & 3) * 16;
    const int r1 = c1 >> 2, o1 = (c1 & 3) * 16;
    const int r2 = c2 >> 2, o2 = (c2 & 3) * 16;
    // rows 0..255 -> A, rows 256..383 -> B
    const __nv_bfloat16* G0 = (r0 < 256) ? A + (size_t)(brow + r0) * K : Bt + (size_t)(bcol + r0 - 256) * K;
    const __nv_bfloat16* G1 = (r1 < 256) ? A + (size_t)(brow + r1) * K : Bt + (size_t)(bcol + r1 - 256) * K;
    const __nv_bfloat16* G2 = (r2 < 256) ? A + (size_t)(brow + r2) * K : Bt + (size_t)(bcol + r2 - 256) * K;
    const unsigned s0 = (unsigned)(r0 * HROWB + o0);
    const unsigned s1 = (unsigned)(r1 * HROWB + o1);
    const unsigned s2 = (unsigned)(r2 * HROWB + o2);

    auto load_stage = [&](int st, int k0) {
        const unsigned base = sb + st * H2STAGE;
        cp_async16(base + s0, (const char*)(G0 + k0) + o0);
        cp_async16(base + s1, (const char*)(G1 + k0) + o1);
        cp_async16(base + s2, (const char*)(G2 + k0) + o2);
    };

    float acc[4][4][4];
#pragma unroll
    for (int i = 0; i < 4; i++)
#pragma unroll
        for (int j = 0; j < 4; j++)
#pragma unroll
            for (int q = 0; q < 4; q++) acc[i][j][q] = 0.f;

    const int wm = wid >> 2;              // 0..3 -> rows wm*64..+63
    const int wn = wid & 3;               // 0..3 -> cols wn*32..+31
    const unsigned aFragOff = (unsigned)((wm * 64 + (lane & 15)) * HROWB + (lane >> 4) * 16);
    const unsigned bFragOff = (unsigned)(256 * HROWB +
        (wn * 32 + ((lane >> 3) & 1) * 8 + (lane & 7)) * HROWB + (lane >> 4) * 16);

#pragma unroll
    for (int s = 0; s < NSTG - 1; s++) {
        if (s < KIT) load_stage(s, s * 32);
        cp_commit();
    }

    int cur = 0;
    for (int it = 0; it < KIT; it++) {
        cp_wait<NSTG - 2>();
        __syncthreads();
        {
            const int pf = it + NSTG - 1;
            if (pf < KIT) {
                int pfs = cur + NSTG - 1; if (pfs >= NSTG) pfs -= NSTG;
                load_stage(pfs, pf * 32);
            }
            cp_commit();
        }
        const unsigned aBase = sb + cur * H2STAGE + aFragOff;
        const unsigned bBase = sb + cur * H2STAGE + bFragOff;
#pragma unroll
        for (int ks = 0; ks < 2; ks++) {
            unsigned afr[4][4];
#pragma unroll
            for (int mt = 0; mt < 4; mt++)
                ldmx4(afr[mt], aBase + ks * 32 + mt * 16 * HROWB);
#pragma unroll
            for (int ng = 0; ng < 2; ng++) {
                unsigned bfr[4];
                ldmx4(bfr, bBase + ks * 32 + ng * 16 * HROWB);
#pragma unroll
                for (int mt = 0; mt < 4; mt++) {
                    mma16816(acc[mt][2 * ng + 0], afr[mt], bfr[0], bfr[2]);
                    mma16816(acc[mt][2 * ng + 1], afr[mt], bfr[1], bfr[3]);
                }
            }
        }
        cur++; if (cur >= NSTG) cur = 0;
    }

    const bool relu = (mode & 1);
    const bool isbf = (mode & 2);
    float* Cf = (float*)Cout;
    __nv_bfloat16* Cb = (__nv_bfloat16*)Cout;
    const int rbase = brow + wm * 64 + (lane >> 2);
    const int cbase = bcol + wn * 32 + 2 * (lane & 3);
#pragma unroll
    for (int mt = 0; mt < 4; mt++) {
#pragma unroll
        for (int nt = 0; nt < 4; nt++) {
            const int gcol = cbase + nt * 8;
            const float b0 = bias[gcol], b1 = bias[gcol + 1];
#pragma unroll
            for (int half = 0; half < 2; half++) {
                const int grow = rbase + mt * 16 + half * 8;
                {
                    float v0 = acc[mt][nt][2 * half + 0] + b0;
                    float v1 = acc[mt][nt][2 * half + 1] + b1;
                    if (relu) { v0 = fmaxf(v0, 0.f); v1 = fmaxf(v1, 0.f); }
                    if (isbf) {
                        __nv_bfloat162 p;
                        p.x = __float2bfloat16(v0); p.y = __float2bfloat16(v1);
                        *reinterpret_cast<__nv_bfloat162*>(Cb + (size_t)grow * N + gcol) = p;
                    } else {
                        *reinterpret_cast<float2*>(Cf + (size_t)grow * N + gcol) = make_float2(v0, v1);
                    }
                }
            }
        }
    }
}

// ---------------- weight transpose+convert: fp32 [R,C] -> bf16 [C,R], batched ----------------
__global__ void wtrans_kernel(const float* __restrict__ src, __nv_bfloat16* __restrict__ dst, int R, int C) {
    __shared__ float t[32][33];
    src += (size_t)blockIdx.z * R * C;
    dst += (size_t)blockIdx.z * R * C;
    const int c0 = blockIdx.x * 32, r0 = blockIdx.y * 32;
    const int x = threadIdx.x, y = threadIdx.y;
#pragma unroll
    for (int i = 0; i < 32; i += 8) {
        const int r = r0 + y + i, c = c0 + x;
        t[y + i][x] = (r < R && c < C) ? src[(size_t)r * C + c] : 0.f;
    }
    __syncthreads();
#pragma unroll
    for (int i = 0; i < 32; i += 8) {
        const int c = c0 + y + i, r = r0 + x;
        if (c < C && r < R) dst[(size_t)c * R + r] = __float2bfloat16(t[x][y + i]);
    }
}

// ---------------- fp32 fallback SGEMM (patch embed, decoder) ----------------
constexpr int BM = 128, BN = 128, BKx = 8;

__global__ __launch_bounds__(256, 2) void sgemm_kernel(
    const float* __restrict__ A, const float* __restrict__ Bm,
    const float* __restrict__ bias, float* __restrict__ Cm,
    int M, int N, int K, int relu)
{
    __shared__ __align__(16) float As[BKx][BM];
    __shared__ __align__(16) float Bs[BKx][BN];
    const int tid  = threadIdx.x;
    const int brow = blockIdx.y * BM;
    const int bcol = blockIdx.x * BN;
    const int tx = tid & 15, ty = tid >> 4;
    const int aRow = tid >> 1, aCol = (tid & 1) * 4;
    const int bRowL = tid >> 5, bColL = (tid & 31) * 4;

    unsigned long long acc[8][4];
#pragma unroll
    for (int i = 0; i < 8; i++)
#pragma unroll
        for (int j = 0; j < 4; j++) acc[i][j] = 0ull;
    const bool n4 = ((N & 3) == 0);

    for (int k0 = 0; k0 < K; k0 += BKx) {
        float4 av = make_float4(0.f, 0.f, 0.f, 0.f);
        const int gr = brow + aRow;
        if (gr < M && k0 + aCol < K) av = *reinterpret_cast<const float4*>(A + (long long)gr * K + k0 + aCol);
        As[aCol + 0][aRow] = av.x; As[aCol + 1][aRow] = av.y;
        As[aCol + 2][aRow] = av.z; As[aCol + 3][aRow] = av.w;
        const int gc = bcol + bColL;
        const int kr = k0 + bRowL;
        const float* bp = Bm + (long long)kr * N + gc;
        if (n4) {
            float4 bv = make_float4(0.f, 0.f, 0.f, 0.f);
            if (gc < N && kr < K) bv = *reinterpret_cast<const float4*>(bp);
            Bs[bRowL][bColL + 0] = bv.x; Bs[bRowL][bColL + 1] = bv.y;
            Bs[bRowL][bColL + 2] = bv.z; Bs[bRowL][bColL + 3] = bv.w;
        } else {
#pragma unroll
            for (int q = 0; q < 4; q++)
                Bs[bRowL][bColL + q] = (gc + q < N && kr < K) ? bp[q] : 0.f;
        }
        __syncthreads();
#pragma unroll
        for (int kk = 0; kk < BKx; kk++) {
            const float4 a0 = *reinterpret_cast<const float4*>(&As[kk][ty * 8]);
            const float4 a1 = *reinterpret_cast<const float4*>(&As[kk][ty * 8 + 4]);
            const unsigned long long b0 = *reinterpret_cast<const unsigned long long*>(&Bs[kk][tx * 8 + 0]);
            const unsigned long long b1 = *reinterpret_cast<const unsigned long long*>(&Bs[kk][tx * 8 + 2]);
            const unsigned long long b2 = *reinterpret_cast<const unsigned long long*>(&Bs[kk][tx * 8 + 4]);
            const unsigned long long b3 = *reinterpret_cast<const unsigned long long*>(&Bs[kk][tx * 8 + 6]);
            const float aa[8] = {a0.x, a0.y, a0.z, a0.w, a1.x, a1.y, a1.z, a1.w};
#pragma unroll
            for (int i = 0; i < 8; i++) {
                const unsigned long long ad = pack2(aa[i], aa[i]);
                fma2(acc[i][0], ad, b0); fma2(acc[i][1], ad, b1);
                fma2(acc[i][2], ad, b2); fma2(acc[i][3], ad, b3);
            }
        }
        __syncthreads();
    }
#pragma unroll
    for (int i = 0; i < 8; i++) {
        const int gi = brow + ty * 8 + i;
        if (gi >= M) continue;
#pragma unroll
        for (int j = 0; j < 4; j++) {
            const float2 v = unpack2(acc[i][j]);
            const int gj = bcol + tx * 8 + 2 * j;
            if (gj < N) {
                float c = v.x + bias[gj];
                if (relu) c = fmaxf(c, 0.f);
                Cm[(long long)gi * N + gj] = c;
            }
            if (gj + 1 < N) {
                float c = v.y + bias[gj + 1];
                if (relu) c = fmaxf(c, 0.f);
                Cm[(long long)gi * N + gj + 1] = c;
            }
        }
    }
}

// ---------------- patch embed prep ----------------
__global__ void patch_kernel(const float* __restrict__ x, float* __restrict__ p) {
    const int total = BAT * 64 * 48;
    for (int idx = blockIdx.x * blockDim.x + threadIdx.x; idx < total; idx += gridDim.x * blockDim.x) {
        const int f = idx % 48;
        const int token = idx / 48;
        const int b = token >> 6;
        const int ij = token & 63;
        const int i = ij >> 3, j = ij & 7;
        const int c = f >> 4, r = (f >> 2) & 3, q = f & 3;
        p[idx] = x[((b * 3 + c) * 32 + (i * 4 + r)) * 32 + (j * 4 + q)];
    }
}

__global__ void assemble_kernel(const float* __restrict__ emb, const float* __restrict__ cls,
                                const float* __restrict__ pos, float* __restrict__ h,
                                __nv_bfloat16* __restrict__ hb) {
    const long long total = (long long)STOK * EMS;
    for (long long idx = (long long)blockIdx.x * blockDim.x + threadIdx.x; idx < total;
         idx += (long long)gridDim.x * blockDim.x) {
        const int d = (int)(idx % EMS);
        const long long s = idx / EMS;
        const int b = (int)(s / SEQL), t = (int)(s % SEQL);
        float v = pos[t * EMS + d];
        v += (t == 0) ? cls[d] : emb[((long long)b * 64 + (t - 1)) * EMS + d];
        h[idx] = v;
        hb[idx] = __float2bfloat16(v);
    }
}

// ---------------- attention (bf16 qkv in, bf16 out), packed fp32x2 ----------------
constexpr int KVSTR = 66;   // even stride -> 8B-aligned rows for LDS.64
__global__ void __launch_bounds__(256) attn_kernel(const __nv_bfloat16* __restrict__ qkv,
                                                   __nv_bfloat16* __restrict__ out) {
    __shared__ float ks[SEQL][KVSTR];
    __shared__ float vs[SEQL][KVSTR];
    __shared__ float qrow[8][HDM];
    __shared__ float probs[8][SEQL + 1];

    const int h = blockIdx.x, b = blockIdx.y;
    const int tid = threadIdx.x, warp = tid >> 5, lane = tid & 31;
    const __nv_bfloat16* base = qkv + (long long)b * SEQL * (3 * EMS);

    for (int idx = tid; idx < SEQL * HDM; idx += 256) {
        const int k = idx >> 6, d = idx & 63;
        ks[k][d] = __bfloat162float(base[(long long)k * (3 * EMS) + EMS     + h * HDM + d]);
        vs[k][d] = __bfloat162float(base[(long long)k * (3 * EMS) + 2 * EMS + h * HDM + d]);
    }
    __syncthreads();

    for (int q = warp; q < SEQL; q += 8) {
        qrow[warp][lane]      = __bfloat162float(base[(long long)q * (3 * EMS) + h * HDM + lane]);
        qrow[warp][lane + 32] = __bfloat162float(base[(long long)q * (3 * EMS) + h * HDM + lane + 32]);
        __syncwarp();
        float sc[3];
        float mx = -1e30f;
        const unsigned long long* qp = reinterpret_cast<const unsigned long long*>(&qrow[warp][0]);
#pragma unroll
        for (int ii = 0; ii < 3; ii++) {
            const int kk = lane + ii * 32;
            float acc = 0.f;
            if (kk < SEQL) {
                const unsigned long long* kp = reinterpret_cast<const unsigned long long*>(&ks[kk][0]);
                unsigned long long a2 = 0ull;
#pragma unroll
                for (int j2 = 0; j2 < 32; j2++) fma2(a2, qp[j2], kp[j2]);
                const float2 f = unpack2(a2);
                acc = (f.x + f.y) * 0.125f;
                mx = fmaxf(mx, acc);
            }
            sc[ii] = acc;
        }
        for (int o = 16; o > 0; o >>= 1) mx = fmaxf(mx, __shfl_xor_sync(0xffffffffu, mx, o));
        float sum = 0.f;
#pragma unroll
        for (int ii = 0; ii < 3; ii++) {
            const int kk = lane + ii * 32;
            float p = 0.f;
            if (kk < SEQL) { p = expf(sc[ii] - mx); sum += p; }
            sc[ii] = p;
        }
        for (int o = 16; o > 0; o >>= 1) sum += __shfl_xor_sync(0xffffffffu, sum, o);
        const float inv = 1.f / sum;
#pragma unroll
        for (int ii = 0; ii < 3; ii++) {
            const int kk = lane + ii * 32;
            if (kk < SEQL) probs[warp][kk] = sc[ii] * inv;
        }
        __syncwarp();
        {
            const int d0 = 2 * lane;
            unsigned long long o2 = 0ull;
            for (int k = 0; k < SEQL; k++) {
                const float p = probs[warp][k];
                fma2(o2, pack2(p, p),
                     *reinterpret_cast<const unsigned long long*>(&vs[k][d0]));
            }
            const float2 f = unpack2(o2);
            __nv_bfloat162 pr;
            pr.x = __float2bfloat16(f.x);
            pr.y = __float2bfloat16(f.y);
            *reinterpret_cast<__nv_bfloat162*>(
                out + ((long long)(b * SEQL + q)) * EMS + h * HDM + d0) = pr;
        }
        __syncwarp();
    }
}

// ---------------- layernorm (shuffle reductions; writes fp32 h + bf16 copy) ----------------
__global__ void __launch_bounds__(256) ln_kernel(float* __restrict__ h, const float* __restrict__ a,
                          const float* __restrict__ g, const float* __restrict__ bta,
                          __nv_bfloat16* __restrict__ hb) {
    __shared__ float wred[8];
    const long long base = (long long)blockIdx.x * EMS;
    const int tid = threadIdx.x, warp = tid >> 5, lane = tid & 31;
    const float x0 = h[base + tid]       + a[base + tid];
    const float x1 = h[base + tid + 256] + a[base + tid + 256];
    const float x2 = h[base + tid + 512] + a[base + tid + 512];
    float s = x0 + x1 + x2;
    for (int o = 16; o > 0; o >>= 1) s += __shfl_xor_sync(0xffffffffu, s, o);
    if (lane == 0) wred[warp] = s;
    __syncthreads();
    float tot = 0.f;
#pragma unroll
    for (int w = 0; w < 8; w++) tot += wred[w];
    const float mean = tot / (float)EMS;
    __syncthreads();
    const float d0 = x0 - mean, d1 = x1 - mean, d2 = x2 - mean;
    float v = d0 * d0 + d1 * d1 + d2 * d2;
    for (int o = 16; o > 0; o >>= 1) v += __shfl_xor_sync(0xffffffffu, v, o);
    if (lane == 0) wred[warp] = v;
    __syncthreads();
    float vtot = 0.f;
#pragma unroll
    for (int w = 0; w < 8; w++) vtot += wred[w];
    const float rstd = rsqrtf(vtot / (float)EMS + 1e-5f);
    const float r0 = d0 * rstd * g[tid]       + bta[tid];
    const float r1 = d1 * rstd * g[tid + 256] + bta[tid + 256];
    const float r2 = d2 * rstd * g[tid + 512] + bta[tid + 512];
    h[base + tid]       = r0;  hb[base + tid]       = __float2bfloat16(r0);
    h[base + tid + 256] = r1;  hb[base + tid + 256] = __float2bfloat16(r1);
    h[base + tid + 512] = r2;  hb[base + tid + 512] = __float2bfloat16(r2);
}

// ---------------- fused MoE keep-mask + gather + layernorm ----------------
__global__ void __launch_bounds__(256) ln_gather_kernel(
    float* __restrict__ h, const float* __restrict__ oe,
    const int* __restrict__ e1, const int* __restrict__ e2,
    const int* __restrict__ p1, const int* __restrict__ p2,
    const float* __restrict__ g1, const float* __restrict__ g2,
    const float* __restrict__ g, const float* __restrict__ bta,
    __nv_bfloat16* __restrict__ hb) {
    __shared__ float wred[8];
    const int s = blockIdx.x;
    const long long base = (long long)s * EMS;
    const int tid = threadIdx.x, warp = tid >> 5, lane = tid & 31;
    const int pp1 = p1[s], pp2 = p2[s];
    const float a = g1[s] * (pp1 < CAP ? 1.f : 0.f);
    const float bgl = g2[s] * (pp2 < CAP ? 1.f : 0.f);
    const float den = fmaxf(a + bgl, 1e-9f);
    const float w1 = a / den, w2 = bgl / den;
    const int q1 = min(pp1, CAP - 1), q2 = min(pp2, CAP - 1);
    const float* r1 = oe + ((long long)e1[s] * CAP + q1) * EMS;
    const float* r2 = oe + ((long long)e2[s] * CAP + q2) * EMS;

    const float x0 = h[base + tid]       + r1[tid]       * w1 + r2[tid]       * w2;
    const float x1 = h[base + tid + 256] + r1[tid + 256] * w1 + r2[tid + 256] * w2;
    const float x2 = h[base + tid + 512] + r1[tid + 512] * w1 + r2[tid + 512] * w2;
    float sm = x0 + x1 + x2;
    for (int o = 16; o > 0; o >>= 1) sm += __shfl_xor_sync(0xffffffffu, sm, o);
    if (lane == 0) wred[warp] = sm;
    __syncthreads();
    float tot = 0.f;
#pragma unroll
    for (int w = 0; w < 8; w++) tot += wred[w];
    const float mean = tot / (float)EMS;
    __syncthreads();
    const float d0 = x0 - mean, d1 = x1 - mean, d2 = x2 - mean;
    float v = d0 * d0 + d1 * d1 + d2 * d2;
    for (int o = 16; o > 0; o >>= 1) v += __shfl_xor_sync(0xffffffffu, v, o);
    if (lane == 0) wred[warp] = v;
    __syncthreads();
    float vtot = 0.f;
#pragma unroll
    for (int w = 0; w < 8; w++) vtot += wred[w];
    const float rstd = rsqrtf(vtot / (float)EMS + 1e-5f);
    const float r0o = d0 * rstd * g[tid]       + bta[tid];
    const float r1o = d1 * rstd * g[tid + 256] + bta[tid + 256];
    const float r2o = d2 * rstd * g[tid + 512] + bta[tid + 512];
    h[base + tid]       = r0o;  hb[base + tid]       = __float2bfloat16(r0o);
    h[base + tid + 256] = r1o;  hb[base + tid + 256] = __float2bfloat16(r1o);
    h[base + tid + 512] = r2o;  hb[base + tid + 512] = __float2bfloat16(r2o);
}

// ---------------- MoE gating (fp32, exact) ----------------
__global__ void gate_kernel(const float* __restrict__ h, const float* __restrict__ gw,
                            int* __restrict__ e1o, int* __restrict__ e2o,
                            float* __restrict__ g1o, float* __restrict__ g2o) {
    const int token = (blockIdx.x * blockDim.x + threadIdx.x) >> 5;
    const int lane = threadIdx.x & 31;
    if (token >= STOK) return;
    const float* x = h + (long long)token * EMS;
    float part[NE] = {0.f, 0.f, 0.f, 0.f, 0.f, 0.f, 0.f, 0.f};
    for (int j = lane; j < EMS; j += 32) {
        const float xv = x[j];
        const float* w = gw + j * NE;
#pragma unroll
        for (int e = 0; e < NE; e++) part[e] += xv * w[e];
    }
#pragma unroll
    for (int e = 0; e < NE; e++)
        for (int o = 16; o > 0; o >>= 1) part[e] += __shfl_xor_sync(0xffffffffu, part[e], o);
    if (lane == 0) {
        float mx = part[0];
#pragma unroll
        for (int e = 1; e < NE; e++) mx = fmaxf(mx, part[e]);
        float gates[NE]; float se = 0.f;
#pragma unroll
        for (int e = 0; e < NE; e++) { gates[e] = expf(part[e] - mx); se += gates[e]; }
        int a1 = 0; float b1v = part[0];
#pragma unroll
        for (int e = 1; e < NE; e++) if (part[e] > b1v) { b1v = part[e]; a1 = e; }
        int a2 = -1; float b2v = -1e30f;
#pragma unroll
        for (int e = 0; e < NE; e++) if (e != a1 && part[e] > b2v) { b2v = part[e]; a2 = e; }
        e1o[token] = a1; e2o[token] = a2;
        g1o[token] = gates[a1] / se;
        g2o[token] = gates[a2] / se;
    }
}

__global__ void hist_kernel(const int* __restrict__ e1, const int* __restrict__ e2,
                            int* __restrict__ h1, int* __restrict__ h2) {
    __shared__ int s1[NE], s2[NE];
    const int tid = threadIdx.x;
    if (tid < NE) { s1[tid] = 0; s2[tid] = 0; }
    __syncthreads();
    const int s = blockIdx.x * 128 + tid;
    atomicAdd(&s1[e1[s]], 1);
    atomicAdd(&s2[e2[s]], 1);
    __syncthreads();
    if (tid < NE) {
        h1[blockIdx.x * NE + tid] = s1[tid];
        h2[blockIdx.x * NE + tid] = s2[tid];
    }
}

__global__ void scan_kernel(const int* __restrict__ h1, const int* __restrict__ h2,
                            int* __restrict__ o1, int* __restrict__ o2) {
    const int e = threadIdx.x;
    if (e < NE) {
        int run = 0;
        for (int c = 0; c < NCHUNK; c++) { o1[c * NE + e] = run; run += h1[c * NE + e]; }
        int run2 = run;
        for (int c = 0; c < NCHUNK; c++) { o2[c * NE + e] = run2; run2 += h2[c * NE + e]; }
    }
}

__global__ void rank_kernel(const int* __restrict__ e1, const int* __restrict__ e2,
                            const int* __restrict__ o1, const int* __restrict__ o2,
                            int* __restrict__ p1, int* __restrict__ p2) {
    const int t = threadIdx.x, c = blockIdx.x;
    if (t < NE) {
        const int e = t;
        int r = o1[c * NE + e];
        for (int i = 0; i < 128; i++) {
            const int s = c * 128 + i;
            if (e1[s] == e) p1[s] = r++;
        }
    } else if (t < 2 * NE) {
        const int e = t - NE;
        int r = o2[c * NE + e];
        for (int i = 0; i < 128; i++) {
            const int s = c * 128 + i;
            if (e2[s] == e) p2[s] = r++;
        }
    }
}

// scatter reads the bf16 mirror hb with vectorized 16B copies
__global__ void scatter_kernel(const __nv_bfloat16* __restrict__ hb, const int* __restrict__ e1,
                               const int* __restrict__ e2, const int* __restrict__ p1,
                               const int* __restrict__ p2, __nv_bfloat16* __restrict__ buf) {
    const int s = blockIdx.x;
    const int q1 = p1[s], q2 = p2[s];
    const uint4* src = reinterpret_cast<const uint4*>(hb + (long long)s * EMS); // 96 uint4
    const int tid = threadIdx.x;   // blockDim = 128
    if (q1 < CAP) {
        uint4* d = reinterpret_cast<uint4*>(buf + ((long long)e1[s] * CAP + q1) * EMS);
        if (tid < 96) d[tid] = src[tid];
    }
    if (q2 < CAP) {
        uint4* d = reinterpret_cast<uint4*>(buf + ((long long)e2[s] * CAP + q2) * EMS);
        if (tid < 96) d[tid] = src[tid];
    }
}

// ---------------- decoder + loss ----------------
__global__ void cls_extract_kernel(const float* __restrict__ h, float* __restrict__ out) {
    const int b = blockIdx.x;
    for (int d = threadIdx.x; d < EMS; d += blockDim.x)
        out[b * EMS + d] = h[(long long)b * SEQL * EMS + d];
}

__global__ void loss_kernel(const float* __restrict__ logits, const int* __restrict__ y,
                            float* __restrict__ lossb) {
    __shared__ float red[256];
    const int b = blockIdx.x, tid = threadIdx.x;
    const float* l = logits + b * NCLS;
    float mx = -1e30f;
    for (int j = tid; j < NCLS; j += 256) mx = fmaxf(mx, l[j]);
    red[tid] = mx;
    __syncthreads();
    for (int o = 128; o > 0; o >>= 1) { if (tid < o) red[tid] = fmaxf(red[tid], red[tid + o]); __syncthreads(); }
    mx = red[0];
    __syncthreads();
    float s = 0.f;
    for (int j = tid; j < NCLS; j += 256) s += expf(l[j] - mx);
    red[tid] = s;
    __syncthreads();
    for (int o = 128; o > 0; o >>= 1) { if (tid < o) red[tid] += red[tid + o]; __syncthreads(); }
    if (tid == 0) lossb[b] = -(l[y[b]] - mx - logf(red[0]));
}

__global__ void sum_kernel(const float* __restrict__ lossb, float* __restrict__ out) {
    if (threadIdx.x == 0) {
        float s = 0.f;
        for (int i = 0; i < BAT; i++) s += lossb[i];
        out[0] = s;
    }
}

// ---------------- host side ----------------
static inline void gemm_tc(const __nv_bfloat16* A, const __nv_bfloat16* Bt, const float* bias,
                           void* C, int M, int N, int K, int mode, int batch = 1,
                           long long sA = 0, long long sB = 0, long long sBias = 0, long long sC = 0) {
    dim3 grid(N / 128, (M + 127) / 128, batch);
    hgemm_kernel<<<grid, 256, HG_SMEM>>>(A, Bt, bias, C, M, N, K, mode, sA, sB, sBias, sC);
}
// big-M variant: M % 256 == 0, batch 1
static inline void gemm_tc256(const __nv_bfloat16* A, const __nv_bfloat16* Bt, const float* bias,
                              void* C, int M, int N, int K, int mode) {
    dim3 grid(N / 128, M / 256, 1);
    hgemm256_kernel<<<grid, 512, HG2_SMEM>>>(A, Bt, bias, C, M, N, K, mode);
}

extern "C" void kernel_launch(void* const* d_in, const int* in_sizes, int n_in,
                              void* d_out, int out_size) {
    const float* x       = (const float*)d_in[0];
    const int*   y       = (const int*)  d_in[1];
    const float* patch_w = (const float*)d_in[2];
    const float* patch_b = (const float*)d_in[3];
    const float* cls     = (const float*)d_in[4];
    const float* pos     = (const float*)d_in[5];
    const float* wqkv    = (const float*)d_in[6];
    const float* bqkv    = (const float*)d_in[7];
    const float* wo      = (const float*)d_in[8];
    const float* bo      = (const float*)d_in[9];
    const float* ln1g    = (const float*)d_in[10];
    const float* ln1b    = (const float*)d_in[11];
    const float* ln2g    = (const float*)d_in[12];
    const float* ln2b    = (const float*)d_in[13];
    const float* dw1     = (const float*)d_in[14];
    const float* db1     = (const float*)d_in[15];
    const float* dw2     = (const float*)d_in[16];
    const float* db2     = (const float*)d_in[17];
    const float* gw      = (const float*)d_in[18];
    const float* ew1     = (const float*)d_in[19];
    const float* eb1     = (const float*)d_in[20];
    const float* ew2     = (const float*)d_in[21];
    const float* eb2     = (const float*)d_in[22];
    const float* decw    = (const float*)d_in[23];
    const float* decb    = (const float*)d_in[24];

    cudaFuncSetAttribute(hgemm_kernel, cudaFuncAttributeMaxDynamicSharedMemorySize, HG_SMEM);
    cudaFuncSetAttribute(hgemm256_kernel, cudaFuncAttributeMaxDynamicSharedMemorySize, HG2_SMEM);

    float *p_h, *p_qkv, *p_attn, *p_f2, *p_patch, *p_eb2;
    float *p_logits, *p_cls, *p_lossb, *p_g1, *p_g2;
    int *p_e1, *p_e2, *p_p1, *p_p2, *p_h1, *p_h2, *p_o1, *p_o2;
    __nv_bfloat16 *p_wb, *p_hb, *p_attnb, *p_f1b, *p_bufb, *p_eb1b;
    cudaGetSymbolAddress((void**)&p_h, g_h);
    cudaGetSymbolAddress((void**)&p_qkv, g_qkv);
    cudaGetSymbolAddress((void**)&p_attn, g_attn);
    cudaGetSymbolAddress((void**)&p_f2, g_f2);
    cudaGetSymbolAddress((void**)&p_patch, g_patch);
    cudaGetSymbolAddress((void**)&p_eb2, g_ebuf2);
    cudaGetSymbolAddress((void**)&p_logits, g_logits);
    cudaGetSymbolAddress((void**)&p_cls, g_clsrow);
    cudaGetSymbolAddress((void**)&p_lossb, g_lossb);
    cudaGetSymbolAddress((void**)&p_g1, g_g1);
    cudaGetSymbolAddress((void**)&p_g2, g_g2);
    cudaGetSymbolAddress((void**)&p_e1, g_e1);
    cudaGetSymbolAddress((void**)&p_e2, g_e2);
    cudaGetSymbolAddress((void**)&p_p1, g_p1);
    cudaGetSymbolAddress((void**)&p_p2, g_p2);
    cudaGetSymbolAddress((void**)&p_h1, g_h1);
    cudaGetSymbolAddress((void**)&p_h2, g_h2);
    cudaGetSymbolAddress((void**)&p_o1, g_o1);
    cudaGetSymbolAddress((void**)&p_o2, g_o2);
    cudaGetSymbolAddress((void**)&p_wb, g_wbf);
    cudaGetSymbolAddress((void**)&p_hb, g_hb);
    cudaGetSymbolAddress((void**)&p_attnb, g_attnb);
    cudaGetSymbolAddress((void**)&p_f1b, g_f1b);
    cudaGetSymbolAddress((void**)&p_bufb, g_bufb);
    cudaGetSymbolAddress((void**)&p_eb1b, g_eb1b);

    __nv_bfloat16* p_qkvb = (__nv_bfloat16*)p_qkv;   // reuse fp32 scratch as bf16

    // ---- weight convert+transpose: fp32 [K,N] -> bf16 [N,K] ----
    dim3 tb(32, 8);
    wtrans_kernel<<<dim3(2304 / 32, 768 / 32, 8),  tb>>>(wqkv, p_wb + W_QKV, 768, 2304);
    wtrans_kernel<<<dim3(768 / 32,  768 / 32, 8),  tb>>>(wo,   p_wb + W_O,   768, 768);
    wtrans_kernel<<<dim3(3072 / 32, 768 / 32, 4),  tb>>>(dw1,  p_wb + W_D1,  768, 3072);
    wtrans_kernel<<<dim3(768 / 32, 3072 / 32, 4),  tb>>>(dw2,  p_wb + W_D2,  3072, 768);
    wtrans_kernel<<<dim3(3072 / 32, 768 / 32, 32), tb>>>(ew1,  p_wb + W_E1,  768, 3072);
    wtrans_kernel<<<dim3(768 / 32, 3072 / 32, 32), tb>>>(ew2,  p_wb + W_E2,  3072, 768);

    // ---- patch embed (fp32 SGEMM; K=48 small) ----
    patch_kernel<<<1024, 256>>>(x, p_patch);
    sgemm_kernel<<<dim3(768 / BN, (BAT * 64 + BM - 1) / BM), 256>>>(p_patch, patch_w, patch_b, p_attn, BAT * 64, EMS, 48, 0);
    assemble_kernel<<<8192, 256>>>(p_attn, cls, pos, p_h, p_hb);

    int di = 0, mi = 0;
    for (int i = 0; i < 8; i++) {
        gemm_tc256(p_hb, p_wb + W_QKV + (size_t)i * 2304 * 768, bqkv + i * 3 * EMS, p_qkvb, STOK, 3 * EMS, EMS, 2);
        attn_kernel<<<dim3(NHD, BAT), 256>>>(p_qkvb, p_attnb);
        gemm_tc256(p_attnb, p_wb + W_O + (size_t)i * 768 * 768, bo + i * EMS, p_f2, STOK, EMS, EMS, 0);
        ln_kernel<<<STOK, 256>>>(p_h, p_f2, ln1g + i * EMS, ln1b + i * EMS, p_hb);

        if ((i & 1) == 0) {
            gemm_tc256(p_hb, p_wb + W_D1 + (size_t)di * 3072 * 768, db1 + di * NHID_, p_f1b, STOK, NHID_, EMS, 3);
            gemm_tc256(p_f1b, p_wb + W_D2 + (size_t)di * 768 * 3072, db2 + di * EMS, p_f2, STOK, EMS, NHID_, 0);
            ln_kernel<<<STOK, 256>>>(p_h, p_f2, ln2g + i * EMS, ln2b + i * EMS, p_hb);
            di++;
        } else {
            gate_kernel<<<STOK / 8, 256>>>(p_h, gw + (long long)mi * EMS * NE, p_e1, p_e2, p_g1, p_g2);
            hist_kernel<<<NCHUNK, 128>>>(p_e1, p_e2, p_h1, p_h2);
            scan_kernel<<<1, 32>>>(p_h1, p_h2, p_o1, p_o2);
            rank_kernel<<<NCHUNK, 32>>>(p_e1, p_e2, p_o1, p_o2, p_p1, p_p2);
            scatter_kernel<<<STOK, 128>>>(p_hb, p_e1, p_e2, p_p1, p_p2, p_bufb);
            gemm_tc(p_bufb, p_wb + W_E1 + (size_t)mi * 8 * 3072 * 768, eb1 + (long long)mi * NE * NHID_, p_eb1b,
                    CAP, NHID_, EMS, 3, NE,
                    (long long)CAP * EMS, (long long)3072 * 768, NHID_, (long long)CAP * NHID_);
            gemm_tc(p_eb1b, p_wb + W_E2 + (size_t)mi * 8 * 768 * 3072, eb2 + (long long)mi * NE * EMS, p_eb2,
                    CAP, EMS, NHID_, 0, NE,
                    (long long)CAP * NHID_, (long long)768 * 3072, EMS, (long long)CAP * EMS);
            ln_gather_kernel<<<STOK, 256>>>(p_h, p_eb2, p_e1, p_e2, p_p1, p_p2, p_g1, p_g2,
                                            ln2g + i * EMS, ln2b + i * EMS, p_hb);
            mi++;
        }
    }

    cls_extract_kernel<<<BAT, 256>>>(p_h, p_cls);
    sgemm_kernel<<<dim3((NCLS + BN - 1) / BN, (BAT + BM - 1) / BM), 256>>>(p_cls, decw, decb, p_logits, BAT, NCLS, EMS, 0);
    loss_kernel<<<BAT, 256>>>(p_logits, y, p_lossb);
    sum_kernel<<<1, 32>>>(p_lossb, (float*)d_out);
}

// round 14
// speedup vs baseline: 1.0283x; 1.0283x over previous
#include <cuda_runtime.h>
#include <cuda_bf16.h>
#include <math.h>

// ---------------- problem constants ----------------
constexpr int EMS   = 768;
constexpr int NHD   = 12;
constexpr int HDM   = 64;
constexpr int SEQL  = 65;
constexpr int BAT   = 256;
constexpr int STOK  = BAT * SEQL;       // 16640
constexpr int NHID_ = 3072;
constexpr int NE    = 8;
constexpr int CAP   = 2600;
constexpr int NCHUNK = 130;
constexpr int NCLS  = 1000;

// ---------------- bf16 transposed weight buffer ----------------
constexpr size_t W_QKV = 0;
constexpr size_t SZ_QKV = (size_t)8 * 2304 * 768;
constexpr size_t W_O  = W_QKV + SZ_QKV;
constexpr size_t SZ_O = (size_t)8 * 768 * 768;
constexpr size_t W_D1 = W_O + SZ_O;
constexpr size_t SZ_D1 = (size_t)4 * 3072 * 768;
constexpr size_t W_D2 = W_D1 + SZ_D1;
constexpr size_t SZ_D2 = (size_t)4 * 768 * 3072;
constexpr size_t W_E1 = W_D2 + SZ_D2;
constexpr size_t SZ_E1 = (size_t)32 * 3072 * 768;
constexpr size_t W_E2 = W_E1 + SZ_E1;
constexpr size_t SZ_E2 = (size_t)32 * 768 * 3072;
constexpr size_t W_TOTAL = W_E2 + SZ_E2;

__device__ __nv_bfloat16 g_wbf[W_TOTAL];

// ---------------- scratch ----------------
__device__ float g_h   [(size_t)STOK * EMS];
__device__ float g_qkv [(size_t)STOK * 3 * EMS];   // low half reused as bf16 qkv
__device__ float g_attn[(size_t)STOK * EMS];
__device__ float g_f2  [(size_t)STOK * EMS];
__device__ float g_patch[(size_t)BAT * 64 * 48];
__device__ float g_ebuf2[(size_t)NE * CAP * EMS];
__device__ float g_logits[BAT * NCLS];
__device__ float g_clsrow[BAT * EMS];
__device__ float g_lossb[BAT];
__device__ float g_g1[STOK], g_g2[STOK];
__device__ int   g_e1[STOK], g_e2[STOK], g_p1[STOK], g_p2[STOK];
__device__ int   g_h1[NCHUNK * NE], g_h2[NCHUNK * NE];
__device__ int   g_o1[NCHUNK * NE], g_o2[NCHUNK * NE];

__device__ __nv_bfloat16 g_hb   [(size_t)STOK * EMS];
__device__ __nv_bfloat16 g_attnb[(size_t)STOK * EMS];
__device__ __nv_bfloat16 g_f1b  [(size_t)STOK * NHID_];
__device__ __nv_bfloat16 g_bufb [(size_t)NE * CAP * EMS];
__device__ __nv_bfloat16 g_eb1b [(size_t)NE * CAP * NHID_];

// ---------------- small PTX helpers (base ISA only) ----------------
__device__ __forceinline__ unsigned smem_u32(const void* p) {
    unsigned a;
    asm("{ .reg .u64 t; cvta.to.shared.u64 t, %1; cvt.u32.u64 %0, t; }" : "=r"(a) : "l"(p));
    return a;
}
__device__ __forceinline__ void cp_async16(unsigned dst, const void* src) {
    asm volatile("cp.async.cg.shared.global [%0], [%1], 16;" :: "r"(dst), "l"(src));
}
__device__ __forceinline__ void cp_commit() { asm volatile("cp.async.commit_group;"); }
template <int N>
__device__ __forceinline__ void cp_wait() { asm volatile("cp.async.wait_group %0;" :: "n"(N)); }

__device__ __forceinline__ void ldmx4(unsigned* r, unsigned addr) {
    asm volatile("ldmatrix.sync.aligned.m8n8.x4.shared.b16 {%0,%1,%2,%3}, [%4];"
                 : "=r"(r[0]), "=r"(r[1]), "=r"(r[2]), "=r"(r[3]) : "r"(addr));
}
__device__ __forceinline__ void mma16816(float* d, const unsigned* a, unsigned b0, unsigned b1) {
    asm volatile("mma.sync.aligned.m16n8k16.row.col.f32.bf16.bf16.f32 "
                 "{%0,%1,%2,%3}, {%4,%5,%6,%7}, {%8,%9}, {%0,%1,%2,%3};"
                 : "+f"(d[0]), "+f"(d[1]), "+f"(d[2]), "+f"(d[3])
                 : "r"(a[0]), "r"(a[1]), "r"(a[2]), "r"(a[3]), "r"(b0), "r"(b1));
}
__device__ __forceinline__ unsigned long long pack2(float lo, float hi) {
    unsigned long long r;
    asm("mov.b64 %0, {%1, %2};" : "=l"(r) : "f"(lo), "f"(hi));
    return r;
}
__device__ __forceinline__ void fma2(unsigned long long& d, unsigned long long a, unsigned long long b) {
    asm("fma.rn.f32x2 %0, %1, %2, %0;" : "+l"(d) : "l"(a), "l"(b));
}
__device__ __forceinline__ float2 unpack2(unsigned long long v) {
    float2 f;
    asm("mov.b64 {%0, %1}, %2;" : "=f"(f.x), "=f"(f.y) : "l"(v));
    return f;
}

// ---------------- bf16 tensor-core GEMM via mma.sync (v4: 4-stage, PROVEN BEST) ----------------
// C[M,N] = A[M,K] @ Bt[N,K]^T + bias.  A,Bt bf16 row-major; K%32==0, N%128==0.
// 256 threads, 8 warps (4x2), warp tile 32x64, 4-stage cp.async (BK=32), 1 sync/iter.
// 82 KB smem/CTA -> 2 CTAs/SM = 16 warps/SM (calibrated minimum for latency hiding).
// mode bits: bit0 = relu, bit1 = bf16 output
constexpr int HROWB = 80;                  // 32 bf16 (64B) + 16B pad -> conflict-free ldmatrix
constexpr int HSTAGE = 2 * 128 * HROWB;    // A tile + B tile = 20480 bytes
constexpr int NSTG = 4;
constexpr int HG_SMEM = NSTG * HSTAGE;     // 81920

__global__ void __launch_bounds__(256) hgemm_kernel(
    const __nv_bfloat16* __restrict__ A, const __nv_bfloat16* __restrict__ Bt,
    const float* __restrict__ bias, void* __restrict__ Cout,
    int M, int N, int K, int mode,
    long long strA, long long strB, long long strBias, long long strC)
{
    extern __shared__ __align__(16) char smem[];
    const unsigned sb = smem_u32(smem);
    const int tid = threadIdx.x;
    const int wid = tid >> 5, lane = tid & 31;

    A    += (long long)blockIdx.z * strA;
    Bt   += (long long)blockIdx.z * strB;
    bias += (long long)blockIdx.z * strBias;

    const int brow = blockIdx.y * 128;
    const int bcol = blockIdx.x * 128;
    const int KIT = K >> 5;                // BK = 32

    // per-thread load slots: 2 A chunks + 2 B chunks of 16B each
    const int c0 = tid, c1 = tid + 256;
    const int ar0 = c0 >> 2, ac0 = (c0 & 3) * 16;
    const int ar1 = c1 >> 2, ac1 = (c1 & 3) * 16;
    const __nv_bfloat16* Arow0 = A + (size_t)min(brow + ar0, M - 1) * K;
    const __nv_bfloat16* Arow1 = A + (size_t)min(brow + ar1, M - 1) * K;
    const __nv_bfloat16* Brow0 = Bt + (size_t)(bcol + ar0) * K;
    const __nv_bfloat16* Brow1 = Bt + (size_t)(bcol + ar1) * K;

    auto load_stage = [&](int st, int k0) {
        const unsigned sa = sb + st * HSTAGE;
        const unsigned sbm = sa + 128 * HROWB;
        cp_async16(sa + ar0 * HROWB + ac0, (const char*)(Arow0 + k0) + ac0);
        cp_async16(sa + ar1 * HROWB + ac1, (const char*)(Arow1 + k0) + ac1);
        cp_async16(sbm + ar0 * HROWB + ac0, (const char*)(Brow0 + k0) + ac0);
        cp_async16(sbm + ar1 * HROWB + ac1, (const char*)(Brow1 + k0) + ac1);
    };

    float acc[2][8][4];
#pragma unroll
    for (int i = 0; i < 2; i++)
#pragma unroll
        for (int j = 0; j < 8; j++)
#pragma unroll
            for (int q = 0; q < 4; q++) acc[i][j][q] = 0.f;

    const int wm = wid >> 1;              // 0..3  -> rows wm*32..+31
    const int wn = wid & 1;               // 0..1  -> cols wn*64..+63
    const unsigned aFragOff = (unsigned)((wm * 32 + (lane & 15)) * HROWB + (lane >> 4) * 16);
    const unsigned bFragOff = (unsigned)(128 * HROWB +
        (wn * 64 + ((lane >> 3) & 1) * 8 + (lane & 7)) * HROWB + (lane >> 4) * 16);

    // prologue: stages 0,1,2
#pragma unroll
    for (int s = 0; s < NSTG - 1; s++) {
        if (s < KIT) load_stage(s, s * 32);
        cp_commit();
    }

    int cur = 0;
    for (int it = 0; it < KIT; it++) {
        cp_wait<NSTG - 2>();
        __syncthreads();
        {
            const int pf = it + NSTG - 1;
            if (pf < KIT) {
                int pfs = cur + NSTG - 1; if (pfs >= NSTG) pfs -= NSTG;
                load_stage(pfs, pf * 32);
            }
            cp_commit();
        }
        const unsigned aBase = sb + cur * HSTAGE + aFragOff;
        const unsigned bBase = sb + cur * HSTAGE + bFragOff;
#pragma unroll
        for (int ks = 0; ks < 2; ks++) {
            unsigned afr[2][4];
            ldmx4(afr[0], aBase + ks * 32);
            ldmx4(afr[1], aBase + ks * 32 + 16 * HROWB);
#pragma unroll
            for (int ng = 0; ng < 4; ng++) {
                unsigned bfr[4];
                ldmx4(bfr, bBase + ks * 32 + ng * 16 * HROWB);
#pragma unroll
                for (int mt = 0; mt < 2; mt++) {
                    mma16816(acc[mt][2 * ng + 0], afr[mt], bfr[0], bfr[2]);
                    mma16816(acc[mt][2 * ng + 1], afr[mt], bfr[1], bfr[3]);
                }
            }
        }
        cur++; if (cur >= NSTG) cur = 0;
    }

    // ---- epilogue: direct register -> global ----
    const bool relu = (mode & 1);
    const bool isbf = (mode & 2);
    float* Cf = (float*)Cout + (long long)blockIdx.z * strC;
    __nv_bfloat16* Cb = (__nv_bfloat16*)Cout + (long long)blockIdx.z * strC;
    const int rbase = brow + wm * 32 + (lane >> 2);
    const int cbase = bcol + wn * 64 + 2 * (lane & 3);
#pragma unroll
    for (int mt = 0; mt < 2; mt++) {
#pragma unroll
        for (int nt = 0; nt < 8; nt++) {
            const int gcol = cbase + nt * 8;
            const float b0 = bias[gcol], b1 = bias[gcol + 1];
#pragma unroll
            for (int half = 0; half < 2; half++) {
                const int grow = rbase + mt * 16 + half * 8;
                if (grow < M) {
                    float v0 = acc[mt][nt][2 * half + 0] + b0;
                    float v1 = acc[mt][nt][2 * half + 1] + b1;
                    if (relu) { v0 = fmaxf(v0, 0.f); v1 = fmaxf(v1, 0.f); }
                    if (isbf) {
                        __nv_bfloat162 p;
                        p.x = __float2bfloat16(v0); p.y = __float2bfloat16(v1);
                        *reinterpret_cast<__nv_bfloat162*>(Cb + (size_t)grow * N + gcol) = p;
                    } else {
                        *reinterpret_cast<float2*>(Cf + (size_t)grow * N + gcol) = make_float2(v0, v1);
                    }
                }
            }
        }
    }
}

// ---------------- weight transpose+convert: fp32 [R,C] -> bf16 [C,R], batched ----------------
__global__ void wtrans_kernel(const float* __restrict__ src, __nv_bfloat16* __restrict__ dst, int R, int C) {
    __shared__ float t[32][33];
    src += (size_t)blockIdx.z * R * C;
    dst += (size_t)blockIdx.z * R * C;
    const int c0 = blockIdx.x * 32, r0 = blockIdx.y * 32;
    const int x = threadIdx.x, y = threadIdx.y;
#pragma unroll
    for (int i = 0; i < 32; i += 8) {
        const int r = r0 + y + i, c = c0 + x;
        t[y + i][x] = (r < R && c < C) ? src[(size_t)r * C + c] : 0.f;
    }
    __syncthreads();
#pragma unroll
    for (int i = 0; i < 32; i += 8) {
        const int c = c0 + y + i, r = r0 + x;
        if (c < C && r < R) dst[(size_t)c * R + r] = __float2bfloat16(t[x][y + i]);
    }
}

// ---------------- fp32 fallback SGEMM (patch embed, decoder) ----------------
constexpr int BM = 128, BN = 128, BKx = 8;

__global__ __launch_bounds__(256, 2) void sgemm_kernel(
    const float* __restrict__ A, const float* __restrict__ Bm,
    const float* __restrict__ bias, float* __restrict__ Cm,
    int M, int N, int K, int relu)
{
    __shared__ __align__(16) float As[BKx][BM];
    __shared__ __align__(16) float Bs[BKx][BN];
    const int tid  = threadIdx.x;
    const int brow = blockIdx.y * BM;
    const int bcol = blockIdx.x * BN;
    const int tx = tid & 15, ty = tid >> 4;
    const int aRow = tid >> 1, aCol = (tid & 1) * 4;
    const int bRowL = tid >> 5, bColL = (tid & 31) * 4;

    unsigned long long acc[8][4];
#pragma unroll
    for (int i = 0; i < 8; i++)
#pragma unroll
        for (int j = 0; j < 4; j++) acc[i][j] = 0ull;
    const bool n4 = ((N & 3) == 0);

    for (int k0 = 0; k0 < K; k0 += BKx) {
        float4 av = make_float4(0.f, 0.f, 0.f, 0.f);
        const int gr = brow + aRow;
        if (gr < M && k0 + aCol < K) av = *reinterpret_cast<const float4*>(A + (long long)gr * K + k0 + aCol);
        As[aCol + 0][aRow] = av.x; As[aCol + 1][aRow] = av.y;
        As[aCol + 2][aRow] = av.z; As[aCol + 3][aRow] = av.w;
        const int gc = bcol + bColL;
        const int kr = k0 + bRowL;
        const float* bp = Bm + (long long)kr * N + gc;
        if (n4) {
            float4 bv = make_float4(0.f, 0.f, 0.f, 0.f);
            if (gc < N && kr < K) bv = *reinterpret_cast<const float4*>(bp);
            Bs[bRowL][bColL + 0] = bv.x; Bs[bRowL][bColL + 1] = bv.y;
            Bs[bRowL][bColL + 2] = bv.z; Bs[bRowL][bColL + 3] = bv.w;
        } else {
#pragma unroll
            for (int q = 0; q < 4; q++)
                Bs[bRowL][bColL + q] = (gc + q < N && kr < K) ? bp[q] : 0.f;
        }
        __syncthreads();
#pragma unroll
        for (int kk = 0; kk < BKx; kk++) {
            const float4 a0 = *reinterpret_cast<const float4*>(&As[kk][ty * 8]);
            const float4 a1 = *reinterpret_cast<const float4*>(&As[kk][ty * 8 + 4]);
            const unsigned long long b0 = *reinterpret_cast<const unsigned long long*>(&Bs[kk][tx * 8 + 0]);
            const unsigned long long b1 = *reinterpret_cast<const unsigned long long*>(&Bs[kk][tx * 8 + 2]);
            const unsigned long long b2 = *reinterpret_cast<const unsigned long long*>(&Bs[kk][tx * 8 + 4]);
            const unsigned long long b3 = *reinterpret_cast<const unsigned long long*>(&Bs[kk][tx * 8 + 6]);
            const float aa[8] = {a0.x, a0.y, a0.z, a0.w, a1.x, a1.y, a1.z, a1.w};
#pragma unroll
            for (int i = 0; i < 8; i++) {
                const unsigned long long ad = pack2(aa[i], aa[i]);
                fma2(acc[i][0], ad, b0); fma2(acc[i][1], ad, b1);
                fma2(acc[i][2], ad, b2); fma2(acc[i][3], ad, b3);
            }
        }
        __syncthreads();
    }
#pragma unroll
    for (int i = 0; i < 8; i++) {
        const int gi = brow + ty * 8 + i;
        if (gi >= M) continue;
#pragma unroll
        for (int j = 0; j < 4; j++) {
            const float2 v = unpack2(acc[i][j]);
            const int gj = bcol + tx * 8 + 2 * j;
            if (gj < N) {
                float c = v.x + bias[gj];
                if (relu) c = fmaxf(c, 0.f);
                Cm[(long long)gi * N + gj] = c;
            }
            if (gj + 1 < N) {
                float c = v.y + bias[gj + 1];
                if (relu) c = fmaxf(c, 0.f);
                Cm[(long long)gi * N + gj + 1] = c;
            }
        }
    }
}

// ---------------- patch embed prep ----------------
__global__ void patch_kernel(const float* __restrict__ x, float* __restrict__ p) {
    const int total = BAT * 64 * 48;
    for (int idx = blockIdx.x * blockDim.x + threadIdx.x; idx < total; idx += gridDim.x * blockDim.x) {
        const int f = idx % 48;
        const int token = idx / 48;
        const int b = token >> 6;
        const int ij = token & 63;
        const int i = ij >> 3, j = ij & 7;
        const int c = f >> 4, r = (f >> 2) & 3, q = f & 3;
        p[idx] = x[((b * 3 + c) * 32 + (i * 4 + r)) * 32 + (j * 4 + q)];
    }
}

__global__ void assemble_kernel(const float* __restrict__ emb, const float* __restrict__ cls,
                                const float* __restrict__ pos, float* __restrict__ h,
                                __nv_bfloat16* __restrict__ hb) {
    const long long total = (long long)STOK * EMS;
    for (long long idx = (long long)blockIdx.x * blockDim.x + threadIdx.x; idx < total;
         idx += (long long)gridDim.x * blockDim.x) {
        const int d = (int)(idx % EMS);
        const long long s = idx / EMS;
        const int b = (int)(s / SEQL), t = (int)(s % SEQL);
        float v = pos[t * EMS + d];
        v += (t == 0) ? cls[d] : emb[((long long)b * 64 + (t - 1)) * EMS + d];
        h[idx] = v;
        hb[idx] = __float2bfloat16(v);
    }
}

// ---------------- attention (bf16 qkv in, bf16 out), packed fp32x2 ----------------
constexpr int KVSTR = 66;   // even stride -> 8B-aligned rows for LDS.64
__global__ void __launch_bounds__(256) attn_kernel(const __nv_bfloat16* __restrict__ qkv,
                                                   __nv_bfloat16* __restrict__ out) {
    __shared__ float ks[SEQL][KVSTR];
    __shared__ float vs[SEQL][KVSTR];
    __shared__ float qrow[8][HDM];
    __shared__ float probs[8][SEQL + 1];

    const int h = blockIdx.x, b = blockIdx.y;
    const int tid = threadIdx.x, warp = tid >> 5, lane = tid & 31;
    const __nv_bfloat16* base = qkv + (long long)b * SEQL * (3 * EMS);

    for (int idx = tid; idx < SEQL * HDM; idx += 256) {
        const int k = idx >> 6, d = idx & 63;
        ks[k][d] = __bfloat162float(base[(long long)k * (3 * EMS) + EMS     + h * HDM + d]);
        vs[k][d] = __bfloat162float(base[(long long)k * (3 * EMS) + 2 * EMS + h * HDM + d]);
    }
    __syncthreads();

    for (int q = warp; q < SEQL; q += 8) {
        qrow[warp][lane]      = __bfloat162float(base[(long long)q * (3 * EMS) + h * HDM + lane]);
        qrow[warp][lane + 32] = __bfloat162float(base[(long long)q * (3 * EMS) + h * HDM + lane + 32]);
        __syncwarp();
        float sc[3];
        float mx = -1e30f;
        const unsigned long long* qp = reinterpret_cast<const unsigned long long*>(&qrow[warp][0]);
#pragma unroll
        for (int ii = 0; ii < 3; ii++) {
            const int kk = lane + ii * 32;
            float acc = 0.f;
            if (kk < SEQL) {
                const unsigned long long* kp = reinterpret_cast<const unsigned long long*>(&ks[kk][0]);
                unsigned long long a2 = 0ull;
#pragma unroll
                for (int j2 = 0; j2 < 32; j2++) fma2(a2, qp[j2], kp[j2]);
                const float2 f = unpack2(a2);
                acc = (f.x + f.y) * 0.125f;
                mx = fmaxf(mx, acc);
            }
            sc[ii] = acc;
        }
        for (int o = 16; o > 0; o >>= 1) mx = fmaxf(mx, __shfl_xor_sync(0xffffffffu, mx, o));
        float sum = 0.f;
#pragma unroll
        for (int ii = 0; ii < 3; ii++) {
            const int kk = lane + ii * 32;
            float p = 0.f;
            if (kk < SEQL) { p = expf(sc[ii] - mx); sum += p; }
            sc[ii] = p;
        }
        for (int o = 16; o > 0; o >>= 1) sum += __shfl_xor_sync(0xffffffffu, sum, o);
        const float inv = 1.f / sum;
#pragma unroll
        for (int ii = 0; ii < 3; ii++) {
            const int kk = lane + ii * 32;
            if (kk < SEQL) probs[warp][kk] = sc[ii] * inv;
        }
        __syncwarp();
        // AV: each lane covers d = 2*lane, 2*lane+1 (packed)
        {
            const int d0 = 2 * lane;
            unsigned long long o2 = 0ull;
            for (int k = 0; k < SEQL; k++) {
                const float p = probs[warp][k];
                fma2(o2, pack2(p, p),
                     *reinterpret_cast<const unsigned long long*>(&vs[k][d0]));
            }
            const float2 f = unpack2(o2);
            __nv_bfloat162 pr;
            pr.x = __float2bfloat16(f.x);
            pr.y = __float2bfloat16(f.y);
            *reinterpret_cast<__nv_bfloat162*>(
                out + ((long long)(b * SEQL + q)) * EMS + h * HDM + d0) = pr;
        }
        __syncwarp();
    }
}

// ---------------- layernorm (shuffle reductions; writes fp32 h + bf16 copy) ----------------
__global__ void __launch_bounds__(256) ln_kernel(float* __restrict__ h, const float* __restrict__ a,
                          const float* __restrict__ g, const float* __restrict__ bta,
                          __nv_bfloat16* __restrict__ hb) {
    __shared__ float wred[8];
    const long long base = (long long)blockIdx.x * EMS;
    const int tid = threadIdx.x, warp = tid >> 5, lane = tid & 31;
    const float x0 = h[base + tid]       + a[base + tid];
    const float x1 = h[base + tid + 256] + a[base + tid + 256];
    const float x2 = h[base + tid + 512] + a[base + tid + 512];
    float s = x0 + x1 + x2;
    for (int o = 16; o > 0; o >>= 1) s += __shfl_xor_sync(0xffffffffu, s, o);
    if (lane == 0) wred[warp] = s;
    __syncthreads();
    float tot = 0.f;
#pragma unroll
    for (int w = 0; w < 8; w++) tot += wred[w];
    const float mean = tot / (float)EMS;
    __syncthreads();
    const float d0 = x0 - mean, d1 = x1 - mean, d2 = x2 - mean;
    float v = d0 * d0 + d1 * d1 + d2 * d2;
    for (int o = 16; o > 0; o >>= 1) v += __shfl_xor_sync(0xffffffffu, v, o);
    if (lane == 0) wred[warp] = v;
    __syncthreads();
    float vtot = 0.f;
#pragma unroll
    for (int w = 0; w < 8; w++) vtot += wred[w];
    const float rstd = rsqrtf(vtot / (float)EMS + 1e-5f);
    const float r0 = d0 * rstd * g[tid]       + bta[tid];
    const float r1 = d1 * rstd * g[tid + 256] + bta[tid + 256];
    const float r2 = d2 * rstd * g[tid + 512] + bta[tid + 512];
    h[base + tid]       = r0;  hb[base + tid]       = __float2bfloat16(r0);
    h[base + tid + 256] = r1;  hb[base + tid + 256] = __float2bfloat16(r1);
    h[base + tid + 512] = r2;  hb[base + tid + 512] = __float2bfloat16(r2);
}

// ---------------- fused MoE keep-mask + gather + layernorm ----------------
__global__ void __launch_bounds__(256) ln_gather_kernel(
    float* __restrict__ h, const float* __restrict__ oe,
    const int* __restrict__ e1, const int* __restrict__ e2,
    const int* __restrict__ p1, const int* __restrict__ p2,
    const float* __restrict__ g1, const float* __restrict__ g2,
    const float* __restrict__ g, const float* __restrict__ bta,
    __nv_bfloat16* __restrict__ hb) {
    __shared__ float wred[8];
    const int s = blockIdx.x;
    const long long base = (long long)s * EMS;
    const int tid = threadIdx.x, warp = tid >> 5, lane = tid & 31;
    const int pp1 = p1[s], pp2 = p2[s];
    const float a = g1[s] * (pp1 < CAP ? 1.f : 0.f);
    const float bgl = g2[s] * (pp2 < CAP ? 1.f : 0.f);
    const float den = fmaxf(a + bgl, 1e-9f);
    const float w1 = a / den, w2 = bgl / den;
    const int q1 = min(pp1, CAP - 1), q2 = min(pp2, CAP - 1);
    const float* r1 = oe + ((long long)e1[s] * CAP + q1) * EMS;
    const float* r2 = oe + ((long long)e2[s] * CAP + q2) * EMS;

    const float x0 = h[base + tid]       + r1[tid]       * w1 + r2[tid]       * w2;
    const float x1 = h[base + tid + 256] + r1[tid + 256] * w1 + r2[tid + 256] * w2;
    const float x2 = h[base + tid + 512] + r1[tid + 512] * w1 + r2[tid + 512] * w2;
    float sm = x0 + x1 + x2;
    for (int o = 16; o > 0; o >>= 1) sm += __shfl_xor_sync(0xffffffffu, sm, o);
    if (lane == 0) wred[warp] = sm;
    __syncthreads();
    float tot = 0.f;
#pragma unroll
    for (int w = 0; w < 8; w++) tot += wred[w];
    const float mean = tot / (float)EMS;
    __syncthreads();
    const float d0 = x0 - mean, d1 = x1 - mean, d2 = x2 - mean;
    float v = d0 * d0 + d1 * d1 + d2 * d2;
    for (int o = 16; o > 0; o >>= 1) v += __shfl_xor_sync(0xffffffffu, v, o);
    if (lane == 0) wred[warp] = v;
    __syncthreads();
    float vtot = 0.f;
#pragma unroll
    for (int w = 0; w < 8; w++) vtot += wred[w];
    const float rstd = rsqrtf(vtot / (float)EMS + 1e-5f);
    const float r0o = d0 * rstd * g[tid]       + bta[tid];
    const float r1o = d1 * rstd * g[tid + 256] + bta[tid + 256];
    const float r2o = d2 * rstd * g[tid + 512] + bta[tid + 512];
    h[base + tid]       = r0o;  hb[base + tid]       = __float2bfloat16(r0o);
    h[base + tid + 256] = r1o;  hb[base + tid + 256] = __float2bfloat16(r1o);
    h[base + tid + 512] = r2o;  hb[base + tid + 512] = __float2bfloat16(r2o);
}

// ---------------- MoE gating (fp32, exact) ----------------
__global__ void gate_kernel(const float* __restrict__ h, const float* __restrict__ gw,
                            int* __restrict__ e1o, int* __restrict__ e2o,
                            float* __restrict__ g1o, float* __restrict__ g2o) {
    const int token = (blockIdx.x * blockDim.x + threadIdx.x) >> 5;
    const int lane = threadIdx.x & 31;
    if (token >= STOK) return;
    const float* x = h + (long long)token * EMS;
    float part[NE] = {0.f, 0.f, 0.f, 0.f, 0.f, 0.f, 0.f, 0.f};
    for (int j = lane; j < EMS; j += 32) {
        const float xv = x[j];
        const float* w = gw + j * NE;
#pragma unroll
        for (int e = 0; e < NE; e++) part[e] += xv * w[e];
    }
#pragma unroll
    for (int e = 0; e < NE; e++)
        for (int o = 16; o > 0; o >>= 1) part[e] += __shfl_xor_sync(0xffffffffu, part[e], o);
    if (lane == 0) {
        float mx = part[0];
#pragma unroll
        for (int e = 1; e < NE; e++) mx = fmaxf(mx, part[e]);
        float gates[NE]; float se = 0.f;
#pragma unroll
        for (int e = 0; e < NE; e++) { gates[e] = expf(part[e] - mx); se += gates[e]; }
        int a1 = 0; float b1v = part[0];
#pragma unroll
        for (int e = 1; e < NE; e++) if (part[e] > b1v) { b1v = part[e]; a1 = e; }
        int a2 = -1; float b2v = -1e30f;
#pragma unroll
        for (int e = 0; e < NE; e++) if (e != a1 && part[e] > b2v) { b2v = part[e]; a2 = e; }
        e1o[token] = a1; e2o[token] = a2;
        g1o[token] = gates[a1] / se;
        g2o[token] = gates[a2] / se;
    }
}

__global__ void hist_kernel(const int* __restrict__ e1, const int* __restrict__ e2,
                            int* __restrict__ h1, int* __restrict__ h2) {
    __shared__ int s1[NE], s2[NE];
    const int tid = threadIdx.x;
    if (tid < NE) { s1[tid] = 0; s2[tid] = 0; }
    __syncthreads();
    const int s = blockIdx.x * 128 + tid;
    atomicAdd(&s1[e1[s]], 1);
    atomicAdd(&s2[e2[s]], 1);
    __syncthreads();
    if (tid < NE) {
        h1[blockIdx.x * NE + tid] = s1[tid];
        h2[blockIdx.x * NE + tid] = s2[tid];
    }
}

__global__ void scan_kernel(const int* __restrict__ h1, const int* __restrict__ h2,
                            int* __restrict__ o1, int* __restrict__ o2) {
    const int e = threadIdx.x;
    if (e < NE) {
        int run = 0;
        for (int c = 0; c < NCHUNK; c++) { o1[c * NE + e] = run; run += h1[c * NE + e]; }
        int run2 = run;
        for (int c = 0; c < NCHUNK; c++) { o2[c * NE + e] = run2; run2 += h2[c * NE + e]; }
    }
}

__global__ void rank_kernel(const int* __restrict__ e1, const int* __restrict__ e2,
                            const int* __restrict__ o1, const int* __restrict__ o2,
                            int* __restrict__ p1, int* __restrict__ p2) {
    const int t = threadIdx.x, c = blockIdx.x;
    if (t < NE) {
        const int e = t;
        int r = o1[c * NE + e];
        for (int i = 0; i < 128; i++) {
            const int s = c * 128 + i;
            if (e1[s] == e) p1[s] = r++;
        }
    } else if (t < 2 * NE) {
        const int e = t - NE;
        int r = o2[c * NE + e];
        for (int i = 0; i < 128; i++) {
            const int s = c * 128 + i;
            if (e2[s] == e) p2[s] = r++;
        }
    }
}

// scatter reads the bf16 mirror hb with vectorized 16B copies
__global__ void scatter_kernel(const __nv_bfloat16* __restrict__ hb, const int* __restrict__ e1,
                               const int* __restrict__ e2, const int* __restrict__ p1,
                               const int* __restrict__ p2, __nv_bfloat16* __restrict__ buf) {
    const int s = blockIdx.x;
    const int q1 = p1[s], q2 = p2[s];
    const uint4* src = reinterpret_cast<const uint4*>(hb + (long long)s * EMS); // 96 uint4
    const int tid = threadIdx.x;   // blockDim = 128
    if (q1 < CAP) {
        uint4* d = reinterpret_cast<uint4*>(buf + ((long long)e1[s] * CAP + q1) * EMS);
        if (tid < 96) d[tid] = src[tid];
    }
    if (q2 < CAP) {
        uint4* d = reinterpret_cast<uint4*>(buf + ((long long)e2[s] * CAP + q2) * EMS);
        if (tid < 96) d[tid] = src[tid];
    }
}

// ---------------- decoder + loss ----------------
__global__ void cls_extract_kernel(const float* __restrict__ h, float* __restrict__ out) {
    const int b = blockIdx.x;
    for (int d = threadIdx.x; d < EMS; d += blockDim.x)
        out[b * EMS + d] = h[(long long)b * SEQL * EMS + d];
}

__global__ void loss_kernel(const float* __restrict__ logits, const int* __restrict__ y,
                            float* __restrict__ lossb) {
    __shared__ float red[256];
    const int b = blockIdx.x, tid = threadIdx.x;
    const float* l = logits + b * NCLS;
    float mx = -1e30f;
    for (int j = tid; j < NCLS; j += 256) mx = fmaxf(mx, l[j]);
    red[tid] = mx;
    __syncthreads();
    for (int o = 128; o > 0; o >>= 1) { if (tid < o) red[tid] = fmaxf(red[tid], red[tid + o]); __syncthreads(); }
    mx = red[0];
    __syncthreads();
    float s = 0.f;
    for (int j = tid; j < NCLS; j += 256) s += expf(l[j] - mx);
    red[tid] = s;
    __syncthreads();
    for (int o = 128; o > 0; o >>= 1) { if (tid < o) red[tid] += red[tid + o]; __syncthreads(); }
    if (tid == 0) lossb[b] = -(l[y[b]] - mx - logf(red[0]));
}

__global__ void sum_kernel(const float* __restrict__ lossb, float* __restrict__ out) {
    if (threadIdx.x == 0) {
        float s = 0.f;
        for (int i = 0; i < BAT; i++) s += lossb[i];
        out[0] = s;
    }
}

// ---------------- host side ----------------
static inline void gemm_tc(const __nv_bfloat16* A, const __nv_bfloat16* Bt, const float* bias,
                           void* C, int M, int N, int K, int mode, int batch = 1,
                           long long sA = 0, long long sB = 0, long long sBias = 0, long long sC = 0) {
    dim3 grid(N / 128, (M + 127) / 128, batch);
    hgemm_kernel<<<grid, 256, HG_SMEM>>>(A, Bt, bias, C, M, N, K, mode, sA, sB, sBias, sC);
}

extern "C" void kernel_launch(void* const* d_in, const int* in_sizes, int n_in,
                              void* d_out, int out_size) {
    const float* x       = (const float*)d_in[0];
    const int*   y       = (const int*)  d_in[1];
    const float* patch_w = (const float*)d_in[2];
    const float* patch_b = (const float*)d_in[3];
    const float* cls     = (const float*)d_in[4];
    const float* pos     = (const float*)d_in[5];
    const float* wqkv    = (const float*)d_in[6];
    const float* bqkv    = (const float*)d_in[7];
    const float* wo      = (const float*)d_in[8];
    const float* bo      = (const float*)d_in[9];
    const float* ln1g    = (const float*)d_in[10];
    const float* ln1b    = (const float*)d_in[11];
    const float* ln2g    = (const float*)d_in[12];
    const float* ln2b    = (const float*)d_in[13];
    const float* dw1     = (const float*)d_in[14];
    const float* db1     = (const float*)d_in[15];
    const float* dw2     = (const float*)d_in[16];
    const float* db2     = (const float*)d_in[17];
    const float* gw      = (const float*)d_in[18];
    const float* ew1     = (const float*)d_in[19];
    const float* eb1     = (const float*)d_in[20];
    const float* ew2     = (const float*)d_in[21];
    const float* eb2     = (const float*)d_in[22];
    const float* decw    = (const float*)d_in[23];
    const float* decb    = (const float*)d_in[24];

    cudaFuncSetAttribute(hgemm_kernel, cudaFuncAttributeMaxDynamicSharedMemorySize, HG_SMEM);

    float *p_h, *p_qkv, *p_attn, *p_f2, *p_patch, *p_eb2;
    float *p_logits, *p_cls, *p_lossb, *p_g1, *p_g2;
    int *p_e1, *p_e2, *p_p1, *p_p2, *p_h1, *p_h2, *p_o1, *p_o2;
    __nv_bfloat16 *p_wb, *p_hb, *p_attnb, *p_f1b, *p_bufb, *p_eb1b;
    cudaGetSymbolAddress((void**)&p_h, g_h);
    cudaGetSymbolAddress((void**)&p_qkv, g_qkv);
    cudaGetSymbolAddress((void**)&p_attn, g_attn);
    cudaGetSymbolAddress((void**)&p_f2, g_f2);
    cudaGetSymbolAddress((void**)&p_patch, g_patch);
    cudaGetSymbolAddress((void**)&p_eb2, g_ebuf2);
    cudaGetSymbolAddress((void**)&p_logits, g_logits);
    cudaGetSymbolAddress((void**)&p_cls, g_clsrow);
    cudaGetSymbolAddress((void**)&p_lossb, g_lossb);
    cudaGetSymbolAddress((void**)&p_g1, g_g1);
    cudaGetSymbolAddress((void**)&p_g2, g_g2);
    cudaGetSymbolAddress((void**)&p_e1, g_e1);
    cudaGetSymbolAddress((void**)&p_e2, g_e2);
    cudaGetSymbolAddress((void**)&p_p1, g_p1);
    cudaGetSymbolAddress((void**)&p_p2, g_p2);
    cudaGetSymbolAddress((void**)&p_h1, g_h1);
    cudaGetSymbolAddress((void**)&p_h2, g_h2);
    cudaGetSymbolAddress((void**)&p_o1, g_o1);
    cudaGetSymbolAddress((void**)&p_o2, g_o2);
    cudaGetSymbolAddress((void**)&p_wb, g_wbf);
    cudaGetSymbolAddress((void**)&p_hb, g_hb);
    cudaGetSymbolAddress((void**)&p_attnb, g_attnb);
    cudaGetSymbolAddress((void**)&p_f1b, g_f1b);
    cudaGetSymbolAddress((void**)&p_bufb, g_bufb);
    cudaGetSymbolAddress((void**)&p_eb1b, g_eb1b);

    __nv_bfloat16* p_qkvb = (__nv_bfloat16*)p_qkv;   // reuse fp32 scratch as bf16

    // ---- weight convert+transpose: fp32 [K,N] -> bf16 [N,K] ----
    dim3 tb(32, 8);
    wtrans_kernel<<<dim3(2304 / 32, 768 / 32, 8),  tb>>>(wqkv, p_wb + W_QKV, 768, 2304);
    wtrans_kernel<<<dim3(768 / 32,  768 / 32, 8),  tb>>>(wo,   p_wb + W_O,   768, 768);
    wtrans_kernel<<<dim3(3072 / 32, 768 / 32, 4),  tb>>>(dw1,  p_wb + W_D1,  768, 3072);
    wtrans_kernel<<<dim3(768 / 32, 3072 / 32, 4),  tb>>>(dw2,  p_wb + W_D2,  3072, 768);
    wtrans_kernel<<<dim3(3072 / 32, 768 / 32, 32), tb>>>(ew1,  p_wb + W_E1,  768, 3072);
    wtrans_kernel<<<dim3(768 / 32, 3072 / 32, 32), tb>>>(ew2,  p_wb + W_E2,  3072, 768);

    // ---- patch embed (fp32 SGEMM; K=48 small) ----
    patch_kernel<<<1024, 256>>>(x, p_patch);
    sgemm_kernel<<<dim3(768 / BN, (BAT * 64 + BM - 1) / BM), 256>>>(p_patch, patch_w, patch_b, p_attn, BAT * 64, EMS, 48, 0);
    assemble_kernel<<<8192, 256>>>(p_attn, cls, pos, p_h, p_hb);

    int di = 0, mi = 0;
    for (int i = 0; i < 8; i++) {
        gemm_tc(p_hb, p_wb + W_QKV + (size_t)i * 2304 * 768, bqkv + i * 3 * EMS, p_qkvb, STOK, 3 * EMS, EMS, 2);
        attn_kernel<<<dim3(NHD, BAT), 256>>>(p_qkvb, p_attnb);
        gemm_tc(p_attnb, p_wb + W_O + (size_t)i * 768 * 768, bo + i * EMS, p_f2, STOK, EMS, EMS, 0);
        ln_kernel<<<STOK, 256>>>(p_h, p_f2, ln1g + i * EMS, ln1b + i * EMS, p_hb);

        if ((i & 1) == 0) {
            gemm_tc(p_hb, p_wb + W_D1 + (size_t)di * 3072 * 768, db1 + di * NHID_, p_f1b, STOK, NHID_, EMS, 3);
            gemm_tc(p_f1b, p_wb + W_D2 + (size_t)di * 768 * 3072, db2 + di * EMS, p_f2, STOK, EMS, NHID_, 0);
            ln_kernel<<<STOK, 256>>>(p_h, p_f2, ln2g + i * EMS, ln2b + i * EMS, p_hb);
            di++;
        } else {
            gate_kernel<<<STOK / 8, 256>>>(p_h, gw + (long long)mi * EMS * NE, p_e1, p_e2, p_g1, p_g2);
            hist_kernel<<<NCHUNK, 128>>>(p_e1, p_e2, p_h1, p_h2);
            scan_kernel<<<1, 32>>>(p_h1, p_h2, p_o1, p_o2);
            rank_kernel<<<NCHUNK, 32>>>(p_e1, p_e2, p_o1, p_o2, p_p1, p_p2);
            // keep-mask + renorm folded into ln_gather (reads raw g1/g2 + p1/p2)
            scatter_kernel<<<STOK, 128>>>(p_hb, p_e1, p_e2, p_p1, p_p2, p_bufb);
            gemm_tc(p_bufb, p_wb + W_E1 + (size_t)mi * 8 * 3072 * 768, eb1 + (long long)mi * NE * NHID_, p_eb1b,
                    CAP, NHID_, EMS, 3, NE,
                    (long long)CAP * EMS, (long long)3072 * 768, NHID_, (long long)CAP * NHID_);
            gemm_tc(p_eb1b, p_wb + W_E2 + (size_t)mi * 8 * 768 * 3072, eb2 + (long long)mi * NE * EMS, p_eb2,
                    CAP, EMS, NHID_, 0, NE,
                    (long long)CAP * NHID_, (long long)768 * 3072, EMS, (long long)CAP * EMS);
            ln_gather_kernel<<<STOK, 256>>>(p_h, p_eb2, p_e1, p_e2, p_p1, p_p2, p_g1, p_g2,
                                            ln2g + i * EMS, ln2b + i * EMS, p_hb);
            mi++;
        }
    }

    cls_extract_kernel<<<BAT, 256>>>(p_h, p_cls);
    sgemm_kernel<<<dim3((NCLS + BN - 1) / BN, (BAT + BM - 1) / BM), 256>>>(p_cls, decw, decb, p_logits, BAT, NCLS, EMS, 0);
    loss_kernel<<<BAT, 256>>>(p_logits, y, p_lossb);
    sum_kernel<<<1, 32>>>(p_lossb, (float*)d_out);
}

// round 15
// speedup vs baseline: 1.0290x; 1.0007x over previous
#include <cuda_runtime.h>
#include <cuda_bf16.h>
#include <math.h>

// ---------------- problem constants ----------------
constexpr int EMS   = 768;
constexpr int NHD   = 12;
constexpr int HDM   = 64;
constexpr int SEQL  = 65;
constexpr int BAT   = 256;
constexpr int STOK  = BAT * SEQL;       // 16640
constexpr int NHID_ = 3072;
constexpr int NE    = 8;
constexpr int CAP   = 2600;
constexpr int NCHUNK = 130;
constexpr int NCLS  = 1000;

// ---------------- bf16 transposed weight buffer ----------------
constexpr size_t W_QKV = 0;
constexpr size_t SZ_QKV = (size_t)8 * 2304 * 768;
constexpr size_t W_O  = W_QKV + SZ_QKV;
constexpr size_t SZ_O = (size_t)8 * 768 * 768;
constexpr size_t W_D1 = W_O + SZ_O;
constexpr size_t SZ_D1 = (size_t)4 * 3072 * 768;
constexpr size_t W_D2 = W_D1 + SZ_D1;
constexpr size_t SZ_D2 = (size_t)4 * 768 * 3072;
constexpr size_t W_E1 = W_D2 + SZ_D2;
constexpr size_t SZ_E1 = (size_t)32 * 3072 * 768;
constexpr size_t W_E2 = W_E1 + SZ_E1;
constexpr size_t SZ_E2 = (size_t)32 * 768 * 3072;
constexpr size_t W_TOTAL = W_E2 + SZ_E2;

__device__ __nv_bfloat16 g_wbf[W_TOTAL];

// ---------------- scratch ----------------
__device__ float g_h   [(size_t)STOK * EMS];
__device__ float g_qkv [(size_t)STOK * 3 * EMS];   // low half reused as bf16 qkv
__device__ float g_attn[(size_t)STOK * EMS];
__device__ float g_f2  [(size_t)STOK * EMS];
__device__ float g_patch[(size_t)BAT * 64 * 48];
__device__ float g_ebuf2[(size_t)NE * CAP * EMS];
__device__ float g_logits[BAT * NCLS];
__device__ float g_clsrow[BAT * EMS];
__device__ float g_lossb[BAT];
__device__ float g_g1[STOK], g_g2[STOK];
__device__ int   g_e1[STOK], g_e2[STOK], g_p1[STOK], g_p2[STOK];
__device__ int   g_h1[NCHUNK * NE], g_h2[NCHUNK * NE];
__device__ int   g_o1[NCHUNK * NE], g_o2[NCHUNK * NE];

__device__ __nv_bfloat16 g_hb   [(size_t)STOK * EMS];
__device__ __nv_bfloat16 g_attnb[(size_t)STOK * EMS];
__device__ __nv_bfloat16 g_f1b  [(size_t)STOK * NHID_];
__device__ __nv_bfloat16 g_bufb [(size_t)NE * CAP * EMS];
__device__ __nv_bfloat16 g_eb1b [(size_t)NE * CAP * NHID_];

// ---------------- small PTX helpers (base ISA only) ----------------
__device__ __forceinline__ unsigned smem_u32(const void* p) {
    unsigned a;
    asm("{ .reg .u64 t; cvta.to.shared.u64 t, %1; cvt.u32.u64 %0, t; }" : "=r"(a) : "l"(p));
    return a;
}
__device__ __forceinline__ void cp_async16(unsigned dst, const void* src) {
    asm volatile("cp.async.cg.shared.global [%0], [%1], 16;" :: "r"(dst), "l"(src));
}
__device__ __forceinline__ void cp_commit() { asm volatile("cp.async.commit_group;"); }
template <int N>
__device__ __forceinline__ void cp_wait() { asm volatile("cp.async.wait_group %0;" :: "n"(N)); }

__device__ __forceinline__ void ldmx4(unsigned* r, unsigned addr) {
    asm volatile("ldmatrix.sync.aligned.m8n8.x4.shared.b16 {%0,%1,%2,%3}, [%4];"
                 : "=r"(r[0]), "=r"(r[1]), "=r"(r[2]), "=r"(r[3]) : "r"(addr));
}
__device__ __forceinline__ void mma16816(float* d, const unsigned* a, unsigned b0, unsigned b1) {
    asm volatile("mma.sync.aligned.m16n8k16.row.col.f32.bf16.bf16.f32 "
                 "{%0,%1,%2,%3}, {%4,%5,%6,%7}, {%8,%9}, {%0,%1,%2,%3};"
                 : "+f"(d[0]), "+f"(d[1]), "+f"(d[2]), "+f"(d[3])
                 : "r"(a[0]), "r"(a[1]), "r"(a[2]), "r"(a[3]), "r"(b0), "r"(b1));
}
__device__ __forceinline__ unsigned long long pack2(float lo, float hi) {
    unsigned long long r;
    asm("mov.b64 %0, {%1, %2};" : "=l"(r) : "f"(lo), "f"(hi));
    return r;
}
__device__ __forceinline__ void fma2(unsigned long long& d, unsigned long long a, unsigned long long b) {
    asm("fma.rn.f32x2 %0, %1, %2, %0;" : "+l"(d) : "l"(a), "l"(b));
}
__device__ __forceinline__ float2 unpack2(unsigned long long v) {
    float2 f;
    asm("mov.b64 {%0, %1}, %2;" : "=f"(f.x), "=f"(f.y) : "l"(v));
    return f;
}

// ---------------- bf16 tensor-core GEMM via mma.sync (v4: 4-stage, PROVEN BEST) ----------------
// C[M,N] = A[M,K] @ Bt[N,K]^T + bias.  A,Bt bf16 row-major; K%32==0, N%128==0.
// 256 threads, 8 warps (4x2), warp tile 32x64, 4-stage cp.async (BK=32), 1 sync/iter.
// 82 KB smem/CTA -> 2 CTAs/SM = 16 warps/SM (calibrated minimum for latency hiding;
// register file caps at 2 CTAs/SM at ~116 regs/thread, so smem <=100KB/CTA is free).
// mode bits: bit0 = relu, bit1 = bf16 output
constexpr int HROWB = 80;                  // 32 bf16 (64B) + 16B pad -> conflict-free ldmatrix
constexpr int HSTAGE = 2 * 128 * HROWB;    // A tile + B tile = 20480 bytes
constexpr int NSTG = 4;
constexpr int HG_SMEM = NSTG * HSTAGE;     // 81920

__global__ void __launch_bounds__(256) hgemm_kernel(
    const __nv_bfloat16* __restrict__ A, const __nv_bfloat16* __restrict__ Bt,
    const float* __restrict__ bias, void* __restrict__ Cout,
    int M, int N, int K, int mode,
    long long strA, long long strB, long long strBias, long long strC)
{
    extern __shared__ __align__(16) char smem[];
    const unsigned sb = smem_u32(smem);
    const int tid = threadIdx.x;
    const int wid = tid >> 5, lane = tid & 31;

    A    += (long long)blockIdx.z * strA;
    Bt   += (long long)blockIdx.z * strB;
    bias += (long long)blockIdx.z * strBias;

    const int brow = blockIdx.y * 128;
    const int bcol = blockIdx.x * 128;
    const int KIT = K >> 5;                // BK = 32

    // per-thread load slots: 2 A chunks + 2 B chunks of 16B each
    const int c0 = tid, c1 = tid + 256;
    const int ar0 = c0 >> 2, ac0 = (c0 & 3) * 16;
    const int ar1 = c1 >> 2, ac1 = (c1 & 3) * 16;
    const __nv_bfloat16* Arow0 = A + (size_t)min(brow + ar0, M - 1) * K;
    const __nv_bfloat16* Arow1 = A + (size_t)min(brow + ar1, M - 1) * K;
    const __nv_bfloat16* Brow0 = Bt + (size_t)(bcol + ar0) * K;
    const __nv_bfloat16* Brow1 = Bt + (size_t)(bcol + ar1) * K;

    auto load_stage = [&](int st, int k0) {
        const unsigned sa = sb + st * HSTAGE;
        const unsigned sbm = sa + 128 * HROWB;
        cp_async16(sa + ar0 * HROWB + ac0, (const char*)(Arow0 + k0) + ac0);
        cp_async16(sa + ar1 * HROWB + ac1, (const char*)(Arow1 + k0) + ac1);
        cp_async16(sbm + ar0 * HROWB + ac0, (const char*)(Brow0 + k0) + ac0);
        cp_async16(sbm + ar1 * HROWB + ac1, (const char*)(Brow1 + k0) + ac1);
    };

    float acc[2][8][4];
#pragma unroll
    for (int i = 0; i < 2; i++)
#pragma unroll
        for (int j = 0; j < 8; j++)
#pragma unroll
            for (int q = 0; q < 4; q++) acc[i][j][q] = 0.f;

    const int wm = wid >> 1;              // 0..3  -> rows wm*32..+31
    const int wn = wid & 1;               // 0..1  -> cols wn*64..+63
    const unsigned aFragOff = (unsigned)((wm * 32 + (lane & 15)) * HROWB + (lane >> 4) * 16);
    const unsigned bFragOff = (unsigned)(128 * HROWB +
        (wn * 64 + ((lane >> 3) & 1) * 8 + (lane & 7)) * HROWB + (lane >> 4) * 16);

    // prologue: stages 0,1,2
#pragma unroll
    for (int s = 0; s < NSTG - 1; s++) {
        if (s < KIT) load_stage(s, s * 32);
        cp_commit();
    }

    int cur = 0;
    for (int it = 0; it < KIT; it++) {
        cp_wait<NSTG - 2>();
        __syncthreads();
        {
            const int pf = it + NSTG - 1;
            if (pf < KIT) {
                int pfs = cur + NSTG - 1; if (pfs >= NSTG) pfs -= NSTG;
                load_stage(pfs, pf * 32);
            }
            cp_commit();
        }
        const unsigned aBase = sb + cur * HSTAGE + aFragOff;
        const unsigned bBase = sb + cur * HSTAGE + bFragOff;
#pragma unroll
        for (int ks = 0; ks < 2; ks++) {
            unsigned afr[2][4];
            ldmx4(afr[0], aBase + ks * 32);
            ldmx4(afr[1], aBase + ks * 32 + 16 * HROWB);
#pragma unroll
            for (int ng = 0; ng < 4; ng++) {
                unsigned bfr[4];
                ldmx4(bfr, bBase + ks * 32 + ng * 16 * HROWB);
#pragma unroll
                for (int mt = 0; mt < 2; mt++) {
                    mma16816(acc[mt][2 * ng + 0], afr[mt], bfr[0], bfr[2]);
                    mma16816(acc[mt][2 * ng + 1], afr[mt], bfr[1], bfr[3]);
                }
            }
        }
        cur++; if (cur >= NSTG) cur = 0;
    }

    // ---- epilogue: direct register -> global ----
    const bool relu = (mode & 1);
    const bool isbf = (mode & 2);
    float* Cf = (float*)Cout + (long long)blockIdx.z * strC;
    __nv_bfloat16* Cb = (__nv_bfloat16*)Cout + (long long)blockIdx.z * strC;
    const int rbase = brow + wm * 32 + (lane >> 2);
    const int cbase = bcol + wn * 64 + 2 * (lane & 3);
#pragma unroll
    for (int mt = 0; mt < 2; mt++) {
#pragma unroll
        for (int nt = 0; nt < 8; nt++) {
            const int gcol = cbase + nt * 8;
            const float b0 = bias[gcol], b1 = bias[gcol + 1];
#pragma unroll
            for (int half = 0; half < 2; half++) {
                const int grow = rbase + mt * 16 + half * 8;
                if (grow < M) {
                    float v0 = acc[mt][nt][2 * half + 0] + b0;
                    float v1 = acc[mt][nt][2 * half + 1] + b1;
                    if (relu) { v0 = fmaxf(v0, 0.f); v1 = fmaxf(v1, 0.f); }
                    if (isbf) {
                        __nv_bfloat162 p;
                        p.x = __float2bfloat16(v0); p.y = __float2bfloat16(v1);
                        *reinterpret_cast<__nv_bfloat162*>(Cb + (size_t)grow * N + gcol) = p;
                    } else {
                        *reinterpret_cast<float2*>(Cf + (size_t)grow * N + gcol) = make_float2(v0, v1);
                    }
                }
            }
        }
    }
}

// ---------------- weight transpose+convert: fp32 [R,C] -> bf16 [C,R], batched ----------------
__global__ void wtrans_kernel(const float* __restrict__ src, __nv_bfloat16* __restrict__ dst, int R, int C) {
    __shared__ float t[32][33];
    src += (size_t)blockIdx.z * R * C;
    dst += (size_t)blockIdx.z * R * C;
    const int c0 = blockIdx.x * 32, r0 = blockIdx.y * 32;
    const int x = threadIdx.x, y = threadIdx.y;
#pragma unroll
    for (int i = 0; i < 32; i += 8) {
        const int r = r0 + y + i, c = c0 + x;
        t[y + i][x] = (r < R && c < C) ? src[(size_t)r * C + c] : 0.f;
    }
    __syncthreads();
#pragma unroll
    for (int i = 0; i < 32; i += 8) {
        const int c = c0 + y + i, r = r0 + x;
        if (c < C && r < R) dst[(size_t)c * R + r] = __float2bfloat16(t[x][y + i]);
    }
}

// ---------------- fp32 fallback SGEMM (patch embed, decoder) ----------------
constexpr int BM = 128, BN = 128, BKx = 8;

__global__ __launch_bounds__(256, 2) void sgemm_kernel(
    const float* __restrict__ A, const float* __restrict__ Bm,
    const float* __restrict__ bias, float* __restrict__ Cm,
    int M, int N, int K, int relu)
{
    __shared__ __align__(16) float As[BKx][BM];
    __shared__ __align__(16) float Bs[BKx][BN];
    const int tid  = threadIdx.x;
    const int brow = blockIdx.y * BM;
    const int bcol = blockIdx.x * BN;
    const int tx = tid & 15, ty = tid >> 4;
    const int aRow = tid >> 1, aCol = (tid & 1) * 4;
    const int bRowL = tid >> 5, bColL = (tid & 31) * 4;

    unsigned long long acc[8][4];
#pragma unroll
    for (int i = 0; i < 8; i++)
#pragma unroll
        for (int j = 0; j < 4; j++) acc[i][j] = 0ull;
    const bool n4 = ((N & 3) == 0);

    for (int k0 = 0; k0 < K; k0 += BKx) {
        float4 av = make_float4(0.f, 0.f, 0.f, 0.f);
        const int gr = brow + aRow;
        if (gr < M && k0 + aCol < K) av = *reinterpret_cast<const float4*>(A + (long long)gr * K + k0 + aCol);
        As[aCol + 0][aRow] = av.x; As[aCol + 1][aRow] = av.y;
        As[aCol + 2][aRow] = av.z; As[aCol + 3][aRow] = av.w;
        const int gc = bcol + bColL;
        const int kr = k0 + bRowL;
        const float* bp = Bm + (long long)kr * N + gc;
        if (n4) {
            float4 bv = make_float4(0.f, 0.f, 0.f, 0.f);
            if (gc < N && kr < K) bv = *reinterpret_cast<const float4*>(bp);
            Bs[bRowL][bColL + 0] = bv.x; Bs[bRowL][bColL + 1] = bv.y;
            Bs[bRowL][bColL + 2] = bv.z; Bs[bRowL][bColL + 3] = bv.w;
        } else {
#pragma unroll
            for (int q = 0; q < 4; q++)
                Bs[bRowL][bColL + q] = (gc + q < N && kr < K) ? bp[q] : 0.f;
        }
        __syncthreads();
#pragma unroll
        for (int kk = 0; kk < BKx; kk++) {
            const float4 a0 = *reinterpret_cast<const float4*>(&As[kk][ty * 8]);
            const float4 a1 = *reinterpret_cast<const float4*>(&As[kk][ty * 8 + 4]);
            const unsigned long long b0 = *reinterpret_cast<const unsigned long long*>(&Bs[kk][tx * 8 + 0]);
            const unsigned long long b1 = *reinterpret_cast<const unsigned long long*>(&Bs[kk][tx * 8 + 2]);
            const unsigned long long b2 = *reinterpret_cast<const unsigned long long*>(&Bs[kk][tx * 8 + 4]);
            const unsigned long long b3 = *reinterpret_cast<const unsigned long long*>(&Bs[kk][tx * 8 + 6]);
            const float aa[8] = {a0.x, a0.y, a0.z, a0.w, a1.x, a1.y, a1.z, a1.w};
#pragma unroll
            for (int i = 0; i < 8; i++) {
                const unsigned long long ad = pack2(aa[i], aa[i]);
                fma2(acc[i][0], ad, b0); fma2(acc[i][1], ad, b1);
                fma2(acc[i][2], ad, b2); fma2(acc[i][3], ad, b3);
            }
        }
        __syncthreads();
    }
#pragma unroll
    for (int i = 0; i < 8; i++) {
        const int gi = brow + ty * 8 + i;
        if (gi >= M) continue;
#pragma unroll
        for (int j = 0; j < 4; j++) {
            const float2 v = unpack2(acc[i][j]);
            const int gj = bcol + tx * 8 + 2 * j;
            if (gj < N) {
                float c = v.x + bias[gj];
                if (relu) c = fmaxf(c, 0.f);
                Cm[(long long)gi * N + gj] = c;
            }
            if (gj + 1 < N) {
                float c = v.y + bias[gj + 1];
                if (relu) c = fmaxf(c, 0.f);
                Cm[(long long)gi * N + gj + 1] = c;
            }
        }
    }
}

// ---------------- patch embed prep ----------------
__global__ void patch_kernel(const float* __restrict__ x, float* __restrict__ p) {
    const int total = BAT * 64 * 48;
    for (int idx = blockIdx.x * blockDim.x + threadIdx.x; idx < total; idx += gridDim.x * blockDim.x) {
        const int f = idx % 48;
        const int token = idx / 48;
        const int b = token >> 6;
        const int ij = token & 63;
        const int i = ij >> 3, j = ij & 7;
        const int c = f >> 4, r = (f >> 2) & 3, q = f & 3;
        p[idx] = x[((b * 3 + c) * 32 + (i * 4 + r)) * 32 + (j * 4 + q)];
    }
}

__global__ void assemble_kernel(const float* __restrict__ emb, const float* __restrict__ cls,
                                const float* __restrict__ pos, float* __restrict__ h,
                                __nv_bfloat16* __restrict__ hb) {
    const long long total = (long long)STOK * EMS;
    for (long long idx = (long long)blockIdx.x * blockDim.x + threadIdx.x; idx < total;
         idx += (long long)gridDim.x * blockDim.x) {
        const int d = (int)(idx % EMS);
        const long long s = idx / EMS;
        const int b = (int)(s / SEQL), t = (int)(s % SEQL);
        float v = pos[t * EMS + d];
        v += (t == 0) ? cls[d] : emb[((long long)b * 64 + (t - 1)) * EMS + d];
        h[idx] = v;
        hb[idx] = __float2bfloat16(v);
    }
}

// ---------------- attention (bf16 qkv in, bf16 out), packed fp32x2 ----------------
constexpr int KVSTR = 66;   // even stride -> 8B-aligned rows for LDS.64
__global__ void __launch_bounds__(256) attn_kernel(const __nv_bfloat16* __restrict__ qkv,
                                                   __nv_bfloat16* __restrict__ out) {
    __shared__ float ks[SEQL][KVSTR];
    __shared__ float vs[SEQL][KVSTR];
    __shared__ float qrow[8][HDM];
    __shared__ float probs[8][SEQL + 1];

    const int h = blockIdx.x, b = blockIdx.y;
    const int tid = threadIdx.x, warp = tid >> 5, lane = tid & 31;
    const __nv_bfloat16* base = qkv + (long long)b * SEQL * (3 * EMS);

    for (int idx = tid; idx < SEQL * HDM; idx += 256) {
        const int k = idx >> 6, d = idx & 63;
        ks[k][d] = __bfloat162float(base[(long long)k * (3 * EMS) + EMS     + h * HDM + d]);
        vs[k][d] = __bfloat162float(base[(long long)k * (3 * EMS) + 2 * EMS + h * HDM + d]);
    }
    __syncthreads();

    for (int q = warp; q < SEQL; q += 8) {
        qrow[warp][lane]      = __bfloat162float(base[(long long)q * (3 * EMS) + h * HDM + lane]);
        qrow[warp][lane + 32] = __bfloat162float(base[(long long)q * (3 * EMS) + h * HDM + lane + 32]);
        __syncwarp();
        float sc[3];
        float mx = -1e30f;
        const unsigned long long* qp = reinterpret_cast<const unsigned long long*>(&qrow[warp][0]);
#pragma unroll
        for (int ii = 0; ii < 3; ii++) {
            const int kk = lane + ii * 32;
            float acc = 0.f;
            if (kk < SEQL) {
                const unsigned long long* kp = reinterpret_cast<const unsigned long long*>(&ks[kk][0]);
                unsigned long long a2 = 0ull;
#pragma unroll
                for (int j2 = 0; j2 < 32; j2++) fma2(a2, qp[j2], kp[j2]);
                const float2 f = unpack2(a2);
                acc = (f.x + f.y) * 0.125f;
                mx = fmaxf(mx, acc);
            }
            sc[ii] = acc;
        }
        for (int o = 16; o > 0; o >>= 1) mx = fmaxf(mx, __shfl_xor_sync(0xffffffffu, mx, o));
        float sum = 0.f;
#pragma unroll
        for (int ii = 0; ii < 3; ii++) {
            const int kk = lane + ii * 32;
            float p = 0.f;
            if (kk < SEQL) { p = expf(sc[ii] - mx); sum += p; }
            sc[ii] = p;
        }
        for (int o = 16; o > 0; o >>= 1) sum += __shfl_xor_sync(0xffffffffu, sum, o);
        const float inv = 1.f / sum;
#pragma unroll
        for (int ii = 0; ii < 3; ii++) {
            const int kk = lane + ii * 32;
            if (kk < SEQL) probs[warp][kk] = sc[ii] * inv;
        }
        __syncwarp();
        // AV: each lane covers d = 2*lane, 2*lane+1 (packed)
        {
            const int d0 = 2 * lane;
            unsigned long long o2 = 0ull;
            for (int k = 0; k < SEQL; k++) {
                const float p = probs[warp][k];
                fma2(o2, pack2(p, p),
                     *reinterpret_cast<const unsigned long long*>(&vs[k][d0]));
            }
            const float2 f = unpack2(o2);
            __nv_bfloat162 pr;
            pr.x = __float2bfloat16(f.x);
            pr.y = __float2bfloat16(f.y);
            *reinterpret_cast<__nv_bfloat162*>(
                out + ((long long)(b * SEQL + q)) * EMS + h * HDM + d0) = pr;
        }
        __syncwarp();
    }
}

// ---------------- layernorm (shuffle reductions; writes fp32 h + bf16 copy) ----------------
__global__ void __launch_bounds__(256) ln_kernel(float* __restrict__ h, const float* __restrict__ a,
                          const float* __restrict__ g, const float* __restrict__ bta,
                          __nv_bfloat16* __restrict__ hb) {
    __shared__ float wred[8];
    const long long base = (long long)blockIdx.x * EMS;
    const int tid = threadIdx.x, warp = tid >> 5, lane = tid & 31;
    const float x0 = h[base + tid]       + a[base + tid];
    const float x1 = h[base + tid + 256] + a[base + tid + 256];
    const float x2 = h[base + tid + 512] + a[base + tid + 512];
    float s = x0 + x1 + x2;
    for (int o = 16; o > 0; o >>= 1) s += __shfl_xor_sync(0xffffffffu, s, o);
    if (lane == 0) wred[warp] = s;
    __syncthreads();
    float tot = 0.f;
#pragma unroll
    for (int w = 0; w < 8; w++) tot += wred[w];
    const float mean = tot / (float)EMS;
    __syncthreads();
    const float d0 = x0 - mean, d1 = x1 - mean, d2 = x2 - mean;
    float v = d0 * d0 + d1 * d1 + d2 * d2;
    for (int o = 16; o > 0; o >>= 1) v += __shfl_xor_sync(0xffffffffu, v, o);
    if (lane == 0) wred[warp] = v;
    __syncthreads();
    float vtot = 0.f;
#pragma unroll
    for (int w = 0; w < 8; w++) vtot += wred[w];
    const float rstd = rsqrtf(vtot / (float)EMS + 1e-5f);
    const float r0 = d0 * rstd * g[tid]       + bta[tid];
    const float r1 = d1 * rstd * g[tid + 256] + bta[tid + 256];
    const float r2 = d2 * rstd * g[tid + 512] + bta[tid + 512];
    h[base + tid]       = r0;  hb[base + tid]       = __float2bfloat16(r0);
    h[base + tid + 256] = r1;  hb[base + tid + 256] = __float2bfloat16(r1);
    h[base + tid + 512] = r2;  hb[base + tid + 512] = __float2bfloat16(r2);
}

// ---------------- fused MoE keep-mask + gather + layernorm ----------------
__global__ void __launch_bounds__(256) ln_gather_kernel(
    float* __restrict__ h, const float* __restrict__ oe,
    const int* __restrict__ e1, const int* __restrict__ e2,
    const int* __restrict__ p1, const int* __restrict__ p2,
    const float* __restrict__ g1, const float* __restrict__ g2,
    const float* __restrict__ g, const float* __restrict__ bta,
    __nv_bfloat16* __restrict__ hb) {
    __shared__ float wred[8];
    const int s = blockIdx.x;
    const long long base = (long long)s * EMS;
    const int tid = threadIdx.x, warp = tid >> 5, lane = tid & 31;
    const int pp1 = p1[s], pp2 = p2[s];
    const float a = g1[s] * (pp1 < CAP ? 1.f : 0.f);
    const float bgl = g2[s] * (pp2 < CAP ? 1.f : 0.f);
    const float den = fmaxf(a + bgl, 1e-9f);
    const float w1 = a / den, w2 = bgl / den;
    const int q1 = min(pp1, CAP - 1), q2 = min(pp2, CAP - 1);
    const float* r1 = oe + ((long long)e1[s] * CAP + q1) * EMS;
    const float* r2 = oe + ((long long)e2[s] * CAP + q2) * EMS;

    const float x0 = h[base + tid]       + r1[tid]       * w1 + r2[tid]       * w2;
    const float x1 = h[base + tid + 256] + r1[tid + 256] * w1 + r2[tid + 256] * w2;
    const float x2 = h[base + tid + 512] + r1[tid + 512] * w1 + r2[tid + 512] * w2;
    float sm = x0 + x1 + x2;
    for (int o = 16; o > 0; o >>= 1) sm += __shfl_xor_sync(0xffffffffu, sm, o);
    if (lane == 0) wred[warp] = sm;
    __syncthreads();
    float tot = 0.f;
#pragma unroll
    for (int w = 0; w < 8; w++) tot += wred[w];
    const float mean = tot / (float)EMS;
    __syncthreads();
    const float d0 = x0 - mean, d1 = x1 - mean, d2 = x2 - mean;
    float v = d0 * d0 + d1 * d1 + d2 * d2;
    for (int o = 16; o > 0; o >>= 1) v += __shfl_xor_sync(0xffffffffu, v, o);
    if (lane == 0) wred[warp] = v;
    __syncthreads();
    float vtot = 0.f;
#pragma unroll
    for (int w = 0; w < 8; w++) vtot += wred[w];
    const float rstd = rsqrtf(vtot / (float)EMS + 1e-5f);
    const float r0o = d0 * rstd * g[tid]       + bta[tid];
    const float r1o = d1 * rstd * g[tid + 256] + bta[tid + 256];
    const float r2o = d2 * rstd * g[tid + 512] + bta[tid + 512];
    h[base + tid]       = r0o;  hb[base + tid]       = __float2bfloat16(r0o);
    h[base + tid + 256] = r1o;  hb[base + tid + 256] = __float2bfloat16(r1o);
    h[base + tid + 512] = r2o;  hb[base + tid + 512] = __float2bfloat16(r2o);
}

// ---------------- MoE gating (fp32, exact) ----------------
__global__ void gate_kernel(const float* __restrict__ h, const float* __restrict__ gw,
                            int* __restrict__ e1o, int* __restrict__ e2o,
                            float* __restrict__ g1o, float* __restrict__ g2o) {
    const int token = (blockIdx.x * blockDim.x + threadIdx.x) >> 5;
    const int lane = threadIdx.x & 31;
    if (token >= STOK) return;
    const float* x = h + (long long)token * EMS;
    float part[NE] = {0.f, 0.f, 0.f, 0.f, 0.f, 0.f, 0.f, 0.f};
    for (int j = lane; j < EMS; j += 32) {
        const float xv = x[j];
        const float* w = gw + j * NE;
#pragma unroll
        for (int e = 0; e < NE; e++) part[e] += xv * w[e];
    }
#pragma unroll
    for (int e = 0; e < NE; e++)
        for (int o = 16; o > 0; o >>= 1) part[e] += __shfl_xor_sync(0xffffffffu, part[e], o);
    if (lane == 0) {
        float mx = part[0];
#pragma unroll
        for (int e = 1; e < NE; e++) mx = fmaxf(mx, part[e]);
        float gates[NE]; float se = 0.f;
#pragma unroll
        for (int e = 0; e < NE; e++) { gates[e] = expf(part[e] - mx); se += gates[e]; }
        int a1 = 0; float b1v = part[0];
#pragma unroll
        for (int e = 1; e < NE; e++) if (part[e] > b1v) { b1v = part[e]; a1 = e; }
        int a2 = -1; float b2v = -1e30f;
#pragma unroll
        for (int e = 0; e < NE; e++) if (e != a1 && part[e] > b2v) { b2v = part[e]; a2 = e; }
        e1o[token] = a1; e2o[token] = a2;
        g1o[token] = gates[a1] / se;
        g2o[token] = gates[a2] / se;
    }
}

__global__ void hist_kernel(const int* __restrict__ e1, const int* __restrict__ e2,
                            int* __restrict__ h1, int* __restrict__ h2) {
    __shared__ int s1[NE], s2[NE];
    const int tid = threadIdx.x;
    if (tid < NE) { s1[tid] = 0; s2[tid] = 0; }
    __syncthreads();
    const int s = blockIdx.x * 128 + tid;
    atomicAdd(&s1[e1[s]], 1);
    atomicAdd(&s2[e2[s]], 1);
    __syncthreads();
    if (tid < NE) {
        h1[blockIdx.x * NE + tid] = s1[tid];
        h2[blockIdx.x * NE + tid] = s2[tid];
    }
}

__global__ void scan_kernel(const int* __restrict__ h1, const int* __restrict__ h2,
                            int* __restrict__ o1, int* __restrict__ o2) {
    const int e = threadIdx.x;
    if (e < NE) {
        int run = 0;
        for (int c = 0; c < NCHUNK; c++) { o1[c * NE + e] = run; run += h1[c * NE + e]; }
        int run2 = run;
        for (int c = 0; c < NCHUNK; c++) { o2[c * NE + e] = run2; run2 += h2[c * NE + e]; }
    }
}

__global__ void rank_kernel(const int* __restrict__ e1, const int* __restrict__ e2,
                            const int* __restrict__ o1, const int* __restrict__ o2,
                            int* __restrict__ p1, int* __restrict__ p2) {
    const int t = threadIdx.x, c = blockIdx.x;
    if (t < NE) {
        const int e = t;
        int r = o1[c * NE + e];
        for (int i = 0; i < 128; i++) {
            const int s = c * 128 + i;
            if (e1[s] == e) p1[s] = r++;
        }
    } else if (t < 2 * NE) {
        const int e = t - NE;
        int r = o2[c * NE + e];
        for (int i = 0; i < 128; i++) {
            const int s = c * 128 + i;
            if (e2[s] == e) p2[s] = r++;
        }
    }
}

// scatter reads the bf16 mirror hb with vectorized 16B copies
__global__ void scatter_kernel(const __nv_bfloat16* __restrict__ hb, const int* __restrict__ e1,
                               const int* __restrict__ e2, const int* __restrict__ p1,
                               const int* __restrict__ p2, __nv_bfloat16* __restrict__ buf) {
    const int s = blockIdx.x;
    const int q1 = p1[s], q2 = p2[s];
    const uint4* src = reinterpret_cast<const uint4*>(hb + (long long)s * EMS); // 96 uint4
    const int tid = threadIdx.x;   // blockDim = 128
    if (q1 < CAP) {
        uint4* d = reinterpret_cast<uint4*>(buf + ((long long)e1[s] * CAP + q1) * EMS);
        if (tid < 96) d[tid] = src[tid];
    }
    if (q2 < CAP) {
        uint4* d = reinterpret_cast<uint4*>(buf + ((long long)e2[s] * CAP + q2) * EMS);
        if (tid < 96) d[tid] = src[tid];
    }
}

// ---------------- decoder + loss ----------------
__global__ void cls_extract_kernel(const float* __restrict__ h, float* __restrict__ out) {
    const int b = blockIdx.x;
    for (int d = threadIdx.x; d < EMS; d += blockDim.x)
        out[b * EMS + d] = h[(long long)b * SEQL * EMS + d];
}

__global__ void loss_kernel(const float* __restrict__ logits, const int* __restrict__ y,
                            float* __restrict__ lossb) {
    __shared__ float red[256];
    const int b = blockIdx.x, tid = threadIdx.x;
    const float* l = logits + b * NCLS;
    float mx = -1e30f;
    for (int j = tid; j < NCLS; j += 256) mx = fmaxf(mx, l[j]);
    red[tid] = mx;
    __syncthreads();
    for (int o = 128; o > 0; o >>= 1) { if (tid < o) red[tid] = fmaxf(red[tid], red[tid + o]); __syncthreads(); }
    mx = red[0];
    __syncthreads();
    float s = 0.f;
    for (int j = tid; j < NCLS; j += 256) s += expf(l[j] - mx);
    red[tid] = s;
    __syncthreads();
    for (int o = 128; o > 0; o >>= 1) { if (tid < o) red[tid] += red[tid + o]; __syncthreads(); }
    if (tid == 0) lossb[b] = -(l[y[b]] - mx - logf(red[0]));
}

__global__ void sum_kernel(const float* __restrict__ lossb, float* __restrict__ out) {
    if (threadIdx.x == 0) {
        float s = 0.f;
        for (int i = 0; i < BAT; i++) s += lossb[i];
        out[0] = s;
    }
}

// ---------------- host side ----------------
static inline void gemm_tc(const __nv_bfloat16* A, const __nv_bfloat16* Bt, const float* bias,
                           void* C, int M, int N, int K, int mode, int batch = 1,
                           long long sA = 0, long long sB = 0, long long sBias = 0, long long sC = 0) {
    dim3 grid(N / 128, (M + 127) / 128, batch);
    hgemm_kernel<<<grid, 256, HG_SMEM>>>(A, Bt, bias, C, M, N, K, mode, sA, sB, sBias, sC);
}

extern "C" void kernel_launch(void* const* d_in, const int* in_sizes, int n_in,
                              void* d_out, int out_size) {
    const float* x       = (const float*)d_in[0];
    const int*   y       = (const int*)  d_in[1];
    const float* patch_w = (const float*)d_in[2];
    const float* patch_b = (const float*)d_in[3];
    const float* cls     = (const float*)d_in[4];
    const float* pos     = (const float*)d_in[5];
    const float* wqkv    = (const float*)d_in[6];
    const float* bqkv    = (const float*)d_in[7];
    const float* wo      = (const float*)d_in[8];
    const float* bo      = (const float*)d_in[9];
    const float* ln1g    = (const float*)d_in[10];
    const float* ln1b    = (const float*)d_in[11];
    const float* ln2g    = (const float*)d_in[12];
    const float* ln2b    = (const float*)d_in[13];
    const float* dw1     = (const float*)d_in[14];
    const float* db1     = (const float*)d_in[15];
    const float* dw2     = (const float*)d_in[16];
    const float* db2     = (const float*)d_in[17];
    const float* gw      = (const float*)d_in[18];
    const float* ew1     = (const float*)d_in[19];
    const float* eb1     = (const float*)d_in[20];
    const float* ew2     = (const float*)d_in[21];
    const float* eb2     = (const float*)d_in[22];
    const float* decw    = (const float*)d_in[23];
    const float* decb    = (const float*)d_in[24];

    cudaFuncSetAttribute(hgemm_kernel, cudaFuncAttributeMaxDynamicSharedMemorySize, HG_SMEM);

    float *p_h, *p_qkv, *p_attn, *p_f2, *p_patch, *p_eb2;
    float *p_logits, *p_cls, *p_lossb, *p_g1, *p_g2;
    int *p_e1, *p_e2, *p_p1, *p_p2, *p_h1, *p_h2, *p_o1, *p_o2;
    __nv_bfloat16 *p_wb, *p_hb, *p_attnb, *p_f1b, *p_bufb, *p_eb1b;
    cudaGetSymbolAddress((void**)&p_h, g_h);
    cudaGetSymbolAddress((void**)&p_qkv, g_qkv);
    cudaGetSymbolAddress((void**)&p_attn, g_attn);
    cudaGetSymbolAddress((void**)&p_f2, g_f2);
    cudaGetSymbolAddress((void**)&p_patch, g_patch);
    cudaGetSymbolAddress((void**)&p_eb2, g_ebuf2);
    cudaGetSymbolAddress((void**)&p_logits, g_logits);
    cudaGetSymbolAddress((void**)&p_cls, g_clsrow);
    cudaGetSymbolAddress((void**)&p_lossb, g_lossb);
    cudaGetSymbolAddress((void**)&p_g1, g_g1);
    cudaGetSymbolAddress((void**)&p_g2, g_g2);
    cudaGetSymbolAddress((void**)&p_e1, g_e1);
    cudaGetSymbolAddress((void**)&p_e2, g_e2);
    cudaGetSymbolAddress((void**)&p_p1, g_p1);
    cudaGetSymbolAddress((void**)&p_p2, g_p2);
    cudaGetSymbolAddress((void**)&p_h1, g_h1);
    cudaGetSymbolAddress((void**)&p_h2, g_h2);
    cudaGetSymbolAddress((void**)&p_o1, g_o1);
    cudaGetSymbolAddress((void**)&p_o2, g_o2);
    cudaGetSymbolAddress((void**)&p_wb, g_wbf);
    cudaGetSymbolAddress((void**)&p_hb, g_hb);
    cudaGetSymbolAddress((void**)&p_attnb, g_attnb);
    cudaGetSymbolAddress((void**)&p_f1b, g_f1b);
    cudaGetSymbolAddress((void**)&p_bufb, g_bufb);
    cudaGetSymbolAddress((void**)&p_eb1b, g_eb1b);

    __nv_bfloat16* p_qkvb = (__nv_bfloat16*)p_qkv;   // reuse fp32 scratch as bf16

    // ---- weight convert+transpose: fp32 [K,N] -> bf16 [N,K] ----
    dim3 tb(32, 8);
    wtrans_kernel<<<dim3(2304 / 32, 768 / 32, 8),  tb>>>(wqkv, p_wb + W_QKV, 768, 2304);
    wtrans_kernel<<<dim3(768 / 32,  768 / 32, 8),  tb>>>(wo,   p_wb + W_O,   768, 768);
    wtrans_kernel<<<dim3(3072 / 32, 768 / 32, 4),  tb>>>(dw1,  p_wb + W_D1,  768, 3072);
    wtrans_kernel<<<dim3(768 / 32, 3072 / 32, 4),  tb>>>(dw2,  p_wb + W_D2,  3072, 768);
    wtrans_kernel<<<dim3(3072 / 32, 768 / 32, 32), tb>>>(ew1,  p_wb + W_E1,  768, 3072);
    wtrans_kernel<<<dim3(768 / 32, 3072 / 32, 32), tb>>>(ew2,  p_wb + W_E2,  3072, 768);

    // ---- patch embed (fp32 SGEMM; K=48 small) ----
    patch_kernel<<<1024, 256>>>(x, p_patch);
    sgemm_kernel<<<dim3(768 / BN, (BAT * 64 + BM - 1) / BM), 256>>>(p_patch, patch_w, patch_b, p_attn, BAT * 64, EMS, 48, 0);
    assemble_kernel<<<8192, 256>>>(p_attn, cls, pos, p_h, p_hb);

    int di = 0, mi = 0;
    for (int i = 0; i < 8; i++) {
        gemm_tc(p_hb, p_wb + W_QKV + (size_t)i * 2304 * 768, bqkv + i * 3 * EMS, p_qkvb, STOK, 3 * EMS, EMS, 2);
        attn_kernel<<<dim3(NHD, BAT), 256>>>(p_qkvb, p_attnb);
        gemm_tc(p_attnb, p_wb + W_O + (size_t)i * 768 * 768, bo + i * EMS, p_f2, STOK, EMS, EMS, 0);
        ln_kernel<<<STOK, 256>>>(p_h, p_f2, ln1g + i * EMS, ln1b + i * EMS, p_hb);

        if ((i & 1) == 0) {
            gemm_tc(p_hb, p_wb + W_D1 + (size_t)di * 3072 * 768, db1 + di * NHID_, p_f1b, STOK, NHID_, EMS, 3);
            gemm_tc(p_f1b, p_wb + W_D2 + (size_t)di * 768 * 3072, db2 + di * EMS, p_f2, STOK, EMS, NHID_, 0);
            ln_kernel<<<STOK, 256>>>(p_h, p_f2, ln2g + i * EMS, ln2b + i * EMS, p_hb);
            di++;
        } else {
            gate_kernel<<<STOK / 8, 256>>>(p_h, gw + (long long)mi * EMS * NE, p_e1, p_e2, p_g1, p_g2);
            hist_kernel<<<NCHUNK, 128>>>(p_e1, p_e2, p_h1, p_h2);
            scan_kernel<<<1, 32>>>(p_h1, p_h2, p_o1, p_o2);
            rank_kernel<<<NCHUNK, 32>>>(p_e1, p_e2, p_o1, p_o2, p_p1, p_p2);
            // keep-mask + renorm folded into ln_gather (reads raw g1/g2 + p1/p2)
            scatter_kernel<<<STOK, 128>>>(p_hb, p_e1, p_e2, p_p1, p_p2, p_bufb);
            gemm_tc(p_bufb, p_wb + W_E1 + (size_t)mi * 8 * 3072 * 768, eb1 + (long long)mi * NE * NHID_, p_eb1b,
                    CAP, NHID_, EMS, 3, NE,
                    (long long)CAP * EMS, (long long)3072 * 768, NHID_, (long long)CAP * NHID_);
            gemm_tc(p_eb1b, p_wb + W_E2 + (size_t)mi * 8 * 768 * 3072, eb2 + (long long)mi * NE * EMS, p_eb2,
                    CAP, EMS, NHID_, 0, NE,
                    (long long)CAP * NHID_, (long long)768 * 3072, EMS, (long long)CAP * EMS);
            ln_gather_kernel<<<STOK, 256>>>(p_h, p_eb2, p_e1, p_e2, p_p1, p_p2, p_g1, p_g2,
                                            ln2g + i * EMS, ln2b + i * EMS, p_hb);
            mi++;
        }
    }

    cls_extract_kernel<<<BAT, 256>>>(p_h, p_cls);
    sgemm_kernel<<<dim3((NCLS + BN - 1) / BN, (BAT + BM - 1) / BM), 256>>>(p_cls, decw, decb, p_logits, BAT, NCLS, EMS, 0);
    loss_kernel<<<BAT, 256>>>(p_logits, y, p_lossb);
    sum_kernel<<<1, 32>>>(p_lossb, (float*)d_out);
}

// round 16
// speedup vs baseline: 1.0318x; 1.0026x over previous
#include <cuda_runtime.h>
#include <cuda_bf16.h>
#include <math.h>

// ---------------- problem constants ----------------
constexpr int EMS   = 768;
constexpr int NHD   = 12;
constexpr int HDM   = 64;
constexpr int SEQL  = 65;
constexpr int BAT   = 256;
constexpr int STOK  = BAT * SEQL;       // 16640
constexpr int NHID_ = 3072;
constexpr int NE    = 8;
constexpr int CAP   = 2600;
constexpr int NCHUNK = 130;
constexpr int NCLS  = 1000;

// ---------------- bf16 transposed weight buffer ----------------
constexpr size_t W_QKV = 0;
constexpr size_t SZ_QKV = (size_t)8 * 2304 * 768;
constexpr size_t W_O  = W_QKV + SZ_QKV;
constexpr size_t SZ_O = (size_t)8 * 768 * 768;
constexpr size_t W_D1 = W_O + SZ_O;
constexpr size_t SZ_D1 = (size_t)4 * 3072 * 768;
constexpr size_t W_D2 = W_D1 + SZ_D1;
constexpr size_t SZ_D2 = (size_t)4 * 768 * 3072;
constexpr size_t W_E1 = W_D2 + SZ_D2;
constexpr size_t SZ_E1 = (size_t)32 * 3072 * 768;
constexpr size_t W_E2 = W_E1 + SZ_E1;
constexpr size_t SZ_E2 = (size_t)32 * 768 * 3072;
constexpr size_t W_TOTAL = W_E2 + SZ_E2;

__device__ __nv_bfloat16 g_wbf[W_TOTAL];

// ---------------- scratch ----------------
__device__ float g_h   [(size_t)STOK * EMS];
__device__ float g_qkv [(size_t)STOK * 3 * EMS];   // low half reused as bf16 qkv
__device__ float g_attn[(size_t)STOK * EMS];
__device__ float g_f2  [(size_t)STOK * EMS];
__device__ float g_patch[(size_t)BAT * 64 * 48];
__device__ float g_ebuf2[(size_t)NE * CAP * EMS];
__device__ float g_logits[BAT * NCLS];
__device__ float g_clsrow[BAT * EMS];
__device__ float g_lossb[BAT];
__device__ float g_g1[STOK], g_g2[STOK];
__device__ int   g_e1[STOK], g_e2[STOK], g_p1[STOK], g_p2[STOK];
__device__ int   g_h1[NCHUNK * NE], g_h2[NCHUNK * NE];
__device__ int   g_o1[NCHUNK * NE], g_o2[NCHUNK * NE];

__device__ __nv_bfloat16 g_hb   [(size_t)STOK * EMS];
__device__ __nv_bfloat16 g_attnb[(size_t)STOK * EMS];
__device__ __nv_bfloat16 g_f1b  [(size_t)STOK * NHID_];
__device__ __nv_bfloat16 g_bufb [(size_t)NE * CAP * EMS];
__device__ __nv_bfloat16 g_eb1b [(size_t)NE * CAP * NHID_];

// ---------------- small PTX helpers (base ISA only) ----------------
__device__ __forceinline__ unsigned smem_u32(const void* p) {
    unsigned a;
    asm("{ .reg .u64 t; cvta.to.shared.u64 t, %1; cvt.u32.u64 %0, t; }" : "=r"(a) : "l"(p));
    return a;
}
__device__ __forceinline__ void cp_async16(unsigned dst, const void* src) {
    asm volatile("cp.async.cg.shared.global [%0], [%1], 16;" :: "r"(dst), "l"(src));
}
__device__ __forceinline__ void cp_commit() { asm volatile("cp.async.commit_group;"); }
template <int N>
__device__ __forceinline__ void cp_wait() { asm volatile("cp.async.wait_group %0;" :: "n"(N)); }

__device__ __forceinline__ void ldmx4(unsigned* r, unsigned addr) {
    asm volatile("ldmatrix.sync.aligned.m8n8.x4.shared.b16 {%0,%1,%2,%3}, [%4];"
                 : "=r"(r[0]), "=r"(r[1]), "=r"(r[2]), "=r"(r[3]) : "r"(addr));
}
__device__ __forceinline__ void mma16816(float* d, const unsigned* a, unsigned b0, unsigned b1) {
    asm volatile("mma.sync.aligned.m16n8k16.row.col.f32.bf16.bf16.f32 "
                 "{%0,%1,%2,%3}, {%4,%5,%6,%7}, {%8,%9}, {%0,%1,%2,%3};"
                 : "+f"(d[0]), "+f"(d[1]), "+f"(d[2]), "+f"(d[3])
                 : "r"(a[0]), "r"(a[1]), "r"(a[2]), "r"(a[3]), "r"(b0), "r"(b1));
}
__device__ __forceinline__ unsigned long long pack2(float lo, float hi) {
    unsigned long long r;
    asm("mov.b64 %0, {%1, %2};" : "=l"(r) : "f"(lo), "f"(hi));
    return r;
}
__device__ __forceinline__ void fma2(unsigned long long& d, unsigned long long a, unsigned long long b) {
    asm("fma.rn.f32x2 %0, %1, %2, %0;" : "+l"(d) : "l"(a), "l"(b));
}
__device__ __forceinline__ float2 unpack2(unsigned long long v) {
    float2 f;
    asm("mov.b64 {%0, %1}, %2;" : "=f"(f.x), "=f"(f.y) : "l"(v));
    return f;
}

// ---------------- bf16 tensor-core GEMM via mma.sync (v4: 4-stage, PROVEN BEST) ----------------
// C[M,N] = A[M,K] @ Bt[N,K]^T + bias.  A,Bt bf16 row-major; K%32==0, N%128==0.
// 256 threads, 8 warps (4x2), warp tile 32x64, 4-stage cp.async (BK=32), 1 sync/iter.
// 82 KB smem/CTA -> 2 CTAs/SM = 16 warps/SM (calibrated minimum for latency hiding;
// register file caps at 2 CTAs/SM at ~116 regs/thread, so smem <=100KB/CTA is free).
// mode bits: bit0 = relu, bit1 = bf16 output
constexpr int HROWB = 80;                  // 32 bf16 (64B) + 16B pad -> conflict-free ldmatrix
constexpr int HSTAGE = 2 * 128 * HROWB;    // A tile + B tile = 20480 bytes
constexpr int NSTG = 4;
constexpr int HG_SMEM = NSTG * HSTAGE;     // 81920

__global__ void __launch_bounds__(256) hgemm_kernel(
    const __nv_bfloat16* __restrict__ A, const __nv_bfloat16* __restrict__ Bt,
    const float* __restrict__ bias, void* __restrict__ Cout,
    int M, int N, int K, int mode,
    long long strA, long long strB, long long strBias, long long strC)
{
    extern __shared__ __align__(16) char smem[];
    const unsigned sb = smem_u32(smem);
    const int tid = threadIdx.x;
    const int wid = tid >> 5, lane = tid & 31;

    A    += (long long)blockIdx.z * strA;
    Bt   += (long long)blockIdx.z * strB;
    bias += (long long)blockIdx.z * strBias;

    const int brow = blockIdx.y * 128;
    const int bcol = blockIdx.x * 128;
    const int KIT = K >> 5;                // BK = 32

    // per-thread load slots: 2 A chunks + 2 B chunks of 16B each
    const int c0 = tid, c1 = tid + 256;
    const int ar0 = c0 >> 2, ac0 = (c0 & 3) * 16;
    const int ar1 = c1 >> 2, ac1 = (c1 & 3) * 16;
    const __nv_bfloat16* Arow0 = A + (size_t)min(brow + ar0, M - 1) * K;
    const __nv_bfloat16* Arow1 = A + (size_t)min(brow + ar1, M - 1) * K;
    const __nv_bfloat16* Brow0 = Bt + (size_t)(bcol + ar0) * K;
    const __nv_bfloat16* Brow1 = Bt + (size_t)(bcol + ar1) * K;

    auto load_stage = [&](int st, int k0) {
        const unsigned sa = sb + st * HSTAGE;
        const unsigned sbm = sa + 128 * HROWB;
        cp_async16(sa + ar0 * HROWB + ac0, (const char*)(Arow0 + k0) + ac0);
        cp_async16(sa + ar1 * HROWB + ac1, (const char*)(Arow1 + k0) + ac1);
        cp_async16(sbm + ar0 * HROWB + ac0, (const char*)(Brow0 + k0) + ac0);
        cp_async16(sbm + ar1 * HROWB + ac1, (const char*)(Brow1 + k0) + ac1);
    };

    float acc[2][8][4];
#pragma unroll
    for (int i = 0; i < 2; i++)
#pragma unroll
        for (int j = 0; j < 8; j++)
#pragma unroll
            for (int q = 0; q < 4; q++) acc[i][j][q] = 0.f;

    const int wm = wid >> 1;              // 0..3  -> rows wm*32..+31
    const int wn = wid & 1;               // 0..1  -> cols wn*64..+63
    const unsigned aFragOff = (unsigned)((wm * 32 + (lane & 15)) * HROWB + (lane >> 4) * 16);
    const unsigned bFragOff = (unsigned)(128 * HROWB +
        (wn * 64 + ((lane >> 3) & 1) * 8 + (lane & 7)) * HROWB + (lane >> 4) * 16);

    // prologue: stages 0,1,2
#pragma unroll
    for (int s = 0; s < NSTG - 1; s++) {
        if (s < KIT) load_stage(s, s * 32);
        cp_commit();
    }

    int cur = 0;
    for (int it = 0; it < KIT; it++) {
        cp_wait<NSTG - 2>();
        __syncthreads();
        {
            const int pf = it + NSTG - 1;
            if (pf < KIT) {
                int pfs = cur + NSTG - 1; if (pfs >= NSTG) pfs -= NSTG;
                load_stage(pfs, pf * 32);
            }
            cp_commit();
        }
        const unsigned aBase = sb + cur * HSTAGE + aFragOff;
        const unsigned bBase = sb + cur * HSTAGE + bFragOff;
#pragma unroll
        for (int ks = 0; ks < 2; ks++) {
            unsigned afr[2][4];
            ldmx4(afr[0], aBase + ks * 32);
            ldmx4(afr[1], aBase + ks * 32 + 16 * HROWB);
#pragma unroll
            for (int ng = 0; ng < 4; ng++) {
                unsigned bfr[4];
                ldmx4(bfr, bBase + ks * 32 + ng * 16 * HROWB);
#pragma unroll
                for (int mt = 0; mt < 2; mt++) {
                    mma16816(acc[mt][2 * ng + 0], afr[mt], bfr[0], bfr[2]);
                    mma16816(acc[mt][2 * ng + 1], afr[mt], bfr[1], bfr[3]);
                }
            }
        }
        cur++; if (cur >= NSTG) cur = 0;
    }

    // ---- epilogue: direct register -> global ----
    const bool relu = (mode & 1);
    const bool isbf = (mode & 2);
    float* Cf = (float*)Cout + (long long)blockIdx.z * strC;
    __nv_bfloat16* Cb = (__nv_bfloat16*)Cout + (long long)blockIdx.z * strC;
    const int rbase = brow + wm * 32 + (lane >> 2);
    const int cbase = bcol + wn * 64 + 2 * (lane & 3);
#pragma unroll
    for (int mt = 0; mt < 2; mt++) {
#pragma unroll
        for (int nt = 0; nt < 8; nt++) {
            const int gcol = cbase + nt * 8;
            const float b0 = bias[gcol], b1 = bias[gcol + 1];
#pragma unroll
            for (int half = 0; half < 2; half++) {
                const int grow = rbase + mt * 16 + half * 8;
                if (grow < M) {
                    float v0 = acc[mt][nt][2 * half + 0] + b0;
                    float v1 = acc[mt][nt][2 * half + 1] + b1;
                    if (relu) { v0 = fmaxf(v0, 0.f); v1 = fmaxf(v1, 0.f); }
                    if (isbf) {
                        __nv_bfloat162 p;
                        p.x = __float2bfloat16(v0); p.y = __float2bfloat16(v1);
                        *reinterpret_cast<__nv_bfloat162*>(Cb + (size_t)grow * N + gcol) = p;
                    } else {
                        *reinterpret_cast<float2*>(Cf + (size_t)grow * N + gcol) = make_float2(v0, v1);
                    }
                }
            }
        }
    }
}

// ---------------- weight transpose+convert v2: fp32 [R,C] -> bf16 [C,R], batched ----------------
// All shapes used are multiples of 32 in both dims -> no bounds checks.
// float4 loads (1/thread) + bf162 stores (2/thread): ~4x fewer ld/st instructions
// than the scalar version (which ncu showed ALU/issue-bound at 33% DRAM).
__global__ void __launch_bounds__(256) wtrans_kernel(
    const float* __restrict__ src, __nv_bfloat16* __restrict__ dst, int R, int C) {
    __shared__ float t[32][33];
    src += (size_t)blockIdx.z * R * C;
    dst += (size_t)blockIdx.z * R * C;
    const int c0 = blockIdx.x * 32, r0 = blockIdx.y * 32;
    const int tid = threadIdx.x;
    // load: each thread one float4 (rows 0..31, col groups of 4); coalesced 128B/warp
    {
        const int r = tid >> 3, cq = (tid & 7) * 4;
        const float4 v = *reinterpret_cast<const float4*>(src + (size_t)(r0 + r) * C + c0 + cq);
        t[r][cq + 0] = v.x; t[r][cq + 1] = v.y;
        t[r][cq + 2] = v.z; t[r][cq + 3] = v.w;
    }
    __syncthreads();
    // store: each thread two bf162 along r (transposed); half-warp per column,
    // paired columns differ in parity -> conflict-free smem reads
    {
        const int lane = tid & 31, w = tid >> 5;
        const int half = lane >> 4, l = lane & 15;
#pragma unroll
        for (int k = 0; k < 2; k++) {
            const int cl = 4 * w + 2 * k + half;   // 0..31
            const int r = 2 * l;
            __nv_bfloat162 p;
            p.x = __float2bfloat16(t[r][cl]);
            p.y = __float2bfloat16(t[r + 1][cl]);
            *reinterpret_cast<__nv_bfloat162*>(dst + (size_t)(c0 + cl) * R + r0 + r) = p;
        }
    }
}

// ---------------- fp32 fallback SGEMM (patch embed, decoder) ----------------
constexpr int BM = 128, BN = 128, BKx = 8;

__global__ __launch_bounds__(256, 2) void sgemm_kernel(
    const float* __restrict__ A, const float* __restrict__ Bm,
    const float* __restrict__ bias, float* __restrict__ Cm,
    int M, int N, int K, int relu)
{
    __shared__ __align__(16) float As[BKx][BM];
    __shared__ __align__(16) float Bs[BKx][BN];
    const int tid  = threadIdx.x;
    const int brow = blockIdx.y * BM;
    const int bcol = blockIdx.x * BN;
    const int tx = tid & 15, ty = tid >> 4;
    const int aRow = tid >> 1, aCol = (tid & 1) * 4;
    const int bRowL = tid >> 5, bColL = (tid & 31) * 4;

    unsigned long long acc[8][4];
#pragma unroll
    for (int i = 0; i < 8; i++)
#pragma unroll
        for (int j = 0; j < 4; j++) acc[i][j] = 0ull;
    const bool n4 = ((N & 3) == 0);

    for (int k0 = 0; k0 < K; k0 += BKx) {
        float4 av = make_float4(0.f, 0.f, 0.f, 0.f);
        const int gr = brow + aRow;
        if (gr < M && k0 + aCol < K) av = *reinterpret_cast<const float4*>(A + (long long)gr * K + k0 + aCol);
        As[aCol + 0][aRow] = av.x; As[aCol + 1][aRow] = av.y;
        As[aCol + 2][aRow] = av.z; As[aCol + 3][aRow] = av.w;
        const int gc = bcol + bColL;
        const int kr = k0 + bRowL;
        const float* bp = Bm + (long long)kr * N + gc;
        if (n4) {
            float4 bv = make_float4(0.f, 0.f, 0.f, 0.f);
            if (gc < N && kr < K) bv = *reinterpret_cast<const float4*>(bp);
            Bs[bRowL][bColL + 0] = bv.x; Bs[bRowL][bColL + 1] = bv.y;
            Bs[bRowL][bColL + 2] = bv.z; Bs[bRowL][bColL + 3] = bv.w;
        } else {
#pragma unroll
            for (int q = 0; q < 4; q++)
                Bs[bRowL][bColL + q] = (gc + q < N && kr < K) ? bp[q] : 0.f;
        }
        __syncthreads();
#pragma unroll
        for (int kk = 0; kk < BKx; kk++) {
            const float4 a0 = *reinterpret_cast<const float4*>(&As[kk][ty * 8]);
            const float4 a1 = *reinterpret_cast<const float4*>(&As[kk][ty * 8 + 4]);
            const unsigned long long b0 = *reinterpret_cast<const unsigned long long*>(&Bs[kk][tx * 8 + 0]);
            const unsigned long long b1 = *reinterpret_cast<const unsigned long long*>(&Bs[kk][tx * 8 + 2]);
            const unsigned long long b2 = *reinterpret_cast<const unsigned long long*>(&Bs[kk][tx * 8 + 4]);
            const unsigned long long b3 = *reinterpret_cast<const unsigned long long*>(&Bs[kk][tx * 8 + 6]);
            const float aa[8] = {a0.x, a0.y, a0.z, a0.w, a1.x, a1.y, a1.z, a1.w};
#pragma unroll
            for (int i = 0; i < 8; i++) {
                const unsigned long long ad = pack2(aa[i], aa[i]);
                fma2(acc[i][0], ad, b0); fma2(acc[i][1], ad, b1);
                fma2(acc[i][2], ad, b2); fma2(acc[i][3], ad, b3);
            }
        }
        __syncthreads();
    }
#pragma unroll
    for (int i = 0; i < 8; i++) {
        const int gi = brow + ty * 8 + i;
        if (gi >= M) continue;
#pragma unroll
        for (int j = 0; j < 4; j++) {
            const float2 v = unpack2(acc[i][j]);
            const int gj = bcol + tx * 8 + 2 * j;
            if (gj < N) {
                float c = v.x + bias[gj];
                if (relu) c = fmaxf(c, 0.f);
                Cm[(long long)gi * N + gj] = c;
            }
            if (gj + 1 < N) {
                float c = v.y + bias[gj + 1];
                if (relu) c = fmaxf(c, 0.f);
                Cm[(long long)gi * N + gj + 1] = c;
            }
        }
    }
}

// ---------------- patch embed prep ----------------
__global__ void patch_kernel(const float* __restrict__ x, float* __restrict__ p) {
    const int total = BAT * 64 * 48;
    for (int idx = blockIdx.x * blockDim.x + threadIdx.x; idx < total; idx += gridDim.x * blockDim.x) {
        const int f = idx % 48;
        const int token = idx / 48;
        const int b = token >> 6;
        const int ij = token & 63;
        const int i = ij >> 3, j = ij & 7;
        const int c = f >> 4, r = (f >> 2) & 3, q = f & 3;
        p[idx] = x[((b * 3 + c) * 32 + (i * 4 + r)) * 32 + (j * 4 + q)];
    }
}

__global__ void assemble_kernel(const float* __restrict__ emb, const float* __restrict__ cls,
                                const float* __restrict__ pos, float* __restrict__ h,
                                __nv_bfloat16* __restrict__ hb) {
    const long long total = (long long)STOK * EMS;
    for (long long idx = (long long)blockIdx.x * blockDim.x + threadIdx.x; idx < total;
         idx += (long long)gridDim.x * blockDim.x) {
        const int d = (int)(idx % EMS);
        const long long s = idx / EMS;
        const int b = (int)(s / SEQL), t = (int)(s % SEQL);
        float v = pos[t * EMS + d];
        v += (t == 0) ? cls[d] : emb[((long long)b * 64 + (t - 1)) * EMS + d];
        h[idx] = v;
        hb[idx] = __float2bfloat16(v);
    }
}

// ---------------- attention (bf16 qkv in, bf16 out), packed fp32x2 ----------------
constexpr int KVSTR = 66;   // even stride -> 8B-aligned rows for LDS.64
__global__ void __launch_bounds__(256) attn_kernel(const __nv_bfloat16* __restrict__ qkv,
                                                   __nv_bfloat16* __restrict__ out) {
    __shared__ float ks[SEQL][KVSTR];
    __shared__ float vs[SEQL][KVSTR];
    __shared__ float qrow[8][HDM];
    __shared__ float probs[8][SEQL + 1];

    const int h = blockIdx.x, b = blockIdx.y;
    const int tid = threadIdx.x, warp = tid >> 5, lane = tid & 31;
    const __nv_bfloat16* base = qkv + (long long)b * SEQL * (3 * EMS);

    for (int idx = tid; idx < SEQL * HDM; idx += 256) {
        const int k = idx >> 6, d = idx & 63;
        ks[k][d] = __bfloat162float(base[(long long)k * (3 * EMS) + EMS     + h * HDM + d]);
        vs[k][d] = __bfloat162float(base[(long long)k * (3 * EMS) + 2 * EMS + h * HDM + d]);
    }
    __syncthreads();

    for (int q = warp; q < SEQL; q += 8) {
        qrow[warp][lane]      = __bfloat162float(base[(long long)q * (3 * EMS) + h * HDM + lane]);
        qrow[warp][lane + 32] = __bfloat162float(base[(long long)q * (3 * EMS) + h * HDM + lane + 32]);
        __syncwarp();
        float sc[3];
        float mx = -1e30f;
        const unsigned long long* qp = reinterpret_cast<const unsigned long long*>(&qrow[warp][0]);
#pragma unroll
        for (int ii = 0; ii < 3; ii++) {
            const int kk = lane + ii * 32;
            float acc = 0.f;
            if (kk < SEQL) {
                const unsigned long long* kp = reinterpret_cast<const unsigned long long*>(&ks[kk][0]);
                unsigned long long a2 = 0ull;
#pragma unroll
                for (int j2 = 0; j2 < 32; j2++) fma2(a2, qp[j2], kp[j2]);
                const float2 f = unpack2(a2);
                acc = (f.x + f.y) * 0.125f;
                mx = fmaxf(mx, acc);
            }
            sc[ii] = acc;
        }
        for (int o = 16; o > 0; o >>= 1) mx = fmaxf(mx, __shfl_xor_sync(0xffffffffu, mx, o));
        float sum = 0.f;
#pragma unroll
        for (int ii = 0; ii < 3; ii++) {
            const int kk = lane + ii * 32;
            float p = 0.f;
            if (kk < SEQL) { p = expf(sc[ii] - mx); sum += p; }
            sc[ii] = p;
        }
        for (int o = 16; o > 0; o >>= 1) sum += __shfl_xor_sync(0xffffffffu, sum, o);
        const float inv = 1.f / sum;
#pragma unroll
        for (int ii = 0; ii < 3; ii++) {
            const int kk = lane + ii * 32;
            if (kk < SEQL) probs[warp][kk] = sc[ii] * inv;
        }
        __syncwarp();
        // AV: each lane covers d = 2*lane, 2*lane+1 (packed)
        {
            const int d0 = 2 * lane;
            unsigned long long o2 = 0ull;
            for (int k = 0; k < SEQL; k++) {
                const float p = probs[warp][k];
                fma2(o2, pack2(p, p),
                     *reinterpret_cast<const unsigned long long*>(&vs[k][d0]));
            }
            const float2 f = unpack2(o2);
            __nv_bfloat162 pr;
            pr.x = __float2bfloat16(f.x);
            pr.y = __float2bfloat16(f.y);
            *reinterpret_cast<__nv_bfloat162*>(
                out + ((long long)(b * SEQL + q)) * EMS + h * HDM + d0) = pr;
        }
        __syncwarp();
    }
}

// ---------------- layernorm (shuffle reductions; writes fp32 h + bf16 copy) ----------------
__global__ void __launch_bounds__(256) ln_kernel(float* __restrict__ h, const float* __restrict__ a,
                          const float* __restrict__ g, const float* __restrict__ bta,
                          __nv_bfloat16* __restrict__ hb) {
    __shared__ float wred[8];
    const long long base = (long long)blockIdx.x * EMS;
    const int tid = threadIdx.x, warp = tid >> 5, lane = tid & 31;
    const float x0 = h[base + tid]       + a[base + tid];
    const float x1 = h[base + tid + 256] + a[base + tid + 256];
    const float x2 = h[base + tid + 512] + a[base + tid + 512];
    float s = x0 + x1 + x2;
    for (int o = 16; o > 0; o >>= 1) s += __shfl_xor_sync(0xffffffffu, s, o);
    if (lane == 0) wred[warp] = s;
    __syncthreads();
    float tot = 0.f;
#pragma unroll
    for (int w = 0; w < 8; w++) tot += wred[w];
    const float mean = tot / (float)EMS;
    __syncthreads();
    const float d0 = x0 - mean, d1 = x1 - mean, d2 = x2 - mean;
    float v = d0 * d0 + d1 * d1 + d2 * d2;
    for (int o = 16; o > 0; o >>= 1) v += __shfl_xor_sync(0xffffffffu, v, o);
    if (lane == 0) wred[warp] = v;
    __syncthreads();
    float vtot = 0.f;
#pragma unroll
    for (int w = 0; w < 8; w++) vtot += wred[w];
    const float rstd = rsqrtf(vtot / (float)EMS + 1e-5f);
    const float r0 = d0 * rstd * g[tid]       + bta[tid];
    const float r1 = d1 * rstd * g[tid + 256] + bta[tid + 256];
    const float r2 = d2 * rstd * g[tid + 512] + bta[tid + 512];
    h[base + tid]       = r0;  hb[base + tid]       = __float2bfloat16(r0);
    h[base + tid + 256] = r1;  hb[base + tid + 256] = __float2bfloat16(r1);
    h[base + tid + 512] = r2;  hb[base + tid + 512] = __float2bfloat16(r2);
}

// ---------------- fused MoE keep-mask + gather + layernorm ----------------
__global__ void __launch_bounds__(256) ln_gather_kernel(
    float* __restrict__ h, const float* __restrict__ oe,
    const int* __restrict__ e1, const int* __restrict__ e2,
    const int* __restrict__ p1, const int* __restrict__ p2,
    const float* __restrict__ g1, const float* __restrict__ g2,
    const float* __restrict__ g, const float* __restrict__ bta,
    __nv_bfloat16* __restrict__ hb) {
    __shared__ float wred[8];
    const int s = blockIdx.x;
    const long long base = (long long)s * EMS;
    const int tid = threadIdx.x, warp = tid >> 5, lane = tid & 31;
    const int pp1 = p1[s], pp2 = p2[s];
    const float a = g1[s] * (pp1 < CAP ? 1.f : 0.f);
    const float bgl = g2[s] * (pp2 < CAP ? 1.f : 0.f);
    const float den = fmaxf(a + bgl, 1e-9f);
    const float w1 = a / den, w2 = bgl / den;
    const int q1 = min(pp1, CAP - 1), q2 = min(pp2, CAP - 1);
    const float* r1 = oe + ((long long)e1[s] * CAP + q1) * EMS;
    const float* r2 = oe + ((long long)e2[s] * CAP + q2) * EMS;

    const float x0 = h[base + tid]       + r1[tid]       * w1 + r2[tid]       * w2;
    const float x1 = h[base + tid + 256] + r1[tid + 256] * w1 + r2[tid + 256] * w2;
    const float x2 = h[base + tid + 512] + r1[tid + 512] * w1 + r2[tid + 512] * w2;
    float sm = x0 + x1 + x2;
    for (int o = 16; o > 0; o >>= 1) sm += __shfl_xor_sync(0xffffffffu, sm, o);
    if (lane == 0) wred[warp] = sm;
    __syncthreads();
    float tot = 0.f;
#pragma unroll
    for (int w = 0; w < 8; w++) tot += wred[w];
    const float mean = tot / (float)EMS;
    __syncthreads();
    const float d0 = x0 - mean, d1 = x1 - mean, d2 = x2 - mean;
    float v = d0 * d0 + d1 * d1 + d2 * d2;
    for (int o = 16; o > 0; o >>= 1) v += __shfl_xor_sync(0xffffffffu, v, o);
    if (lane == 0) wred[warp] = v;
    __syncthreads();
    float vtot = 0.f;
#pragma unroll
    for (int w = 0; w < 8; w++) vtot += wred[w];
    const float rstd = rsqrtf(vtot / (float)EMS + 1e-5f);
    const float r0o = d0 * rstd * g[tid]       + bta[tid];
    const float r1o = d1 * rstd * g[tid + 256] + bta[tid + 256];
    const float r2o = d2 * rstd * g[tid + 512] + bta[tid + 512];
    h[base + tid]       = r0o;  hb[base + tid]       = __float2bfloat16(r0o);
    h[base + tid + 256] = r1o;  hb[base + tid + 256] = __float2bfloat16(r1o);
    h[base + tid + 512] = r2o;  hb[base + tid + 512] = __float2bfloat16(r2o);
}

// ---------------- MoE gating (fp32, exact) ----------------
__global__ void gate_kernel(const float* __restrict__ h, const float* __restrict__ gw,
                            int* __restrict__ e1o, int* __restrict__ e2o,
                            float* __restrict__ g1o, float* __restrict__ g2o) {
    const int token = (blockIdx.x * blockDim.x + threadIdx.x) >> 5;
    const int lane = threadIdx.x & 31;
    if (token >= STOK) return;
    const float* x = h + (long long)token * EMS;
    float part[NE] = {0.f, 0.f, 0.f, 0.f, 0.f, 0.f, 0.f, 0.f};
    for (int j = lane; j < EMS; j += 32) {
        const float xv = x[j];
        const float* w = gw + j * NE;
#pragma unroll
        for (int e = 0; e < NE; e++) part[e] += xv * w[e];
    }
#pragma unroll
    for (int e = 0; e < NE; e++)
        for (int o = 16; o > 0; o >>= 1) part[e] += __shfl_xor_sync(0xffffffffu, part[e], o);
    if (lane == 0) {
        float mx = part[0];
#pragma unroll
        for (int e = 1; e < NE; e++) mx = fmaxf(mx, part[e]);
        float gates[NE]; float se = 0.f;
#pragma unroll
        for (int e = 0; e < NE; e++) { gates[e] = expf(part[e] - mx); se += gates[e]; }
        int a1 = 0; float b1v = part[0];
#pragma unroll
        for (int e = 1; e < NE; e++) if (part[e] > b1v) { b1v = part[e]; a1 = e; }
        int a2 = -1; float b2v = -1e30f;
#pragma unroll
        for (int e = 0; e < NE; e++) if (e != a1 && part[e] > b2v) { b2v = part[e]; a2 = e; }
        e1o[token] = a1; e2o[token] = a2;
        g1o[token] = gates[a1] / se;
        g2o[token] = gates[a2] / se;
    }
}

__global__ void hist_kernel(const int* __restrict__ e1, const int* __restrict__ e2,
                            int* __restrict__ h1, int* __restrict__ h2) {
    __shared__ int s1[NE], s2[NE];
    const int tid = threadIdx.x;
    if (tid < NE) { s1[tid] = 0; s2[tid] = 0; }
    __syncthreads();
    const int s = blockIdx.x * 128 + tid;
    atomicAdd(&s1[e1[s]], 1);
    atomicAdd(&s2[e2[s]], 1);
    __syncthreads();
    if (tid < NE) {
        h1[blockIdx.x * NE + tid] = s1[tid];
        h2[blockIdx.x * NE + tid] = s2[tid];
    }
}

__global__ void scan_kernel(const int* __restrict__ h1, const int* __restrict__ h2,
                            int* __restrict__ o1, int* __restrict__ o2) {
    const int e = threadIdx.x;
    if (e < NE) {
        int run = 0;
        for (int c = 0; c < NCHUNK; c++) { o1[c * NE + e] = run; run += h1[c * NE + e]; }
        int run2 = run;
        for (int c = 0; c < NCHUNK; c++) { o2[c * NE + e] = run2; run2 += h2[c * NE + e]; }
    }
}

__global__ void rank_kernel(const int* __restrict__ e1, const int* __restrict__ e2,
                            const int* __restrict__ o1, const int* __restrict__ o2,
                            int* __restrict__ p1, int* __restrict__ p2) {
    const int t = threadIdx.x, c = blockIdx.x;
    if (t < NE) {
        const int e = t;
        int r = o1[c * NE + e];
        for (int i = 0; i < 128; i++) {
            const int s = c * 128 + i;
            if (e1[s] == e) p1[s] = r++;
        }
    } else if (t < 2 * NE) {
        const int e = t - NE;
        int r = o2[c * NE + e];
        for (int i = 0; i < 128; i++) {
            const int s = c * 128 + i;
            if (e2[s] == e) p2[s] = r++;
        }
    }
}

// scatter reads the bf16 mirror hb with vectorized 16B copies
__global__ void scatter_kernel(const __nv_bfloat16* __restrict__ hb, const int* __restrict__ e1,
                               const int* __restrict__ e2, const int* __restrict__ p1,
                               const int* __restrict__ p2, __nv_bfloat16* __restrict__ buf) {
    const int s = blockIdx.x;
    const int q1 = p1[s], q2 = p2[s];
    const uint4* src = reinterpret_cast<const uint4*>(hb + (long long)s * EMS); // 96 uint4
    const int tid = threadIdx.x;   // blockDim = 128
    if (q1 < CAP) {
        uint4* d = reinterpret_cast<uint4*>(buf + ((long long)e1[s] * CAP + q1) * EMS);
        if (tid < 96) d[tid] = src[tid];
    }
    if (q2 < CAP) {
        uint4* d = reinterpret_cast<uint4*>(buf + ((long long)e2[s] * CAP + q2) * EMS);
        if (tid < 96) d[tid] = src[tid];
    }
}

// ---------------- decoder + loss ----------------
__global__ void cls_extract_kernel(const float* __restrict__ h, float* __restrict__ out) {
    const int b = blockIdx.x;
    for (int d = threadIdx.x; d < EMS; d += blockDim.x)
        out[b * EMS + d] = h[(long long)b * SEQL * EMS + d];
}

__global__ void loss_kernel(const float* __restrict__ logits, const int* __restrict__ y,
                            float* __restrict__ lossb) {
    __shared__ float red[256];
    const int b = blockIdx.x, tid = threadIdx.x;
    const float* l = logits + b * NCLS;
    float mx = -1e30f;
    for (int j = tid; j < NCLS; j += 256) mx = fmaxf(mx, l[j]);
    red[tid] = mx;
    __syncthreads();
    for (int o = 128; o > 0; o >>= 1) { if (tid < o) red[tid] = fmaxf(red[tid], red[tid + o]); __syncthreads(); }
    mx = red[0];
    __syncthreads();
    float s = 0.f;
    for (int j = tid; j < NCLS; j += 256) s += expf(l[j] - mx);
    red[tid] = s;
    __syncthreads();
    for (int o = 128; o > 0; o >>= 1) { if (tid < o) red[tid] += red[tid + o]; __syncthreads(); }
    if (tid == 0) lossb[b] = -(l[y[b]] - mx - logf(red[0]));
}

__global__ void sum_kernel(const float* __restrict__ lossb, float* __restrict__ out) {
    if (threadIdx.x == 0) {
        float s = 0.f;
        for (int i = 0; i < BAT; i++) s += lossb[i];
        out[0] = s;
    }
}

// ---------------- host side ----------------
static inline void gemm_tc(const __nv_bfloat16* A, const __nv_bfloat16* Bt, const float* bias,
                           void* C, int M, int N, int K, int mode, int batch = 1,
                           long long sA = 0, long long sB = 0, long long sBias = 0, long long sC = 0) {
    dim3 grid(N / 128, (M + 127) / 128, batch);
    hgemm_kernel<<<grid, 256, HG_SMEM>>>(A, Bt, bias, C, M, N, K, mode, sA, sB, sBias, sC);
}

extern "C" void kernel_launch(void* const* d_in, const int* in_sizes, int n_in,
                              void* d_out, int out_size) {
    const float* x       = (const float*)d_in[0];
    const int*   y       = (const int*)  d_in[1];
    const float* patch_w = (const float*)d_in[2];
    const float* patch_b = (const float*)d_in[3];
    const float* cls     = (const float*)d_in[4];
    const float* pos     = (const float*)d_in[5];
    const float* wqkv    = (const float*)d_in[6];
    const float* bqkv    = (const float*)d_in[7];
    const float* wo      = (const float*)d_in[8];
    const float* bo      = (const float*)d_in[9];
    const float* ln1g    = (const float*)d_in[10];
    const float* ln1b    = (const float*)d_in[11];
    const float* ln2g    = (const float*)d_in[12];
    const float* ln2b    = (const float*)d_in[13];
    const float* dw1     = (const float*)d_in[14];
    const float* db1     = (const float*)d_in[15];
    const float* dw2     = (const float*)d_in[16];
    const float* db2     = (const float*)d_in[17];
    const float* gw      = (const float*)d_in[18];
    const float* ew1     = (const float*)d_in[19];
    const float* eb1     = (const float*)d_in[20];
    const float* ew2     = (const float*)d_in[21];
    const float* eb2     = (const float*)d_in[22];
    const float* decw    = (const float*)d_in[23];
    const float* decb    = (const float*)d_in[24];

    cudaFuncSetAttribute(hgemm_kernel, cudaFuncAttributeMaxDynamicSharedMemorySize, HG_SMEM);

    float *p_h, *p_qkv, *p_attn, *p_f2, *p_patch, *p_eb2;
    float *p_logits, *p_cls, *p_lossb, *p_g1, *p_g2;
    int *p_e1, *p_e2, *p_p1, *p_p2, *p_h1, *p_h2, *p_o1, *p_o2;
    __nv_bfloat16 *p_wb, *p_hb, *p_attnb, *p_f1b, *p_bufb, *p_eb1b;
    cudaGetSymbolAddress((void**)&p_h, g_h);
    cudaGetSymbolAddress((void**)&p_qkv, g_qkv);
    cudaGetSymbolAddress((void**)&p_attn, g_attn);
    cudaGetSymbolAddress((void**)&p_f2, g_f2);
    cudaGetSymbolAddress((void**)&p_patch, g_patch);
    cudaGetSymbolAddress((void**)&p_eb2, g_ebuf2);
    cudaGetSymbolAddress((void**)&p_logits, g_logits);
    cudaGetSymbolAddress((void**)&p_cls, g_clsrow);
    cudaGetSymbolAddress((void**)&p_lossb, g_lossb);
    cudaGetSymbolAddress((void**)&p_g1, g_g1);
    cudaGetSymbolAddress((void**)&p_g2, g_g2);
    cudaGetSymbolAddress((void**)&p_e1, g_e1);
    cudaGetSymbolAddress((void**)&p_e2, g_e2);
    cudaGetSymbolAddress((void**)&p_p1, g_p1);
    cudaGetSymbolAddress((void**)&p_p2, g_p2);
    cudaGetSymbolAddress((void**)&p_h1, g_h1);
    cudaGetSymbolAddress((void**)&p_h2, g_h2);
    cudaGetSymbolAddress((void**)&p_o1, g_o1);
    cudaGetSymbolAddress((void**)&p_o2, g_o2);
    cudaGetSymbolAddress((void**)&p_wb, g_wbf);
    cudaGetSymbolAddress((void**)&p_hb, g_hb);
    cudaGetSymbolAddress((void**)&p_attnb, g_attnb);
    cudaGetSymbolAddress((void**)&p_f1b, g_f1b);
    cudaGetSymbolAddress((void**)&p_bufb, g_bufb);
    cudaGetSymbolAddress((void**)&p_eb1b, g_eb1b);

    __nv_bfloat16* p_qkvb = (__nv_bfloat16*)p_qkv;   // reuse fp32 scratch as bf16

    // ---- weight convert+transpose: fp32 [K,N] -> bf16 [N,K] (vectorized v2) ----
    wtrans_kernel<<<dim3(2304 / 32, 768 / 32, 8),  256>>>(wqkv, p_wb + W_QKV, 768, 2304);
    wtrans_kernel<<<dim3(768 / 32,  768 / 32, 8),  256>>>(wo,   p_wb + W_O,   768, 768);
    wtrans_kernel<<<dim3(3072 / 32, 768 / 32, 4),  256>>>(dw1,  p_wb + W_D1,  768, 3072);
    wtrans_kernel<<<dim3(768 / 32, 3072 / 32, 4),  256>>>(dw2,  p_wb + W_D2,  3072, 768);
    wtrans_kernel<<<dim3(3072 / 32, 768 / 32, 32), 256>>>(ew1,  p_wb + W_E1,  768, 3072);
    wtrans_kernel<<<dim3(768 / 32, 3072 / 32, 32), 256>>>(ew2,  p_wb + W_E2,  3072, 768);

    // ---- patch embed (fp32 SGEMM; K=48 small) ----
    patch_kernel<<<1024, 256>>>(x, p_patch);
    sgemm_kernel<<<dim3(768 / BN, (BAT * 64 + BM - 1) / BM), 256>>>(p_patch, patch_w, patch_b, p_attn, BAT * 64, EMS, 48, 0);
    assemble_kernel<<<8192, 256>>>(p_attn, cls, pos, p_h, p_hb);

    int di = 0, mi = 0;
    for (int i = 0; i < 8; i++) {
        gemm_tc(p_hb, p_wb + W_QKV + (size_t)i * 2304 * 768, bqkv + i * 3 * EMS, p_qkvb, STOK, 3 * EMS, EMS, 2);
        attn_kernel<<<dim3(NHD, BAT), 256>>>(p_qkvb, p_attnb);
        gemm_tc(p_attnb, p_wb + W_O + (size_t)i * 768 * 768, bo + i * EMS, p_f2, STOK, EMS, EMS, 0);
        ln_kernel<<<STOK, 256>>>(p_h, p_f2, ln1g + i * EMS, ln1b + i * EMS, p_hb);

        if ((i & 1) == 0) {
            gemm_tc(p_hb, p_wb + W_D1 + (size_t)di * 3072 * 768, db1 + di * NHID_, p_f1b, STOK, NHID_, EMS, 3);
            gemm_tc(p_f1b, p_wb + W_D2 + (size_t)di * 768 * 3072, db2 + di * EMS, p_f2, STOK, EMS, NHID_, 0);
            ln_kernel<<<STOK, 256>>>(p_h, p_f2, ln2g + i * EMS, ln2b + i * EMS, p_hb);
            di++;
        } else {
            gate_kernel<<<STOK / 8, 256>>>(p_h, gw + (long long)mi * EMS * NE, p_e1, p_e2, p_g1, p_g2);
            hist_kernel<<<NCHUNK, 128>>>(p_e1, p_e2, p_h1, p_h2);
            scan_kernel<<<1, 32>>>(p_h1, p_h2, p_o1, p_o2);
            rank_kernel<<<NCHUNK, 32>>>(p_e1, p_e2, p_o1, p_o2, p_p1, p_p2);
            // keep-mask + renorm folded into ln_gather (reads raw g1/g2 + p1/p2)
            scatter_kernel<<<STOK, 128>>>(p_hb, p_e1, p_e2, p_p1, p_p2, p_bufb);
            gemm_tc(p_bufb, p_wb + W_E1 + (size_t)mi * 8 * 3072 * 768, eb1 + (long long)mi * NE * NHID_, p_eb1b,
                    CAP, NHID_, EMS, 3, NE,
                    (long long)CAP * EMS, (long long)3072 * 768, NHID_, (long long)CAP * NHID_);
            gemm_tc(p_eb1b, p_wb + W_E2 + (size_t)mi * 8 * 768 * 3072, eb2 + (long long)mi * NE * EMS, p_eb2,
                    CAP, EMS, NHID_, 0, NE,
                    (long long)CAP * NHID_, (long long)768 * 3072, EMS, (long long)CAP * EMS);
            ln_gather_kernel<<<STOK, 256>>>(p_h, p_eb2, p_e1, p_e2, p_p1, p_p2, p_g1, p_g2,
                                            ln2g + i * EMS, ln2b + i * EMS, p_hb);
            mi++;
        }
    }

    cls_extract_kernel<<<BAT, 256>>>(p_h, p_cls);
    sgemm_kernel<<<dim3((NCLS + BN - 1) / BN, (BAT + BM - 1) / BM), 256>>>(p_cls, decw, decb, p_logits, BAT, NCLS, EMS, 0);
    loss_kernel<<<BAT, 256>>>(p_logits, y, p_lossb);
    sum_kernel<<<1, 32>>>(p_lossb, (float*)d_out);
}

// round 17
// speedup vs baseline: 1.0335x; 1.0016x over previous
#include <cuda_runtime.h>
#include <cuda_bf16.h>
#include <math.h>

// ---------------- problem constants ----------------
constexpr int EMS   = 768;
constexpr int NHD   = 12;
constexpr int HDM   = 64;
constexpr int SEQL  = 65;
constexpr int BAT   = 256;
constexpr int STOK  = BAT * SEQL;       // 16640
constexpr int NHID_ = 3072;
constexpr int NE    = 8;
constexpr int CAP   = 2600;
constexpr int NCHUNK = 130;
constexpr int NCLS  = 1000;

// ---------------- bf16 transposed weight buffer ----------------
constexpr size_t W_QKV = 0;
constexpr size_t SZ_QKV = (size_t)8 * 2304 * 768;
constexpr size_t W_O  = W_QKV + SZ_QKV;
constexpr size_t SZ_O = (size_t)8 * 768 * 768;
constexpr size_t W_D1 = W_O + SZ_O;
constexpr size_t SZ_D1 = (size_t)4 * 3072 * 768;
constexpr size_t W_D2 = W_D1 + SZ_D1;
constexpr size_t SZ_D2 = (size_t)4 * 768 * 3072;
constexpr size_t W_E1 = W_D2 + SZ_D2;
constexpr size_t SZ_E1 = (size_t)32 * 3072 * 768;
constexpr size_t W_E2 = W_E1 + SZ_E1;
constexpr size_t SZ_E2 = (size_t)32 * 768 * 3072;
constexpr size_t W_TOTAL = W_E2 + SZ_E2;

__device__ __nv_bfloat16 g_wbf[W_TOTAL];

// ---------------- scratch ----------------
__device__ float g_h   [(size_t)STOK * EMS];
__device__ float g_qkv [(size_t)STOK * 3 * EMS];   // low half reused as bf16 qkv
__device__ float g_attn[(size_t)STOK * EMS];
__device__ float g_f2  [(size_t)STOK * EMS];
__device__ float g_patch[(size_t)BAT * 64 * 48];
__device__ float g_ebuf2[(size_t)NE * CAP * EMS];
__device__ float g_logits[BAT * NCLS];
__device__ float g_clsrow[BAT * EMS];
__device__ float g_lossb[BAT];
__device__ float g_g1[STOK], g_g2[STOK];
__device__ int   g_e1[STOK], g_e2[STOK], g_p1[STOK], g_p2[STOK];
__device__ int   g_h1[NCHUNK * NE], g_h2[NCHUNK * NE];
__device__ int   g_o1[NCHUNK * NE], g_o2[NCHUNK * NE];

__device__ __nv_bfloat16 g_hb   [(size_t)STOK * EMS];
__device__ __nv_bfloat16 g_attnb[(size_t)STOK * EMS];
__device__ __nv_bfloat16 g_f1b  [(size_t)STOK * NHID_];
__device__ __nv_bfloat16 g_bufb [(size_t)NE * CAP * EMS];
__device__ __nv_bfloat16 g_eb1b [(size_t)NE * CAP * NHID_];

// ---------------- small PTX helpers (base ISA only) ----------------
__device__ __forceinline__ unsigned smem_u32(const void* p) {
    unsigned a;
    asm("{ .reg .u64 t; cvta.to.shared.u64 t, %1; cvt.u32.u64 %0, t; }" : "=r"(a) : "l"(p));
    return a;
}
__device__ __forceinline__ void cp_async16(unsigned dst, const void* src) {
    asm volatile("cp.async.cg.shared.global [%0], [%1], 16;" :: "r"(dst), "l"(src));
}
__device__ __forceinline__ void cp_commit() { asm volatile("cp.async.commit_group;"); }
template <int N>
__device__ __forceinline__ void cp_wait() { asm volatile("cp.async.wait_group %0;" :: "n"(N)); }

__device__ __forceinline__ void ldmx4(unsigned* r, unsigned addr) {
    asm volatile("ldmatrix.sync.aligned.m8n8.x4.shared.b16 {%0,%1,%2,%3}, [%4];"
                 : "=r"(r[0]), "=r"(r[1]), "=r"(r[2]), "=r"(r[3]) : "r"(addr));
}
__device__ __forceinline__ void mma16816(float* d, const unsigned* a, unsigned b0, unsigned b1) {
    asm volatile("mma.sync.aligned.m16n8k16.row.col.f32.bf16.bf16.f32 "
                 "{%0,%1,%2,%3}, {%4,%5,%6,%7}, {%8,%9}, {%0,%1,%2,%3};"
                 : "+f"(d[0]), "+f"(d[1]), "+f"(d[2]), "+f"(d[3])
                 : "r"(a[0]), "r"(a[1]), "r"(a[2]), "r"(a[3]), "r"(b0), "r"(b1));
}
__device__ __forceinline__ unsigned long long pack2(float lo, float hi) {
    unsigned long long r;
    asm("mov.b64 %0, {%1, %2};" : "=l"(r) : "f"(lo), "f"(hi));
    return r;
}
__device__ __forceinline__ void fma2(unsigned long long& d, unsigned long long a, unsigned long long b) {
    asm("fma.rn.f32x2 %0, %1, %2, %0;" : "+l"(d) : "l"(a), "l"(b));
}
__device__ __forceinline__ float2 unpack2(unsigned long long v) {
    float2 f;
    asm("mov.b64 {%0, %1}, %2;" : "=f"(f.x), "=f"(f.y) : "l"(v));
    return f;
}

// ---------------- bf16 tensor-core GEMM via mma.sync (v4: 4-stage, PROVEN BEST) ----------------
// C[M,N] = A[M,K] @ Bt[N,K]^T + bias.  A,Bt bf16 row-major; K%32==0, N%128==0.
// 256 threads, 8 warps (4x2), warp tile 32x64, 4-stage cp.async (BK=32), 1 sync/iter.
// 82 KB smem/CTA -> 2 CTAs/SM = 16 warps/SM.
// mode bits: bit0 = relu, bit1 = bf16 output
constexpr int HROWB = 80;                  // 32 bf16 (64B) + 16B pad -> conflict-free ldmatrix
constexpr int HSTAGE = 2 * 128 * HROWB;    // A tile + B tile = 20480 bytes
constexpr int NSTG = 4;
constexpr int HG_SMEM = NSTG * HSTAGE;     // 81920

__global__ void __launch_bounds__(256) hgemm_kernel(
    const __nv_bfloat16* __restrict__ A, const __nv_bfloat16* __restrict__ Bt,
    const float* __restrict__ bias, void* __restrict__ Cout,
    int M, int N, int K, int mode,
    long long strA, long long strB, long long strBias, long long strC)
{
    extern __shared__ __align__(16) char smem[];
    const unsigned sb = smem_u32(smem);
    const int tid = threadIdx.x;
    const int wid = tid >> 5, lane = tid & 31;

    A    += (long long)blockIdx.z * strA;
    Bt   += (long long)blockIdx.z * strB;
    bias += (long long)blockIdx.z * strBias;

    const int brow = blockIdx.y * 128;
    const int bcol = blockIdx.x * 128;
    const int KIT = K >> 5;                // BK = 32

    // per-thread load slots: 2 A chunks + 2 B chunks of 16B each
    const int c0 = tid, c1 = tid + 256;
    const int ar0 = c0 >> 2, ac0 = (c0 & 3) * 16;
    const int ar1 = c1 >> 2, ac1 = (c1 & 3) * 16;
    const __nv_bfloat16* Arow0 = A + (size_t)min(brow + ar0, M - 1) * K;
    const __nv_bfloat16* Arow1 = A + (size_t)min(brow + ar1, M - 1) * K;
    const __nv_bfloat16* Brow0 = Bt + (size_t)(bcol + ar0) * K;
    const __nv_bfloat16* Brow1 = Bt + (size_t)(bcol + ar1) * K;

    auto load_stage = [&](int st, int k0) {
        const unsigned sa = sb + st * HSTAGE;
        const unsigned sbm = sa + 128 * HROWB;
        cp_async16(sa + ar0 * HROWB + ac0, (const char*)(Arow0 + k0) + ac0);
        cp_async16(sa + ar1 * HROWB + ac1, (const char*)(Arow1 + k0) + ac1);
        cp_async16(sbm + ar0 * HROWB + ac0, (const char*)(Brow0 + k0) + ac0);
        cp_async16(sbm + ar1 * HROWB + ac1, (const char*)(Brow1 + k0) + ac1);
    };

    float acc[2][8][4];
#pragma unroll
    for (int i = 0; i < 2; i++)
#pragma unroll
        for (int j = 0; j < 8; j++)
#pragma unroll
            for (int q = 0; q < 4; q++) acc[i][j][q] = 0.f;

    const int wm = wid >> 1;              // 0..3  -> rows wm*32..+31
    const int wn = wid & 1;               // 0..1  -> cols wn*64..+63
    const unsigned aFragOff = (unsigned)((wm * 32 + (lane & 15)) * HROWB + (lane >> 4) * 16);
    const unsigned bFragOff = (unsigned)(128 * HROWB +
        (wn * 64 + ((lane >> 3) & 1) * 8 + (lane & 7)) * HROWB + (lane >> 4) * 16);

    // prologue: stages 0,1,2
#pragma unroll
    for (int s = 0; s < NSTG - 1; s++) {
        if (s < KIT) load_stage(s, s * 32);
        cp_commit();
    }

    int cur = 0;
    for (int it = 0; it < KIT; it++) {
        cp_wait<NSTG - 2>();
        __syncthreads();
        {
            const int pf = it + NSTG - 1;
            if (pf < KIT) {
                int pfs = cur + NSTG - 1; if (pfs >= NSTG) pfs -= NSTG;
                load_stage(pfs, pf * 32);
            }
            cp_commit();
        }
        const unsigned aBase = sb + cur * HSTAGE + aFragOff;
        const unsigned bBase = sb + cur * HSTAGE + bFragOff;
#pragma unroll
        for (int ks = 0; ks < 2; ks++) {
            unsigned afr[2][4];
            ldmx4(afr[0], aBase + ks * 32);
            ldmx4(afr[1], aBase + ks * 32 + 16 * HROWB);
#pragma unroll
            for (int ng = 0; ng < 4; ng++) {
                unsigned bfr[4];
                ldmx4(bfr, bBase + ks * 32 + ng * 16 * HROWB);
#pragma unroll
                for (int mt = 0; mt < 2; mt++) {
                    mma16816(acc[mt][2 * ng + 0], afr[mt], bfr[0], bfr[2]);
                    mma16816(acc[mt][2 * ng + 1], afr[mt], bfr[1], bfr[3]);
                }
            }
        }
        cur++; if (cur >= NSTG) cur = 0;
    }

    // ---- epilogue: direct register -> global ----
    const bool relu = (mode & 1);
    const bool isbf = (mode & 2);
    float* Cf = (float*)Cout + (long long)blockIdx.z * strC;
    __nv_bfloat16* Cb = (__nv_bfloat16*)Cout + (long long)blockIdx.z * strC;
    const int rbase = brow + wm * 32 + (lane >> 2);
    const int cbase = bcol + wn * 64 + 2 * (lane & 3);
#pragma unroll
    for (int mt = 0; mt < 2; mt++) {
#pragma unroll
        for (int nt = 0; nt < 8; nt++) {
            const int gcol = cbase + nt * 8;
            const float b0 = bias[gcol], b1 = bias[gcol + 1];
#pragma unroll
            for (int half = 0; half < 2; half++) {
                const int grow = rbase + mt * 16 + half * 8;
                if (grow < M) {
                    float v0 = acc[mt][nt][2 * half + 0] + b0;
                    float v1 = acc[mt][nt][2 * half + 1] + b1;
                    if (relu) { v0 = fmaxf(v0, 0.f); v1 = fmaxf(v1, 0.f); }
                    if (isbf) {
                        __nv_bfloat162 p;
                        p.x = __float2bfloat16(v0); p.y = __float2bfloat16(v1);
                        *reinterpret_cast<__nv_bfloat162*>(Cb + (size_t)grow * N + gcol) = p;
                    } else {
                        *reinterpret_cast<float2*>(Cf + (size_t)grow * N + gcol) = make_float2(v0, v1);
                    }
                }
            }
        }
    }
}

// ---------------- weight transpose+convert v3: fp32 [R,C] -> bf16 [C,R], batched ----------------
// 32x128 strip per block (4x v2's tile): 4 independent float4 loads/thread (MLP=4
// hides DRAM latency per the LDG model), 8 bf162 stores/thread, 2 barriers amortized.
// R % 32 == 0 and C % 128 == 0 for all shapes used -> no bounds checks.
constexpr int WT_STR = 129;   // odd stride: load banks (r+4q), store banks (2l+cl) even/odd split
__global__ void __launch_bounds__(256) wtrans_kernel(
    const float* __restrict__ src, __nv_bfloat16* __restrict__ dst, int R, int C) {
    __shared__ float t[32][WT_STR];
    src += (size_t)blockIdx.z * R * C;
    dst += (size_t)blockIdx.z * R * C;
    const int c0 = blockIdx.x * 128, r0 = blockIdx.y * 32;
    const int tid = threadIdx.x;
    // load: 4 float4 per thread, issued back-to-back (independent -> MLP=4)
    float4 v[4];
#pragma unroll
    for (int i = 0; i < 4; i++) {
        const int idx = tid + 256 * i;
        const int r = idx >> 5, cq = (idx & 31) * 4;
        v[i] = *reinterpret_cast<const float4*>(src + (size_t)(r0 + r) * C + c0 + cq);
    }
#pragma unroll
    for (int i = 0; i < 4; i++) {
        const int idx = tid + 256 * i;
        const int r = idx >> 5, cq = (idx & 31) * 4;
        t[r][cq + 0] = v[i].x; t[r][cq + 1] = v[i].y;
        t[r][cq + 2] = v[i].z; t[r][cq + 3] = v[i].w;
    }
    __syncthreads();
    // store: 8 bf162 per thread; 16 consecutive threads cover one 64B output row
#pragma unroll
    for (int k = 0; k < 8; k++) {
        const int j = tid + 256 * k;
        const int cl = j >> 4, l = j & 15;
        const int r = 2 * l;
        __nv_bfloat162 p;
        p.x = __float2bfloat16(t[r][cl]);
        p.y = __float2bfloat16(t[r + 1][cl]);
        *reinterpret_cast<__nv_bfloat162*>(dst + (size_t)(c0 + cl) * R + r0 + r) = p;
    }
}

// ---------------- fp32 fallback SGEMM (patch embed, decoder) ----------------
constexpr int BM = 128, BN = 128, BKx = 8;

__global__ __launch_bounds__(256, 2) void sgemm_kernel(
    const float* __restrict__ A, const float* __restrict__ Bm,
    const float* __restrict__ bias, float* __restrict__ Cm,
    int M, int N, int K, int relu)
{
    __shared__ __align__(16) float As[BKx][BM];
    __shared__ __align__(16) float Bs[BKx][BN];
    const int tid  = threadIdx.x;
    const int brow = blockIdx.y * BM;
    const int bcol = blockIdx.x * BN;
    const int tx = tid & 15, ty = tid >> 4;
    const int aRow = tid >> 1, aCol = (tid & 1) * 4;
    const int bRowL = tid >> 5, bColL = (tid & 31) * 4;

    unsigned long long acc[8][4];
#pragma unroll
    for (int i = 0; i < 8; i++)
#pragma unroll
        for (int j = 0; j < 4; j++) acc[i][j] = 0ull;
    const bool n4 = ((N & 3) == 0);

    for (int k0 = 0; k0 < K; k0 += BKx) {
        float4 av = make_float4(0.f, 0.f, 0.f, 0.f);
        const int gr = brow + aRow;
        if (gr < M && k0 + aCol < K) av = *reinterpret_cast<const float4*>(A + (long long)gr * K + k0 + aCol);
        As[aCol + 0][aRow] = av.x; As[aCol + 1][aRow] = av.y;
        As[aCol + 2][aRow] = av.z; As[aCol + 3][aRow] = av.w;
        const int gc = bcol + bColL;
        const int kr = k0 + bRowL;
        const float* bp = Bm + (long long)kr * N + gc;
        if (n4) {
            float4 bv = make_float4(0.f, 0.f, 0.f, 0.f);
            if (gc < N && kr < K) bv = *reinterpret_cast<const float4*>(bp);
            Bs[bRowL][bColL + 0] = bv.x; Bs[bRowL][bColL + 1] = bv.y;
            Bs[bRowL][bColL + 2] = bv.z; Bs[bRowL][bColL + 3] = bv.w;
        } else {
#pragma unroll
            for (int q = 0; q < 4; q++)
                Bs[bRowL][bColL + q] = (gc + q < N && kr < K) ? bp[q] : 0.f;
        }
        __syncthreads();
#pragma unroll
        for (int kk = 0; kk < BKx; kk++) {
            const float4 a0 = *reinterpret_cast<const float4*>(&As[kk][ty * 8]);
            const float4 a1 = *reinterpret_cast<const float4*>(&As[kk][ty * 8 + 4]);
            const unsigned long long b0 = *reinterpret_cast<const unsigned long long*>(&Bs[kk][tx * 8 + 0]);
            const unsigned long long b1 = *reinterpret_cast<const unsigned long long*>(&Bs[kk][tx * 8 + 2]);
            const unsigned long long b2 = *reinterpret_cast<const unsigned long long*>(&Bs[kk][tx * 8 + 4]);
            const unsigned long long b3 = *reinterpret_cast<const unsigned long long*>(&Bs[kk][tx * 8 + 6]);
            const float aa[8] = {a0.x, a0.y, a0.z, a0.w, a1.x, a1.y, a1.z, a1.w};
#pragma unroll
            for (int i = 0; i < 8; i++) {
                const unsigned long long ad = pack2(aa[i], aa[i]);
                fma2(acc[i][0], ad, b0); fma2(acc[i][1], ad, b1);
                fma2(acc[i][2], ad, b2); fma2(acc[i][3], ad, b3);
            }
        }
        __syncthreads();
    }
#pragma unroll
    for (int i = 0; i < 8; i++) {
        const int gi = brow + ty * 8 + i;
        if (gi >= M) continue;
#pragma unroll
        for (int j = 0; j < 4; j++) {
            const float2 v = unpack2(acc[i][j]);
            const int gj = bcol + tx * 8 + 2 * j;
            if (gj < N) {
                float c = v.x + bias[gj];
                if (relu) c = fmaxf(c, 0.f);
                Cm[(long long)gi * N + gj] = c;
            }
            if (gj + 1 < N) {
                float c = v.y + bias[gj + 1];
                if (relu) c = fmaxf(c, 0.f);
                Cm[(long long)gi * N + gj + 1] = c;
            }
        }
    }
}

// ---------------- patch embed prep ----------------
__global__ void patch_kernel(const float* __restrict__ x, float* __restrict__ p) {
    const int total = BAT * 64 * 48;
    for (int idx = blockIdx.x * blockDim.x + threadIdx.x; idx < total; idx += gridDim.x * blockDim.x) {
        const int f = idx % 48;
        const int token = idx / 48;
        const int b = token >> 6;
        const int ij = token & 63;
        const int i = ij >> 3, j = ij & 7;
        const int c = f >> 4, r = (f >> 2) & 3, q = f & 3;
        p[idx] = x[((b * 3 + c) * 32 + (i * 4 + r)) * 32 + (j * 4 + q)];
    }
}

__global__ void assemble_kernel(const float* __restrict__ emb, const float* __restrict__ cls,
                                const float* __restrict__ pos, float* __restrict__ h,
                                __nv_bfloat16* __restrict__ hb) {
    const long long total = (long long)STOK * EMS;
    for (long long idx = (long long)blockIdx.x * blockDim.x + threadIdx.x; idx < total;
         idx += (long long)gridDim.x * blockDim.x) {
        const int d = (int)(idx % EMS);
        const long long s = idx / EMS;
        const int b = (int)(s / SEQL), t = (int)(s % SEQL);
        float v = pos[t * EMS + d];
        v += (t == 0) ? cls[d] : emb[((long long)b * 64 + (t - 1)) * EMS + d];
        h[idx] = v;
        hb[idx] = __float2bfloat16(v);
    }
}

// ---------------- attention (bf16 qkv in, bf16 out), packed fp32x2 ----------------
constexpr int KVSTR = 66;   // even stride -> 8B-aligned rows for LDS.64
__global__ void __launch_bounds__(256) attn_kernel(const __nv_bfloat16* __restrict__ qkv,
                                                   __nv_bfloat16* __restrict__ out) {
    __shared__ float ks[SEQL][KVSTR];
    __shared__ float vs[SEQL][KVSTR];
    __shared__ float qrow[8][HDM];
    __shared__ float probs[8][SEQL + 1];

    const int h = blockIdx.x, b = blockIdx.y;
    const int tid = threadIdx.x, warp = tid >> 5, lane = tid & 31;
    const __nv_bfloat16* base = qkv + (long long)b * SEQL * (3 * EMS);

    for (int idx = tid; idx < SEQL * HDM; idx += 256) {
        const int k = idx >> 6, d = idx & 63;
        ks[k][d] = __bfloat162float(base[(long long)k * (3 * EMS) + EMS     + h * HDM + d]);
        vs[k][d] = __bfloat162float(base[(long long)k * (3 * EMS) + 2 * EMS + h * HDM + d]);
    }
    __syncthreads();

    for (int q = warp; q < SEQL; q += 8) {
        qrow[warp][lane]      = __bfloat162float(base[(long long)q * (3 * EMS) + h * HDM + lane]);
        qrow[warp][lane + 32] = __bfloat162float(base[(long long)q * (3 * EMS) + h * HDM + lane + 32]);
        __syncwarp();
        float sc[3];
        float mx = -1e30f;
        const unsigned long long* qp = reinterpret_cast<const unsigned long long*>(&qrow[warp][0]);
#pragma unroll
        for (int ii = 0; ii < 3; ii++) {
            const int kk = lane + ii * 32;
            float acc = 0.f;
            if (kk < SEQL) {
                const unsigned long long* kp = reinterpret_cast<const unsigned long long*>(&ks[kk][0]);
                unsigned long long a2 = 0ull;
#pragma unroll
                for (int j2 = 0; j2 < 32; j2++) fma2(a2, qp[j2], kp[j2]);
                const float2 f = unpack2(a2);
                acc = (f.x + f.y) * 0.125f;
                mx = fmaxf(mx, acc);
            }
            sc[ii] = acc;
        }
        for (int o = 16; o > 0; o >>= 1) mx = fmaxf(mx, __shfl_xor_sync(0xffffffffu, mx, o));
        float sum = 0.f;
#pragma unroll
        for (int ii = 0; ii < 3; ii++) {
            const int kk = lane + ii * 32;
            float p = 0.f;
            if (kk < SEQL) { p = expf(sc[ii] - mx); sum += p; }
            sc[ii] = p;
        }
        for (int o = 16; o > 0; o >>= 1) sum += __shfl_xor_sync(0xffffffffu, sum, o);
        const float inv = 1.f / sum;
#pragma unroll
        for (int ii = 0; ii < 3; ii++) {
            const int kk = lane + ii * 32;
            if (kk < SEQL) probs[warp][kk] = sc[ii] * inv;
        }
        __syncwarp();
        // AV: each lane covers d = 2*lane, 2*lane+1 (packed)
        {
            const int d0 = 2 * lane;
            unsigned long long o2 = 0ull;
            for (int k = 0; k < SEQL; k++) {
                const float p = probs[warp][k];
                fma2(o2, pack2(p, p),
                     *reinterpret_cast<const unsigned long long*>(&vs[k][d0]));
            }
            const float2 f = unpack2(o2);
            __nv_bfloat162 pr;
            pr.x = __float2bfloat16(f.x);
            pr.y = __float2bfloat16(f.y);
            *reinterpret_cast<__nv_bfloat162*>(
                out + ((long long)(b * SEQL + q)) * EMS + h * HDM + d0) = pr;
        }
        __syncwarp();
    }
}

// ---------------- layernorm (shuffle reductions; writes fp32 h + bf16 copy) ----------------
__global__ void __launch_bounds__(256) ln_kernel(float* __restrict__ h, const float* __restrict__ a,
                          const float* __restrict__ g, const float* __restrict__ bta,
                          __nv_bfloat16* __restrict__ hb) {
    __shared__ float wred[8];
    const long long base = (long long)blockIdx.x * EMS;
    const int tid = threadIdx.x, warp = tid >> 5, lane = tid & 31;
    const float x0 = h[base + tid]       + a[base + tid];
    const float x1 = h[base + tid + 256] + a[base + tid + 256];
    const float x2 = h[base + tid + 512] + a[base + tid + 512];
    float s = x0 + x1 + x2;
    for (int o = 16; o > 0; o >>= 1) s += __shfl_xor_sync(0xffffffffu, s, o);
    if (lane == 0) wred[warp] = s;
    __syncthreads();
    float tot = 0.f;
#pragma unroll
    for (int w = 0; w < 8; w++) tot += wred[w];
    const float mean = tot / (float)EMS;
    __syncthreads();
    const float d0 = x0 - mean, d1 = x1 - mean, d2 = x2 - mean;
    float v = d0 * d0 + d1 * d1 + d2 * d2;
    for (int o = 16; o > 0; o >>= 1) v += __shfl_xor_sync(0xffffffffu, v, o);
    if (lane == 0) wred[warp] = v;
    __syncthreads();
    float vtot = 0.f;
#pragma unroll
    for (int w = 0; w < 8; w++) vtot += wred[w];
    const float rstd = rsqrtf(vtot / (float)EMS + 1e-5f);
    const float r0 = d0 * rstd * g[tid]       + bta[tid];
    const float r1 = d1 * rstd * g[tid + 256] + bta[tid + 256];
    const float r2 = d2 * rstd * g[tid + 512] + bta[tid + 512];
    h[base + tid]       = r0;  hb[base + tid]       = __float2bfloat16(r0);
    h[base + tid + 256] = r1;  hb[base + tid + 256] = __float2bfloat16(r1);
    h[base + tid + 512] = r2;  hb[base + tid + 512] = __float2bfloat16(r2);
}

// ---------------- fused MoE keep-mask + gather + layernorm ----------------
__global__ void __launch_bounds__(256) ln_gather_kernel(
    float* __restrict__ h, const float* __restrict__ oe,
    const int* __restrict__ e1, const int* __restrict__ e2,
    const int* __restrict__ p1, const int* __restrict__ p2,
    const float* __restrict__ g1, const float* __restrict__ g2,
    const float* __restrict__ g, const float* __restrict__ bta,
    __nv_bfloat16* __restrict__ hb) {
    __shared__ float wred[8];
    const int s = blockIdx.x;
    const long long base = (long long)s * EMS;
    const int tid = threadIdx.x, warp = tid >> 5, lane = tid & 31;
    const int pp1 = p1[s], pp2 = p2[s];
    const float a = g1[s] * (pp1 < CAP ? 1.f : 0.f);
    const float bgl = g2[s] * (pp2 < CAP ? 1.f : 0.f);
    const float den = fmaxf(a + bgl, 1e-9f);
    const float w1 = a / den, w2 = bgl / den;
    const int q1 = min(pp1, CAP - 1), q2 = min(pp2, CAP - 1);
    const float* r1 = oe + ((long long)e1[s] * CAP + q1) * EMS;
    const float* r2 = oe + ((long long)e2[s] * CAP + q2) * EMS;

    const float x0 = h[base + tid]       + r1[tid]       * w1 + r2[tid]       * w2;
    const float x1 = h[base + tid + 256] + r1[tid + 256] * w1 + r2[tid + 256] * w2;
    const float x2 = h[base + tid + 512] + r1[tid + 512] * w1 + r2[tid + 512] * w2;
    float sm = x0 + x1 + x2;
    for (int o = 16; o > 0; o >>= 1) sm += __shfl_xor_sync(0xffffffffu, sm, o);
    if (lane == 0) wred[warp] = sm;
    __syncthreads();
    float tot = 0.f;
#pragma unroll
    for (int w = 0; w < 8; w++) tot += wred[w];
    const float mean = tot / (float)EMS;
    __syncthreads();
    const float d0 = x0 - mean, d1 = x1 - mean, d2 = x2 - mean;
    float v = d0 * d0 + d1 * d1 + d2 * d2;
    for (int o = 16; o > 0; o >>= 1) v += __shfl_xor_sync(0xffffffffu, v, o);
    if (lane == 0) wred[warp] = v;
    __syncthreads();
    float vtot = 0.f;
#pragma unroll
    for (int w = 0; w < 8; w++) vtot += wred[w];
    const float rstd = rsqrtf(vtot / (float)EMS + 1e-5f);
    const float r0o = d0 * rstd * g[tid]       + bta[tid];
    const float r1o = d1 * rstd * g[tid + 256] + bta[tid + 256];
    const float r2o = d2 * rstd * g[tid + 512] + bta[tid + 512];
    h[base + tid]       = r0o;  hb[base + tid]       = __float2bfloat16(r0o);
    h[base + tid + 256] = r1o;  hb[base + tid + 256] = __float2bfloat16(r1o);
    h[base + tid + 512] = r2o;  hb[base + tid + 512] = __float2bfloat16(r2o);
}

// ---------------- MoE gating (fp32, exact) ----------------
__global__ void gate_kernel(const float* __restrict__ h, const float* __restrict__ gw,
                            int* __restrict__ e1o, int* __restrict__ e2o,
                            float* __restrict__ g1o, float* __restrict__ g2o) {
    const int token = (blockIdx.x * blockDim.x + threadIdx.x) >> 5;
    const int lane = threadIdx.x & 31;
    if (token >= STOK) return;
    const float* x = h + (long long)token * EMS;
    float part[NE] = {0.f, 0.f, 0.f, 0.f, 0.f, 0.f, 0.f, 0.f};
    for (int j = lane; j < EMS; j += 32) {
        const float xv = x[j];
        const float* w = gw + j * NE;
#pragma unroll
        for (int e = 0; e < NE; e++) part[e] += xv * w[e];
    }
#pragma unroll
    for (int e = 0; e < NE; e++)
        for (int o = 16; o > 0; o >>= 1) part[e] += __shfl_xor_sync(0xffffffffu, part[e], o);
    if (lane == 0) {
        float mx = part[0];
#pragma unroll
        for (int e = 1; e < NE; e++) mx = fmaxf(mx, part[e]);
        float gates[NE]; float se = 0.f;
#pragma unroll
        for (int e = 0; e < NE; e++) { gates[e] = expf(part[e] - mx); se += gates[e]; }
        int a1 = 0; float b1v = part[0];
#pragma unroll
        for (int e = 1; e < NE; e++) if (part[e] > b1v) { b1v = part[e]; a1 = e; }
        int a2 = -1; float b2v = -1e30f;
#pragma unroll
        for (int e = 0; e < NE; e++) if (e != a1 && part[e] > b2v) { b2v = part[e]; a2 = e; }
        e1o[token] = a1; e2o[token] = a2;
        g1o[token] = gates[a1] / se;
        g2o[token] = gates[a2] / se;
    }
}

__global__ void hist_kernel(const int* __restrict__ e1, const int* __restrict__ e2,
                            int* __restrict__ h1, int* __restrict__ h2) {
    __shared__ int s1[NE], s2[NE];
    const int tid = threadIdx.x;
    if (tid < NE) { s1[tid] = 0; s2[tid] = 0; }
    __syncthreads();
    const int s = blockIdx.x * 128 + tid;
    atomicAdd(&s1[e1[s]], 1);
    atomicAdd(&s2[e2[s]], 1);
    __syncthreads();
    if (tid < NE) {
        h1[blockIdx.x * NE + tid] = s1[tid];
        h2[blockIdx.x * NE + tid] = s2[tid];
    }
}

__global__ void scan_kernel(const int* __restrict__ h1, const int* __restrict__ h2,
                            int* __restrict__ o1, int* __restrict__ o2) {
    const int e = threadIdx.x;
    if (e < NE) {
        int run = 0;
        for (int c = 0; c < NCHUNK; c++) { o1[c * NE + e] = run; run += h1[c * NE + e]; }
        int run2 = run;
        for (int c = 0; c < NCHUNK; c++) { o2[c * NE + e] = run2; run2 += h2[c * NE + e]; }
    }
}

__global__ void rank_kernel(const int* __restrict__ e1, const int* __restrict__ e2,
                            const int* __restrict__ o1, const int* __restrict__ o2,
                            int* __restrict__ p1, int* __restrict__ p2) {
    const int t = threadIdx.x, c = blockIdx.x;
    if (t < NE) {
        const int e = t;
        int r = o1[c * NE + e];
        for (int i = 0; i < 128; i++) {
            const int s = c * 128 + i;
            if (e1[s] == e) p1[s] = r++;
        }
    } else if (t < 2 * NE) {
        const int e = t - NE;
        int r = o2[c * NE + e];
        for (int i = 0; i < 128; i++) {
            const int s = c * 128 + i;
            if (e2[s] == e) p2[s] = r++;
        }
    }
}

// scatter reads the bf16 mirror hb with vectorized 16B copies
__global__ void scatter_kernel(const __nv_bfloat16* __restrict__ hb, const int* __restrict__ e1,
                               const int* __restrict__ e2, const int* __restrict__ p1,
                               const int* __restrict__ p2, __nv_bfloat16* __restrict__ buf) {
    const int s = blockIdx.x;
    const int q1 = p1[s], q2 = p2[s];
    const uint4* src = reinterpret_cast<const uint4*>(hb + (long long)s * EMS); // 96 uint4
    const int tid = threadIdx.x;   // blockDim = 128
    if (q1 < CAP) {
        uint4* d = reinterpret_cast<uint4*>(buf + ((long long)e1[s] * CAP + q1) * EMS);
        if (tid < 96) d[tid] = src[tid];
    }
    if (q2 < CAP) {
        uint4* d = reinterpret_cast<uint4*>(buf + ((long long)e2[s] * CAP + q2) * EMS);
        if (tid < 96) d[tid] = src[tid];
    }
}

// ---------------- decoder + loss ----------------
__global__ void cls_extract_kernel(const float* __restrict__ h, float* __restrict__ out) {
    const int b = blockIdx.x;
    for (int d = threadIdx.x; d < EMS; d += blockDim.x)
        out[b * EMS + d] = h[(long long)b * SEQL * EMS + d];
}

__global__ void loss_kernel(const float* __restrict__ logits, const int* __restrict__ y,
                            float* __restrict__ lossb) {
    __shared__ float red[256];
    const int b = blockIdx.x, tid = threadIdx.x;
    const float* l = logits + b * NCLS;
    float mx = -1e30f;
    for (int j = tid; j < NCLS; j += 256) mx = fmaxf(mx, l[j]);
    red[tid] = mx;
    __syncthreads();
    for (int o = 128; o > 0; o >>= 1) { if (tid < o) red[tid] = fmaxf(red[tid], red[tid + o]); __syncthreads(); }
    mx = red[0];
    __syncthreads();
    float s = 0.f;
    for (int j = tid; j < NCLS; j += 256) s += expf(l[j] - mx);
    red[tid] = s;
    __syncthreads();
    for (int o = 128; o > 0; o >>= 1) { if (tid < o) red[tid] += red[tid + o]; __syncthreads(); }
    if (tid == 0) lossb[b] = -(l[y[b]] - mx - logf(red[0]));
}

__global__ void sum_kernel(const float* __restrict__ lossb, float* __restrict__ out) {
    if (threadIdx.x == 0) {
        float s = 0.f;
        for (int i = 0; i < BAT; i++) s += lossb[i];
        out[0] = s;
    }
}

// ---------------- host side ----------------
static inline void gemm_tc(const __nv_bfloat16* A, const __nv_bfloat16* Bt, const float* bias,
                           void* C, int M, int N, int K, int mode, int batch = 1,
                           long long sA = 0, long long sB = 0, long long sBias = 0, long long sC = 0) {
    dim3 grid(N / 128, (M + 127) / 128, batch);
    hgemm_kernel<<<grid, 256, HG_SMEM>>>(A, Bt, bias, C, M, N, K, mode, sA, sB, sBias, sC);
}

extern "C" void kernel_launch(void* const* d_in, const int* in_sizes, int n_in,
                              void* d_out, int out_size) {
    const float* x       = (const float*)d_in[0];
    const int*   y       = (const int*)  d_in[1];
    const float* patch_w = (const float*)d_in[2];
    const float* patch_b = (const float*)d_in[3];
    const float* cls     = (const float*)d_in[4];
    const float* pos     = (const float*)d_in[5];
    const float* wqkv    = (const float*)d_in[6];
    const float* bqkv    = (const float*)d_in[7];
    const float* wo      = (const float*)d_in[8];
    const float* bo      = (const float*)d_in[9];
    const float* ln1g    = (const float*)d_in[10];
    const float* ln1b    = (const float*)d_in[11];
    const float* ln2g    = (const float*)d_in[12];
    const float* ln2b    = (const float*)d_in[13];
    const float* dw1     = (const float*)d_in[14];
    const float* db1     = (const float*)d_in[15];
    const float* dw2     = (const float*)d_in[16];
    const float* db2     = (const float*)d_in[17];
    const float* gw      = (const float*)d_in[18];
    const float* ew1     = (const float*)d_in[19];
    const float* eb1     = (const float*)d_in[20];
    const float* ew2     = (const float*)d_in[21];
    const float* eb2     = (const float*)d_in[22];
    const float* decw    = (const float*)d_in[23];
    const float* decb    = (const float*)d_in[24];

    cudaFuncSetAttribute(hgemm_kernel, cudaFuncAttributeMaxDynamicSharedMemorySize, HG_SMEM);

    float *p_h, *p_qkv, *p_attn, *p_f2, *p_patch, *p_eb2;
    float *p_logits, *p_cls, *p_lossb, *p_g1, *p_g2;
    int *p_e1, *p_e2, *p_p1, *p_p2, *p_h1, *p_h2, *p_o1, *p_o2;
    __nv_bfloat16 *p_wb, *p_hb, *p_attnb, *p_f1b, *p_bufb, *p_eb1b;
    cudaGetSymbolAddress((void**)&p_h, g_h);
    cudaGetSymbolAddress((void**)&p_qkv, g_qkv);
    cudaGetSymbolAddress((void**)&p_attn, g_attn);
    cudaGetSymbolAddress((void**)&p_f2, g_f2);
    cudaGetSymbolAddress((void**)&p_patch, g_patch);
    cudaGetSymbolAddress((void**)&p_eb2, g_ebuf2);
    cudaGetSymbolAddress((void**)&p_logits, g_logits);
    cudaGetSymbolAddress((void**)&p_cls, g_clsrow);
    cudaGetSymbolAddress((void**)&p_lossb, g_lossb);
    cudaGetSymbolAddress((void**)&p_g1, g_g1);
    cudaGetSymbolAddress((void**)&p_g2, g_g2);
    cudaGetSymbolAddress((void**)&p_e1, g_e1);
    cudaGetSymbolAddress((void**)&p_e2, g_e2);
    cudaGetSymbolAddress((void**)&p_p1, g_p1);
    cudaGetSymbolAddress((void**)&p_p2, g_p2);
    cudaGetSymbolAddress((void**)&p_h1, g_h1);
    cudaGetSymbolAddress((void**)&p_h2, g_h2);
    cudaGetSymbolAddress((void**)&p_o1, g_o1);
    cudaGetSymbolAddress((void**)&p_o2, g_o2);
    cudaGetSymbolAddress((void**)&p_wb, g_wbf);
    cudaGetSymbolAddress((void**)&p_hb, g_hb);
    cudaGetSymbolAddress((void**)&p_attnb, g_attnb);
    cudaGetSymbolAddress((void**)&p_f1b, g_f1b);
    cudaGetSymbolAddress((void**)&p_bufb, g_bufb);
    cudaGetSymbolAddress((void**)&p_eb1b, g_eb1b);

    __nv_bfloat16* p_qkvb = (__nv_bfloat16*)p_qkv;   // reuse fp32 scratch as bf16

    // ---- weight convert+transpose: fp32 [K,N] -> bf16 [N,K] (v3: 32x128 strips) ----
    wtrans_kernel<<<dim3(2304 / 128, 768 / 32, 8),  256>>>(wqkv, p_wb + W_QKV, 768, 2304);
    wtrans_kernel<<<dim3(768 / 128,  768 / 32, 8),  256>>>(wo,   p_wb + W_O,   768, 768);
    wtrans_kernel<<<dim3(3072 / 128, 768 / 32, 4),  256>>>(dw1,  p_wb + W_D1,  768, 3072);
    wtrans_kernel<<<dim3(768 / 128, 3072 / 32, 4),  256>>>(dw2,  p_wb + W_D2,  3072, 768);
    wtrans_kernel<<<dim3(3072 / 128, 768 / 32, 32), 256>>>(ew1,  p_wb + W_E1,  768, 3072);
    wtrans_kernel<<<dim3(768 / 128, 3072 / 32, 32), 256>>>(ew2,  p_wb + W_E2,  3072, 768);

    // ---- patch embed (fp32 SGEMM; K=48 small) ----
    patch_kernel<<<1024, 256>>>(x, p_patch);
    sgemm_kernel<<<dim3(768 / BN, (BAT * 64 + BM - 1) / BM), 256>>>(p_patch, patch_w, patch_b, p_attn, BAT * 64, EMS, 48, 0);
    assemble_kernel<<<8192, 256>>>(p_attn, cls, pos, p_h, p_hb);

    int di = 0, mi = 0;
    for (int i = 0; i < 8; i++) {
        gemm_tc(p_hb, p_wb + W_QKV + (size_t)i * 2304 * 768, bqkv + i * 3 * EMS, p_qkvb, STOK, 3 * EMS, EMS, 2);
        attn_kernel<<<dim3(NHD, BAT), 256>>>(p_qkvb, p_attnb);
        gemm_tc(p_attnb, p_wb + W_O + (size_t)i * 768 * 768, bo + i * EMS, p_f2, STOK, EMS, EMS, 0);
        ln_kernel<<<STOK, 256>>>(p_h, p_f2, ln1g + i * EMS, ln1b + i * EMS, p_hb);

        if ((i & 1) == 0) {
            gemm_tc(p_hb, p_wb + W_D1 + (size_t)di * 3072 * 768, db1 + di * NHID_, p_f1b, STOK, NHID_, EMS, 3);
            gemm_tc(p_f1b, p_wb + W_D2 + (size_t)di * 768 * 3072, db2 + di * EMS, p_f2, STOK, EMS, NHID_, 0);
            ln_kernel<<<STOK, 256>>>(p_h, p_f2, ln2g + i * EMS, ln2b + i * EMS, p_hb);
            di++;
        } else {
            gate_kernel<<<STOK / 8, 256>>>(p_h, gw + (long long)mi * EMS * NE, p_e1, p_e2, p_g1, p_g2);
            hist_kernel<<<NCHUNK, 128>>>(p_e1, p_e2, p_h1, p_h2);
            scan_kernel<<<1, 32>>>(p_h1, p_h2, p_o1, p_o2);
            rank_kernel<<<NCHUNK, 32>>>(p_e1, p_e2, p_o1, p_o2, p_p1, p_p2);
            // keep-mask + renorm folded into ln_gather (reads raw g1/g2 + p1/p2)
            scatter_kernel<<<STOK, 128>>>(p_hb, p_e1, p_e2, p_p1, p_p2, p_bufb);
            gemm_tc(p_bufb, p_wb + W_E1 + (size_t)mi * 8 * 3072 * 768, eb1 + (long long)mi * NE * NHID_, p_eb1b,
                    CAP, NHID_, EMS, 3, NE,
                    (long long)CAP * EMS, (long long)3072 * 768, NHID_, (long long)CAP * NHID_);
            gemm_tc(p_eb1b, p_wb + W_E2 + (size_t)mi * 8 * 768 * 3072, eb2 + (long long)mi * NE * EMS, p_eb2,
                    CAP, EMS, NHID_, 0, NE,
                    (long long)CAP * NHID_, (long long)768 * 3072, EMS, (long long)CAP * EMS);
            ln_gather_kernel<<<STOK, 256>>>(p_h, p_eb2, p_e1, p_e2, p_p1, p_p2, p_g1, p_g2,
                                            ln2g + i * EMS, ln2b + i * EMS, p_hb);
            mi++;
        }
    }

    cls_extract_kernel<<<BAT, 256>>>(p_h, p_cls);
    sgemm_kernel<<<dim3((NCLS + BN - 1) / BN, (BAT + BM - 1) / BM), 256>>>(p_cls, decw, decb, p_logits, BAT, NCLS, EMS, 0);
    loss_kernel<<<BAT, 256>>>(p_logits, y, p_lossb);
    sum_kernel<<<1, 32>>>(p_lossb, (float*)d_out);
}